// round 6
// baseline (speedup 1.0000x reference)
#include <cuda_runtime.h>
#include <math.h>

#define SS 1024
#define DM 1024
#define NHQ 16
#define NKVH 4
#define HDIM 64
#define NE 64
#define TOPK 6
#define HE 512
#define NPAIR (SS*TOPK)

typedef unsigned long long u64;

__device__ __forceinline__ void fm2(u64 &d, u64 a, u64 b) {
    asm("fma.rn.f32x2 %0,%1,%2,%0;" : "+l"(d) : "l"(a), "l"(b));
}
__device__ __forceinline__ u64 ad2(u64 a, u64 b) {
    u64 d; asm("add.rn.f32x2 %0,%1,%2;" : "=l"(d) : "l"(a), "l"(b)); return d;
}
__device__ __forceinline__ void up2(float &lo, float &hi, u64 v) {
    asm("mov.b64 {%0,%1},%2;" : "=f"(lo), "=f"(hi) : "l"(v));
}

// ---------------- scratch ----------------
__device__ float g_hx[SS*DM];
__device__ float g_q[SS*NHQ*HDIM];
__device__ float g_k[SS*NKVH*HDIM];
__device__ float g_v[SS*NKVH*HDIM];
__device__ float g_attn[SS*NHQ*HDIM];
__device__ float g_h[SS*DM];
__device__ float g_z[SS*DM];
__device__ float g_logits[SS*NE];
__device__ float g_pairw[NPAIR];
__device__ int   g_cnt[NE];
__device__ int   g_list[NE*SS];
__device__ float g_gbuf[(size_t)NPAIR*HE];
__device__ float g_g2[(size_t)NPAIR*DM];
__device__ float g_a1[SS*HE];
__device__ float g_sh[SS*DM];

// ---------------- rmsnorm ----------------
__global__ __launch_bounds__(256) void rmsnorm_k(const float* __restrict__ x,
                                                 const float* __restrict__ w,
                                                 float* __restrict__ out) {
    int t = blockIdx.x;
    int tid = threadIdx.x;
    float4 xv = *(const float4*)&x[(size_t)t*DM + tid*4];
    float ss = xv.x*xv.x + xv.y*xv.y + xv.z*xv.z + xv.w*xv.w;
    #pragma unroll
    for (int off = 16; off; off >>= 1) ss += __shfl_xor_sync(0xffffffffu, ss, off);
    __shared__ float red[8];
    if ((tid & 31) == 0) red[tid >> 5] = ss;
    __syncthreads();
    float tot = 0.f;
    #pragma unroll
    for (int i = 0; i < 8; i++) tot += red[i];
    float r = rsqrtf(tot * (1.0f/DM) + 1e-5f);
    float4 wv = *(const float4*)&w[tid*4];
    float4 ov;
    ov.x = wv.x * (xv.x * r); ov.y = wv.y * (xv.y * r);
    ov.z = wv.z * (xv.z * r); ov.w = wv.w * (xv.w * r);
    *(float4*)&out[(size_t)t*DM + tid*4] = ov;
}

// ============ BM=32 FFMA2 tile, duplicated-A smem (no pk2 MOVs) ============
// 256 threads. compute map: ty=tid>>4 -> rows ty*2,ty*2+1 ; tx=tid&15.
// A loader: amr=tid>>3 (0..31), akc=(tid&7)*2. A-dup row stride 72 words.
// B loader (BN=128): bkr=tid>>4, bnc=(tid&15)*8. (BN=64): bnc=(tid&15)*4.

#define ASTR 72
#define ABUF (16*ASTR)          // 1152 floats per buffer

#define STA(Asb, v0, v1)                                                      \
  { *(float2*)&(Asb)[(akc+0)*ASTR + amr*2] = make_float2(v0,v0);              \
    *(float2*)&(Asb)[(akc+1)*ASTR + amr*2] = make_float2(v1,v1); }

#define KSTEP128(Asb, Bsb)                                                    \
  { ulonglong2 a  = *(const ulonglong2*)&(Asb)[k*ASTR + ty*4];                \
    ulonglong2 q0 = *(const ulonglong2*)&(Bsb)[k*128 + tx*8];                 \
    ulonglong2 q1 = *(const ulonglong2*)&(Bsb)[k*128 + tx*8 + 4];             \
    fm2(acc[0][0],a.x,q0.x); fm2(acc[0][1],a.x,q0.y);                         \
    fm2(acc[0][2],a.x,q1.x); fm2(acc[0][3],a.x,q1.y);                         \
    fm2(acc[1][0],a.y,q0.x); fm2(acc[1][1],a.y,q0.y);                         \
    fm2(acc[1][2],a.y,q1.x); fm2(acc[1][3],a.y,q1.y); }

#define KSTEPD(Asb, B1sb, B2sb)                                               \
  { ulonglong2 a  = *(const ulonglong2*)&(Asb)[k*ASTR + ty*4];                \
    ulonglong2 r1 = *(const ulonglong2*)&(B1sb)[k*64 + tx*4];                 \
    ulonglong2 r2 = *(const ulonglong2*)&(B2sb)[k*64 + tx*4];                 \
    fm2(acc1[0][0],a.x,r1.x); fm2(acc1[0][1],a.x,r1.y);                       \
    fm2(acc1[1][0],a.y,r1.x); fm2(acc1[1][1],a.y,r1.y);                       \
    fm2(acc3[0][0],a.x,r2.x); fm2(acc3[0][1],a.x,r2.y);                       \
    fm2(acc3[1][0],a.y,r2.x); fm2(acc3[1][1],a.y,r2.y); }

// ---------------- fused QKV GEMM: BM=32, BN=128 ----------------
__global__ __launch_bounds__(256) void qkv_gemm(const float* __restrict__ A,
                                                const float* __restrict__ wq,
                                                const float* __restrict__ wk,
                                                const float* __restrict__ wv) {
    __shared__ float sm[2*ABUF + 2*16*128];
    float* Asm = sm;
    float* Bsm = sm + 2*ABUF;
    int bn = blockIdx.x, m0 = blockIdx.y * 32;
    const float* B; float* C; int ldb; int col;
    if (bn < 8)       { B = wq; C = g_q; ldb = 1024; col = bn * 128; }
    else if (bn < 10) { B = wk; C = g_k; ldb = 256;  col = (bn - 8) * 128; }
    else              { B = wv; C = g_v; ldb = 256;  col = (bn - 10) * 128; }
    int tid = threadIdx.x, ty = tid >> 4, tx = tid & 15;
    int amr = tid >> 3, akc = (tid & 7) * 2;
    int bkr = tid >> 4, bnc = (tid & 15) * 8;
    const float* Arow = &A[(size_t)(m0 + amr) * DM];
    const float* Bp0 = &B[(size_t)bkr * ldb + col + bnc];
    u64 acc[2][4] = {};
    {
        float2 av = *(const float2*)&Arow[akc];
        float4 b0 = *(const float4*)Bp0;
        float4 b1 = *(const float4*)(Bp0 + 4);
        STA(Asm, av.x, av.y);
        *(float4*)&Bsm[bkr*128 + bnc]     = b0;
        *(float4*)&Bsm[bkr*128 + bnc + 4] = b1;
    }
    __syncthreads();
    int buf = 0;
    for (int k0 = 16; k0 <= DM; k0 += 16) {
        float2 nav; float4 nb0, nb1;
        bool more = (k0 < DM);
        if (more) {
            nav = *(const float2*)&Arow[k0 + akc];
            const float* bp = Bp0 + (size_t)k0 * ldb;
            nb0 = *(const float4*)bp;
            nb1 = *(const float4*)(bp + 4);
        }
        const float* Asb = Asm + buf*ABUF;
        const float* Bsb = Bsm + buf*2048;
        #pragma unroll
        for (int k = 0; k < 16; k++) KSTEP128(Asb, Bsb)
        if (more) {
            float* Asn = Asm + (buf^1)*ABUF;
            float* Bsn = Bsm + (buf^1)*2048;
            STA(Asn, nav.x, nav.y);
            *(float4*)&Bsn[bkr*128 + bnc]     = nb0;
            *(float4*)&Bsn[bkr*128 + bnc + 4] = nb1;
        }
        __syncthreads();
        buf ^= 1;
    }
    #pragma unroll
    for (int i = 0; i < 2; i++) {
        float* crow = &C[(size_t)(m0 + ty*2 + i) * ldb + col + tx*8];
        #pragma unroll
        for (int j = 0; j < 4; j++) *(float2*)&crow[2*j] = *(float2*)&acc[i][j];
    }
}

// ---------------- generic BM=32 GEMM + optional residual ----------------
__global__ __launch_bounds__(256) void sgemm_res(const float* __restrict__ A,
                                                 const float* __restrict__ B,
                                                 float* __restrict__ C,
                                                 const float* __restrict__ res,
                                                 int N, int K) {
    __shared__ float sm[2*ABUF + 2*16*128];
    float* Asm = sm;
    float* Bsm = sm + 2*ABUF;
    int n0 = blockIdx.x * 128, m0 = blockIdx.y * 32;
    int tid = threadIdx.x, ty = tid >> 4, tx = tid & 15;
    int amr = tid >> 3, akc = (tid & 7) * 2;
    int bkr = tid >> 4, bnc = (tid & 15) * 8;
    const float* Arow = &A[(size_t)(m0 + amr) * K];
    const float* Bp0 = &B[(size_t)bkr * N + n0 + bnc];
    u64 acc[2][4] = {};
    {
        float2 av = *(const float2*)&Arow[akc];
        float4 b0 = *(const float4*)Bp0;
        float4 b1 = *(const float4*)(Bp0 + 4);
        STA(Asm, av.x, av.y);
        *(float4*)&Bsm[bkr*128 + bnc]     = b0;
        *(float4*)&Bsm[bkr*128 + bnc + 4] = b1;
    }
    __syncthreads();
    int buf = 0;
    for (int k0 = 16; k0 <= K; k0 += 16) {
        float2 nav; float4 nb0, nb1;
        bool more = (k0 < K);
        if (more) {
            nav = *(const float2*)&Arow[k0 + akc];
            const float* bp = Bp0 + (size_t)k0 * N;
            nb0 = *(const float4*)bp;
            nb1 = *(const float4*)(bp + 4);
        }
        const float* Asb = Asm + buf*ABUF;
        const float* Bsb = Bsm + buf*2048;
        #pragma unroll
        for (int k = 0; k < 16; k++) KSTEP128(Asb, Bsb)
        if (more) {
            float* Asn = Asm + (buf^1)*ABUF;
            float* Bsn = Bsm + (buf^1)*2048;
            STA(Asn, nav.x, nav.y);
            *(float4*)&Bsn[bkr*128 + bnc]     = nb0;
            *(float4*)&Bsn[bkr*128 + bnc + 4] = nb1;
        }
        __syncthreads();
        buf ^= 1;
    }
    #pragma unroll
    for (int i = 0; i < 2; i++) {
        size_t ridx = (size_t)(m0 + ty*2 + i) * N + n0 + tx*8;
        if (res) {
            #pragma unroll
            for (int j = 0; j < 4; j++) {
                u64 rv = *(const u64*)&res[ridx + 2*j];
                u64 s = ad2(acc[i][j], rv);
                *(float2*)&C[ridx + 2*j] = *(float2*)&s;
            }
        } else {
            #pragma unroll
            for (int j = 0; j < 4; j++) *(float2*)&C[ridx + 2*j] = *(float2*)&acc[i][j];
        }
    }
}

// ---------------- fused FFN stage A: moe_gemm1 (512 blocks) + dual_shared (256) ----------------
__global__ __launch_bounds__(256) void ffn_a(const float* __restrict__ w1e,
                                             const float* __restrict__ w3e,
                                             const float* __restrict__ sw1,
                                             const float* __restrict__ sw3) {
    __shared__ float sm[2*ABUF + 4*16*64];
    __shared__ int s_p[32];
    float* Asm  = sm;
    float* B1sm = sm + 2*ABUF;
    float* B2sm = sm + 2*ABUF + 2*16*64;
    int tid = threadIdx.x, ty = tid >> 4, tx = tid & 15;
    int amr = tid >> 3, akc = (tid & 7) * 2;
    int bkr = tid >> 4, bnc = (tid & 15) * 4;
    int bid = blockIdx.x;

    if (bid < NE*8) {
        // ---- MoE GEMM1 ----
        int e  = bid >> 3;
        int n0 = (bid & 7) * 64;
        int n = g_cnt[e];
        if (n == 0) return;
        const int* lst = &g_list[e*SS];
        const float* B1p0 = &w1e[(size_t)e * DM * HE + (size_t)bkr * HE + n0 + bnc];
        const float* B2p0 = &w3e[(size_t)e * DM * HE + (size_t)bkr * HE + n0 + bnc];
        for (int m0 = 0; m0 < n; m0 += 32) {
            if (tid < 32) s_p[tid] = (m0 + tid < n) ? lst[m0 + tid] : -1;
            __syncthreads();
            int pz = s_p[amr];
            const float* Arow = &g_z[(size_t)(pz < 0 ? 0 : pz / TOPK) * DM];
            u64 acc1[2][2] = {}; u64 acc3[2][2] = {};
            {
                float2 av = *(const float2*)&Arow[akc];
                float4 b1 = *(const float4*)B1p0;
                float4 b2 = *(const float4*)B2p0;
                STA(Asm, av.x, av.y);
                *(float4*)&B1sm[bkr*64 + bnc] = b1;
                *(float4*)&B2sm[bkr*64 + bnc] = b2;
            }
            __syncthreads();
            int buf = 0;
            for (int k0 = 16; k0 <= DM; k0 += 16) {
                float2 nav; float4 nb1, nb2;
                bool more = (k0 < DM);
                if (more) {
                    nav = *(const float2*)&Arow[k0 + akc];
                    nb1 = *(const float4*)(B1p0 + (size_t)k0 * HE);
                    nb2 = *(const float4*)(B2p0 + (size_t)k0 * HE);
                }
                const float* Asb  = Asm  + buf*ABUF;
                const float* B1sb = B1sm + buf*1024;
                const float* B2sb = B2sm + buf*1024;
                #pragma unroll
                for (int k = 0; k < 16; k++) KSTEPD(Asb, B1sb, B2sb)
                if (more) {
                    float* Asn  = Asm  + (buf^1)*ABUF;
                    float* B1sn = B1sm + (buf^1)*1024;
                    float* B2sn = B2sm + (buf^1)*1024;
                    STA(Asn, nav.x, nav.y);
                    *(float4*)&B1sn[bkr*64 + bnc] = nb1;
                    *(float4*)&B2sn[bkr*64 + bnc] = nb2;
                }
                __syncthreads();
                buf ^= 1;
            }
            #pragma unroll
            for (int i = 0; i < 2; i++) {
                int pr = s_p[ty*2 + i];
                if (pr >= 0) {
                    float w = g_pairw[pr];
                    float* crow = &g_gbuf[(size_t)pr * HE + n0 + tx*4];
                    #pragma unroll
                    for (int p = 0; p < 2; p++) {
                        float x0,x1,y0,y1;
                        up2(x0,x1,acc1[i][p]); up2(y0,y1,acc3[i][p]);
                        float2 o;
                        o.x = (x0/(1.f+__expf(-x0))) * y0 * w;
                        o.y = (x1/(1.f+__expf(-x1))) * y1 * w;
                        *(float2*)&crow[2*p] = o;
                    }
                }
            }
            __syncthreads();
        }
    } else {
        // ---- shared expert dual GEMM ----
        int b = bid - NE*8;
        int n0 = (b & 7) * 64;
        int m0 = (b >> 3) * 32;
        const float* Arow = &g_z[(size_t)(m0 + amr) * DM];
        const float* B1p0 = &sw1[(size_t)bkr * HE + n0 + bnc];
        const float* B2p0 = &sw3[(size_t)bkr * HE + n0 + bnc];
        u64 acc1[2][2] = {}; u64 acc3[2][2] = {};
        {
            float2 av = *(const float2*)&Arow[akc];
            float4 b1 = *(const float4*)B1p0;
            float4 b2 = *(const float4*)B2p0;
            STA(Asm, av.x, av.y);
            *(float4*)&B1sm[bkr*64 + bnc] = b1;
            *(float4*)&B2sm[bkr*64 + bnc] = b2;
        }
        __syncthreads();
        int buf = 0;
        for (int k0 = 16; k0 <= DM; k0 += 16) {
            float2 nav; float4 nb1, nb2;
            bool more = (k0 < DM);
            if (more) {
                nav = *(const float2*)&Arow[k0 + akc];
                nb1 = *(const float4*)(B1p0 + (size_t)k0 * HE);
                nb2 = *(const float4*)(B2p0 + (size_t)k0 * HE);
            }
            const float* Asb  = Asm  + buf*ABUF;
            const float* B1sb = B1sm + buf*1024;
            const float* B2sb = B2sm + buf*1024;
            #pragma unroll
            for (int k = 0; k < 16; k++) KSTEPD(Asb, B1sb, B2sb)
            if (more) {
                float* Asn  = Asm  + (buf^1)*ABUF;
                float* B1sn = B1sm + (buf^1)*1024;
                float* B2sn = B2sm + (buf^1)*1024;
                STA(Asn, nav.x, nav.y);
                *(float4*)&B1sn[bkr*64 + bnc] = nb1;
                *(float4*)&B2sn[bkr*64 + bnc] = nb2;
            }
            __syncthreads();
            buf ^= 1;
        }
        #pragma unroll
        for (int i = 0; i < 2; i++) {
            float* crow = &g_a1[(size_t)(m0 + ty*2 + i) * HE + n0 + tx*4];
            #pragma unroll
            for (int p = 0; p < 2; p++) {
                float x0,x1,y0,y1;
                up2(x0,x1,acc1[i][p]); up2(y0,y1,acc3[i][p]);
                float2 o;
                o.x = (x0/(1.f+__expf(-x0))) * y0;
                o.y = (x1/(1.f+__expf(-x1))) * y1;
                *(float2*)&crow[2*p] = o;
            }
        }
    }
}

// ---------------- fused FFN stage B: moe_gemm2 (512 blocks) + sw2 (256) ----------------
__global__ __launch_bounds__(256) void ffn_b(const float* __restrict__ w2e,
                                             const float* __restrict__ sw2) {
    __shared__ float sm[2*ABUF + 2*16*128];
    __shared__ int s_p[32];
    float* Asm = sm;
    float* Bsm = sm + 2*ABUF;
    int tid = threadIdx.x, ty = tid >> 4, tx = tid & 15;
    int amr = tid >> 3, akc = (tid & 7) * 2;
    int bkr = tid >> 4, bnc = (tid & 15) * 8;
    int bid = blockIdx.x;

    if (bid < NE*8) {
        // ---- MoE GEMM2: K = HE ----
        int e  = bid >> 3;
        int n0 = (bid & 7) * 128;
        int n = g_cnt[e];
        if (n == 0) return;
        const int* lst = &g_list[e*SS];
        const float* Bp0 = &w2e[(size_t)e * HE * DM + (size_t)bkr * DM + n0 + bnc];
        for (int m0 = 0; m0 < n; m0 += 32) {
            if (tid < 32) s_p[tid] = (m0 + tid < n) ? lst[m0 + tid] : -1;
            __syncthreads();
            int pz = s_p[amr];
            const float* Arow = &g_gbuf[(size_t)(pz < 0 ? 0 : pz) * HE];
            u64 acc[2][4] = {};
            {
                float2 av = *(const float2*)&Arow[akc];
                float4 b0 = *(const float4*)Bp0;
                float4 b1 = *(const float4*)(Bp0 + 4);
                STA(Asm, av.x, av.y);
                *(float4*)&Bsm[bkr*128 + bnc]     = b0;
                *(float4*)&Bsm[bkr*128 + bnc + 4] = b1;
            }
            __syncthreads();
            int buf = 0;
            for (int k0 = 16; k0 <= HE; k0 += 16) {
                float2 nav; float4 nb0, nb1;
                bool more = (k0 < HE);
                if (more) {
                    nav = *(const float2*)&Arow[k0 + akc];
                    const float* bp = Bp0 + (size_t)k0 * DM;
                    nb0 = *(const float4*)bp;
                    nb1 = *(const float4*)(bp + 4);
                }
                const float* Asb = Asm + buf*ABUF;
                const float* Bsb = Bsm + buf*2048;
                #pragma unroll
                for (int k = 0; k < 16; k++) KSTEP128(Asb, Bsb)
                if (more) {
                    float* Asn = Asm + (buf^1)*ABUF;
                    float* Bsn = Bsm + (buf^1)*2048;
                    STA(Asn, nav.x, nav.y);
                    *(float4*)&Bsn[bkr*128 + bnc]     = nb0;
                    *(float4*)&Bsn[bkr*128 + bnc + 4] = nb1;
                }
                __syncthreads();
                buf ^= 1;
            }
            #pragma unroll
            for (int i = 0; i < 2; i++) {
                int pr = s_p[ty*2 + i];
                if (pr >= 0) {
                    float* crow = &g_g2[(size_t)pr * DM + n0 + tx*8];
                    #pragma unroll
                    for (int j = 0; j < 4; j++) *(float2*)&crow[2*j] = *(float2*)&acc[i][j];
                }
            }
            __syncthreads();
        }
    } else {
        // ---- shared expert down proj: g_sh = g_a1 @ sw2 (K=HE) ----
        int b = bid - NE*8;
        int n0 = (b & 7) * 128;
        int m0 = (b >> 3) * 32;
        const float* Arow = &g_a1[(size_t)(m0 + amr) * HE];
        const float* Bp0 = &sw2[(size_t)bkr * DM + n0 + bnc];
        u64 acc[2][4] = {};
        {
            float2 av = *(const float2*)&Arow[akc];
            float4 b0 = *(const float4*)Bp0;
            float4 b1 = *(const float4*)(Bp0 + 4);
            STA(Asm, av.x, av.y);
            *(float4*)&Bsm[bkr*128 + bnc]     = b0;
            *(float4*)&Bsm[bkr*128 + bnc + 4] = b1;
        }
        __syncthreads();
        int buf = 0;
        for (int k0 = 16; k0 <= HE; k0 += 16) {
            float2 nav; float4 nb0, nb1;
            bool more = (k0 < HE);
            if (more) {
                nav = *(const float2*)&Arow[k0 + akc];
                const float* bp = Bp0 + (size_t)k0 * DM;
                nb0 = *(const float4*)bp;
                nb1 = *(const float4*)(bp + 4);
            }
            const float* Asb = Asm + buf*ABUF;
            const float* Bsb = Bsm + buf*2048;
            #pragma unroll
            for (int k = 0; k < 16; k++) KSTEP128(Asb, Bsb)
            if (more) {
                float* Asn = Asm + (buf^1)*ABUF;
                float* Bsn = Bsm + (buf^1)*2048;
                STA(Asn, nav.x, nav.y);
                *(float4*)&Bsn[bkr*128 + bnc]     = nb0;
                *(float4*)&Bsn[bkr*128 + bnc + 4] = nb1;
            }
            __syncthreads();
            buf ^= 1;
        }
        #pragma unroll
        for (int i = 0; i < 2; i++) {
            float* crow = &g_sh[(size_t)(m0 + ty*2 + i) * DM + n0 + tx*8];
            #pragma unroll
            for (int j = 0; j < 4; j++) *(float2*)&crow[2*j] = *(float2*)&acc[i][j];
        }
    }
}

// ---------------- q/k rmsnorm + rope ----------------
__global__ __launch_bounds__(256) void qknorm_rope(const float* __restrict__ qw,
                                                   const float* __restrict__ kw,
                                                   const float* __restrict__ cosb,
                                                   const float* __restrict__ sinb) {
    int gw = (blockIdx.x * blockDim.x + threadIdx.x) >> 5;
    int lane = threadIdx.x & 31;
    if (gw >= SS * (NHQ + NKVH)) return;
    int t = gw / (NHQ + NKVH);
    int hh = gw % (NHQ + NKVH);
    float* base;
    const float* w;
    if (hh < NHQ) { base = &g_q[(size_t)t*(NHQ*HDIM) + hh*HDIM]; w = qw; }
    else          { base = &g_k[(size_t)t*(NKVH*HDIM) + (hh-NHQ)*HDIM]; w = kw; }
    int d0 = lane * 2;
    float v0 = base[d0], v1 = base[d0+1];
    float ss = v0*v0 + v1*v1;
    #pragma unroll
    for (int off = 16; off; off >>= 1) ss += __shfl_xor_sync(0xffffffffu, ss, off);
    float r = rsqrtf(ss * (1.0f/HDIM) + 1e-5f);
    float n0 = v0 * r * w[d0];
    float n1 = v1 * r * w[d0+1];
    float c = cosb[t*(HDIM/2) + lane];
    float s = sinb[t*(HDIM/2) + lane];
    base[d0]   = n0*c - n1*s;
    base[d0+1] = n0*s + n1*c;
}

// ---------------- flash attention (heavy blocks first) ----------------
#define FLASH_SMEM (4*64*65*4)
__global__ __launch_bounds__(256) void flash_attn() {
    extern __shared__ float smf[];
    float* Qs = smf;
    float* Ks = smf + 64*65;
    float* Vs = smf + 2*64*65;
    float* Ps = smf + 3*64*65;
    int qt = (int)gridDim.x - 1 - (int)blockIdx.x;
    int h = blockIdx.y;
    int kvh = h >> 2;
    int q0 = qt * 64;
    int tid = threadIdx.x;
    int tx = tid & 15, ty = tid >> 4;
    {
        int r = tid >> 2, c = (tid & 3) * 16;
        const float* src = &g_q[(size_t)(q0 + r)*(NHQ*HDIM) + h*HDIM + c];
        #pragma unroll
        for (int i = 0; i < 16; i += 4) {
            float4 vq = *(const float4*)(src + i);
            Qs[r*65+c+i]   = vq.x; Qs[r*65+c+i+1] = vq.y;
            Qs[r*65+c+i+2] = vq.z; Qs[r*65+c+i+3] = vq.w;
        }
    }
    float O[4][4] = {};
    float m_i[4] = {-1e30f,-1e30f,-1e30f,-1e30f};
    float l_i[4] = {};
    __syncthreads();
    for (int kt = 0; kt <= qt; kt++) {
        int k0 = kt * 64;
        {
            int r = tid >> 2, c = (tid & 3) * 16;
            const float* ksrc = &g_k[(size_t)(k0 + r)*(NKVH*HDIM) + kvh*HDIM + c];
            const float* vsrc = &g_v[(size_t)(k0 + r)*(NKVH*HDIM) + kvh*HDIM + c];
            #pragma unroll
            for (int i = 0; i < 16; i += 4) {
                float4 a = *(const float4*)(ksrc + i);
                float4 b = *(const float4*)(vsrc + i);
                Ks[r*65+c+i]=a.x; Ks[r*65+c+i+1]=a.y; Ks[r*65+c+i+2]=a.z; Ks[r*65+c+i+3]=a.w;
                Vs[r*65+c+i]=b.x; Vs[r*65+c+i+1]=b.y; Vs[r*65+c+i+2]=b.z; Vs[r*65+c+i+3]=b.w;
            }
        }
        __syncthreads();
        float s[4][4] = {};
        #pragma unroll 8
        for (int d = 0; d < 64; d++) {
            float qv[4], kv[4];
            #pragma unroll
            for (int i = 0; i < 4; i++) qv[i] = Qs[(ty*4+i)*65 + d];
            #pragma unroll
            for (int j = 0; j < 4; j++) kv[j] = Ks[(tx*4+j)*65 + d];
            #pragma unroll
            for (int i = 0; i < 4; i++)
                #pragma unroll
                for (int j = 0; j < 4; j++)
                    s[i][j] += qv[i]*kv[j];
        }
        const float sc = 0.125f;
        if (kt == qt) {
            #pragma unroll
            for (int i = 0; i < 4; i++)
                #pragma unroll
                for (int j = 0; j < 4; j++)
                    s[i][j] = (tx*4+j <= ty*4+i) ? s[i][j]*sc : -1e30f;
        } else {
            #pragma unroll
            for (int i = 0; i < 4; i++)
                #pragma unroll
                for (int j = 0; j < 4; j++)
                    s[i][j] *= sc;
        }
        #pragma unroll
        for (int i = 0; i < 4; i++) {
            float mx = fmaxf(fmaxf(s[i][0],s[i][1]), fmaxf(s[i][2],s[i][3]));
            mx = fmaxf(mx, __shfl_xor_sync(0xffffffffu, mx, 1));
            mx = fmaxf(mx, __shfl_xor_sync(0xffffffffu, mx, 2));
            mx = fmaxf(mx, __shfl_xor_sync(0xffffffffu, mx, 4));
            mx = fmaxf(mx, __shfl_xor_sync(0xffffffffu, mx, 8));
            float mn = fmaxf(m_i[i], mx);
            float scale = __expf(m_i[i] - mn);
            float rs = 0.f;
            #pragma unroll
            for (int j = 0; j < 4; j++) { float p = __expf(s[i][j]-mn); s[i][j]=p; rs += p; }
            rs += __shfl_xor_sync(0xffffffffu, rs, 1);
            rs += __shfl_xor_sync(0xffffffffu, rs, 2);
            rs += __shfl_xor_sync(0xffffffffu, rs, 4);
            rs += __shfl_xor_sync(0xffffffffu, rs, 8);
            l_i[i] = l_i[i]*scale + rs;
            m_i[i] = mn;
            #pragma unroll
            for (int j = 0; j < 4; j++) {
                O[i][j] *= scale;
                Ps[(ty*4+i)*65 + tx*4+j] = s[i][j];
            }
        }
        __syncthreads();
        #pragma unroll 4
        for (int jj = 0; jj < 64; jj++) {
            float pv[4], vv[4];
            #pragma unroll
            for (int i = 0; i < 4; i++) pv[i] = Ps[(ty*4+i)*65 + jj];
            #pragma unroll
            for (int j = 0; j < 4; j++) vv[j] = Vs[jj*65 + tx*4+j];
            #pragma unroll
            for (int i = 0; i < 4; i++)
                #pragma unroll
                for (int j = 0; j < 4; j++)
                    O[i][j] += pv[i]*vv[j];
        }
        __syncthreads();
    }
    #pragma unroll
    for (int i = 0; i < 4; i++) {
        float inv = 1.f / l_i[i];
        #pragma unroll
        for (int j = 0; j < 4; j++)
            g_attn[(size_t)(q0+ty*4+i)*(NHQ*HDIM) + h*HDIM + tx*4+j] = O[i][j]*inv;
    }
}

// ---------------- gate GEMM (N=64) ----------------
__global__ __launch_bounds__(256) void gemm64(const float* __restrict__ A,
                                              const float* __restrict__ B,
                                              float* __restrict__ C,
                                              int M, int N, int K) {
    __shared__ float As[16][64];
    __shared__ float Bs[16][64];
    int tid = threadIdx.x;
    int tx = tid & 15, ty = tid >> 4;
    int m0 = blockIdx.y * 64, n0 = blockIdx.x * 64;
    int ar = tid >> 2;
    int ac = (tid & 3) * 4;
    int br = tid >> 4;
    int bc = (tid & 15) * 4;
    float acc[4][4] = {};
    for (int k0 = 0; k0 < K; k0 += 16) {
        float4 av = *(const float4*)&A[(size_t)(m0 + ar)*K + k0 + ac];
        float4 bv = *(const float4*)&B[(size_t)(k0 + br)*N + n0 + bc];
        As[ac+0][ar] = av.x; As[ac+1][ar] = av.y;
        As[ac+2][ar] = av.z; As[ac+3][ar] = av.w;
        *(float4*)&Bs[br][bc] = bv;
        __syncthreads();
        #pragma unroll
        for (int k = 0; k < 16; k++) {
            float4 a = *(const float4*)&As[k][ty*4];
            float4 b = *(const float4*)&Bs[k][tx*4];
            float aa[4] = {a.x,a.y,a.z,a.w};
            float bb[4] = {b.x,b.y,b.z,b.w};
            #pragma unroll
            for (int i = 0; i < 4; i++)
                #pragma unroll
                for (int j = 0; j < 4; j++)
                    acc[i][j] += aa[i]*bb[j];
        }
        __syncthreads();
    }
    #pragma unroll
    for (int i = 0; i < 4; i++) {
        float4 ov = make_float4(acc[i][0],acc[i][1],acc[i][2],acc[i][3]);
        *(float4*)&C[(size_t)(m0 + ty*4 + i)*N + n0 + tx*4] = ov;
    }
}

// ---------------- routing ----------------
__global__ void zero_cnt_k() { if (threadIdx.x < NE) g_cnt[threadIdx.x] = 0; }

__global__ void route_k() {
    int t = blockIdx.x;
    int lane = threadIdx.x;
    float v0 = g_logits[t*NE + lane];
    float v1 = g_logits[t*NE + 32 + lane];
    float selv[TOPK]; int seli[TOPK];
    #pragma unroll
    for (int it = 0; it < TOPK; it++) {
        float best = (v0 >= v1) ? v0 : v1;
        int   bi   = (v0 >= v1) ? lane : lane + 32;
        #pragma unroll
        for (int off = 16; off; off >>= 1) {
            float ov = __shfl_xor_sync(0xffffffffu, best, off);
            int   oi = __shfl_xor_sync(0xffffffffu, bi, off);
            if (ov > best || (ov == best && oi < bi)) { best = ov; bi = oi; }
        }
        selv[it] = best; seli[it] = bi;
        if (bi == lane)      v0 = -1e30f;
        if (bi == lane + 32) v1 = -1e30f;
    }
    if (lane < TOPK) {
        float sum = 0.f;
        #pragma unroll
        for (int i = 0; i < TOPK; i++) sum += __expf(selv[i] - selv[0]);
        float w = __expf(selv[lane] - selv[0]) / sum;
        int e = seli[lane];
        int pos = atomicAdd(&g_cnt[e], 1);
        g_list[e*SS + pos] = t*TOPK + lane;
        g_pairw[t*TOPK + lane] = w;
    }
}

// ---------------- final ----------------
__global__ __launch_bounds__(256) void final_k(float* __restrict__ out) {
    int t = blockIdx.x;
    int c = threadIdx.x * 4;
    float4 a = *(const float4*)&g_h[(size_t)t*DM + c];
    float4 b = *(const float4*)&g_sh[(size_t)t*DM + c];
    a.x += b.x; a.y += b.y; a.z += b.z; a.w += b.w;
    #pragma unroll
    for (int kk = 0; kk < TOPK; kk++) {
        float4 gv = *(const float4*)&g_g2[(size_t)(t*TOPK+kk)*DM + c];
        a.x += gv.x; a.y += gv.y; a.z += gv.z; a.w += gv.w;
    }
    *(float4*)&out[(size_t)t*DM + c] = a;
}

// ---------------- host ----------------
extern "C" void kernel_launch(void* const* d_in, const int* in_sizes, int n_in,
                              void* d_out, int out_size) {
    const float* x   = (const float*)d_in[0];
    const float* fc  = (const float*)d_in[1];
    const float* fs  = (const float*)d_in[2];
    const float* anw = (const float*)d_in[3];
    const float* fnw = (const float*)d_in[4];
    const float* wq  = (const float*)d_in[5];
    const float* wk  = (const float*)d_in[6];
    const float* wv  = (const float*)d_in[7];
    const float* wo  = (const float*)d_in[8];
    const float* qnw = (const float*)d_in[9];
    const float* knw = (const float*)d_in[10];
    const float* gw  = (const float*)d_in[11];
    const float* w1e = (const float*)d_in[12];
    const float* w3e = (const float*)d_in[13];
    const float* w2e = (const float*)d_in[14];
    const float* sw1 = (const float*)d_in[15];
    const float* sw3 = (const float*)d_in[16];
    const float* sw2 = (const float*)d_in[17];
    float* out = (float*)d_out;

    float *hx,*attn,*h,*z,*logits;
    cudaGetSymbolAddress((void**)&hx, g_hx);
    cudaGetSymbolAddress((void**)&attn, g_attn);
    cudaGetSymbolAddress((void**)&h,  g_h);
    cudaGetSymbolAddress((void**)&z,  g_z);
    cudaGetSymbolAddress((void**)&logits, g_logits);

    cudaFuncSetAttribute(flash_attn, cudaFuncAttributeMaxDynamicSharedMemorySize, FLASH_SMEM);

    // attention branch
    rmsnorm_k<<<SS, 256>>>(x, anw, hx);
    qkv_gemm<<<dim3(12, 32), 256>>>(hx, wq, wk, wv);
    qknorm_rope<<<(SS*(NHQ+NKVH)*32)/256, 256>>>(qnw, knw, fc, fs);
    flash_attn<<<dim3(16,16), 256, FLASH_SMEM>>>();
    sgemm_res<<<dim3(8, 32), 256>>>(attn, wo, h, x, 1024, 1024);   // h = attn@wo + x

    // ffn branch
    rmsnorm_k<<<SS, 256>>>(h, fnw, z);
    gemm64<<<dim3(1, 16), 256>>>(z, gw, logits, SS, NE, DM);
    zero_cnt_k<<<1, 64>>>();
    route_k<<<SS, 32>>>();
    ffn_a<<<NE*8 + 256, 256>>>(w1e, w3e, sw1, sw3);   // moe1 + dual_shared fused
    ffn_b<<<NE*8 + 256, 256>>>(w2e, sw2);             // moe2 + sw2 fused

    final_k<<<SS, 256>>>(out);
}

// round 7
// speedup vs baseline: 1.5680x; 1.5680x over previous
#include <cuda_runtime.h>
#include <math.h>

#define SS 1024
#define DM 1024
#define NHQ 16
#define NKVH 4
#define HDIM 64
#define NE 64
#define TOPK 6
#define HE 512
#define NPAIR (SS*TOPK)

typedef unsigned long long u64;

// ---------------- packed f32x2 helpers ----------------
__device__ __forceinline__ u64 pk2(float x) {
    u64 r; asm("mov.b64 %0,{%1,%1};" : "=l"(r) : "f"(x)); return r;
}
__device__ __forceinline__ void fm2(u64 &d, u64 a, u64 b) {
    asm("fma.rn.f32x2 %0,%1,%2,%0;" : "+l"(d) : "l"(a), "l"(b));
}
__device__ __forceinline__ u64 ad2(u64 a, u64 b) {
    u64 d; asm("add.rn.f32x2 %0,%1,%2;" : "=l"(d) : "l"(a), "l"(b)); return d;
}
__device__ __forceinline__ void up2(float &lo, float &hi, u64 v) {
    asm("mov.b64 {%0,%1},%2;" : "=f"(lo), "=f"(hi) : "l"(v));
}

// ---------------- scratch ----------------
__device__ float g_hx[SS*DM];
__device__ float g_q[SS*NHQ*HDIM];
__device__ float g_k[SS*NKVH*HDIM];
__device__ float g_v[SS*NKVH*HDIM];
__device__ float g_attn[SS*NHQ*HDIM];
__device__ float g_h[SS*DM];
__device__ float g_z[SS*DM];
__device__ float g_logits[SS*NE];
__device__ float g_pairw[NPAIR];
__device__ int   g_cnt[NE];
__device__ int   g_list[NE*SS];
__device__ float g_gbuf[(size_t)NPAIR*HE];
__device__ float g_g2[(size_t)NPAIR*DM];
__device__ float g_a1[SS*HE];
__device__ float g_sh[SS*DM];

// ---------------- rmsnorm ----------------
__global__ __launch_bounds__(256) void rmsnorm_k(const float* __restrict__ x,
                                                 const float* __restrict__ w,
                                                 float* __restrict__ out) {
    int t = blockIdx.x;
    int tid = threadIdx.x;
    float4 xv = *(const float4*)&x[(size_t)t*DM + tid*4];
    float ss = xv.x*xv.x + xv.y*xv.y + xv.z*xv.z + xv.w*xv.w;
    #pragma unroll
    for (int off = 16; off; off >>= 1) ss += __shfl_xor_sync(0xffffffffu, ss, off);
    __shared__ float red[8];
    if ((tid & 31) == 0) red[tid >> 5] = ss;
    __syncthreads();
    float tot = 0.f;
    #pragma unroll
    for (int i = 0; i < 8; i++) tot += red[i];
    float r = rsqrtf(tot * (1.0f/DM) + 1e-5f);
    float4 wv = *(const float4*)&w[tid*4];
    float4 ov;
    ov.x = wv.x * (xv.x * r); ov.y = wv.y * (xv.y * r);
    ov.z = wv.z * (xv.z * r); ov.w = wv.w * (xv.w * r);
    *(float4*)&out[(size_t)t*DM + tid*4] = ov;
}

// ============ FFMA2 tile: BM=64, BN=128, BK=16, 256 thr, TM=4, TN=8 ============
#define GEMM_K_STEP(Ap, Bp)                                                        \
    {                                                                              \
        float4 a = *(const float4*)&(Ap)[k*68 + ty*4];                             \
        u64 pa0 = pk2(a.x), pa1 = pk2(a.y), pa2 = pk2(a.z), pa3 = pk2(a.w);        \
        ulonglong2 q0 = *(const ulonglong2*)&(Bp)[k*128 + tx*8];                   \
        ulonglong2 q1 = *(const ulonglong2*)&(Bp)[k*128 + tx*8 + 4];               \
        fm2(acc[0][0],pa0,q0.x); fm2(acc[0][1],pa0,q0.y);                          \
        fm2(acc[0][2],pa0,q1.x); fm2(acc[0][3],pa0,q1.y);                          \
        fm2(acc[1][0],pa1,q0.x); fm2(acc[1][1],pa1,q0.y);                          \
        fm2(acc[1][2],pa1,q1.x); fm2(acc[1][3],pa1,q1.y);                          \
        fm2(acc[2][0],pa2,q0.x); fm2(acc[2][1],pa2,q0.y);                          \
        fm2(acc[2][2],pa2,q1.x); fm2(acc[2][3],pa2,q1.y);                          \
        fm2(acc[3][0],pa3,q0.x); fm2(acc[3][1],pa3,q0.y);                          \
        fm2(acc[3][2],pa3,q1.x); fm2(acc[3][3],pa3,q1.y);                          \
    }

#define STORE_A(Ap, av)                                                            \
    { (Ap)[(akc+0)*68 + amr] = (av).x; (Ap)[(akc+1)*68 + amr] = (av).y;            \
      (Ap)[(akc+2)*68 + amr] = (av).z; (Ap)[(akc+3)*68 + amr] = (av).w; }

// ---------------- fused QKV GEMM (double-buffered) ----------------
__global__ __launch_bounds__(256) void qkv_gemm(const float* __restrict__ A,
                                                const float* __restrict__ wq,
                                                const float* __restrict__ wk,
                                                const float* __restrict__ wv) {
    __shared__ float As[2][16*68];
    __shared__ float Bs[2][16*128];
    int bn = blockIdx.x, m0 = blockIdx.y * 64;
    const float* B; float* C; int ldb; int col;
    if (bn < 8)       { B = wq; C = g_q; ldb = 1024; col = bn * 128; }
    else if (bn < 10) { B = wk; C = g_k; ldb = 256;  col = (bn - 8) * 128; }
    else              { B = wv; C = g_v; ldb = 256;  col = (bn - 10) * 128; }
    int tid = threadIdx.x, ty = tid >> 4, tx = tid & 15;
    int amr = tid >> 2, akc = (tid & 3) * 4;
    int bkr = tid >> 4, bnc = (tid & 15) * 8;
    const float* Arow = &A[(size_t)(m0 + amr) * DM];
    const float* Bp0 = &B[(size_t)bkr * ldb + col + bnc];
    u64 acc[4][4] = {};
    {
        float4 av = *(const float4*)&Arow[akc];
        float4 b0 = *(const float4*)Bp0;
        float4 b1 = *(const float4*)(Bp0 + 4);
        STORE_A(As[0], av);
        *(float4*)&Bs[0][bkr*128 + bnc]     = b0;
        *(float4*)&Bs[0][bkr*128 + bnc + 4] = b1;
    }
    __syncthreads();
    int buf = 0;
    for (int k0 = 16; k0 <= DM; k0 += 16) {
        float4 nav, nb0, nb1;
        bool more = (k0 < DM);
        if (more) {
            nav = *(const float4*)&Arow[k0 + akc];
            const float* bp = Bp0 + (size_t)k0 * ldb;
            nb0 = *(const float4*)bp;
            nb1 = *(const float4*)(bp + 4);
        }
        #pragma unroll
        for (int k = 0; k < 16; k++) GEMM_K_STEP(As[buf], Bs[buf])
        if (more) {
            STORE_A(As[buf^1], nav);
            *(float4*)&Bs[buf^1][bkr*128 + bnc]     = nb0;
            *(float4*)&Bs[buf^1][bkr*128 + bnc + 4] = nb1;
        }
        __syncthreads();
        buf ^= 1;
    }
    #pragma unroll
    for (int i = 0; i < 4; i++) {
        float* crow = &C[(size_t)(m0 + ty*4 + i) * ldb + col + tx*8];
        #pragma unroll
        for (int j = 0; j < 4; j++) *(float2*)&crow[2*j] = *(float2*)&acc[i][j];
    }
}

// ---------------- generic GEMM + optional residual (double-buffered) ----------------
__global__ __launch_bounds__(256) void sgemm_res(const float* __restrict__ A,
                                                 const float* __restrict__ B,
                                                 float* __restrict__ C,
                                                 const float* __restrict__ res,
                                                 int N, int K) {
    __shared__ float As[2][16*68];
    __shared__ float Bs[2][16*128];
    int n0 = blockIdx.x * 128, m0 = blockIdx.y * 64;
    int tid = threadIdx.x, ty = tid >> 4, tx = tid & 15;
    int amr = tid >> 2, akc = (tid & 3) * 4;
    int bkr = tid >> 4, bnc = (tid & 15) * 8;
    const float* Arow = &A[(size_t)(m0 + amr) * K];
    const float* Bp0 = &B[(size_t)bkr * N + n0 + bnc];
    u64 acc[4][4] = {};
    {
        float4 av = *(const float4*)&Arow[akc];
        float4 b0 = *(const float4*)Bp0;
        float4 b1 = *(const float4*)(Bp0 + 4);
        STORE_A(As[0], av);
        *(float4*)&Bs[0][bkr*128 + bnc]     = b0;
        *(float4*)&Bs[0][bkr*128 + bnc + 4] = b1;
    }
    __syncthreads();
    int buf = 0;
    for (int k0 = 16; k0 <= K; k0 += 16) {
        float4 nav, nb0, nb1;
        bool more = (k0 < K);
        if (more) {
            nav = *(const float4*)&Arow[k0 + akc];
            const float* bp = Bp0 + (size_t)k0 * N;
            nb0 = *(const float4*)bp;
            nb1 = *(const float4*)(bp + 4);
        }
        #pragma unroll
        for (int k = 0; k < 16; k++) GEMM_K_STEP(As[buf], Bs[buf])
        if (more) {
            STORE_A(As[buf^1], nav);
            *(float4*)&Bs[buf^1][bkr*128 + bnc]     = nb0;
            *(float4*)&Bs[buf^1][bkr*128 + bnc + 4] = nb1;
        }
        __syncthreads();
        buf ^= 1;
    }
    #pragma unroll
    for (int i = 0; i < 4; i++) {
        size_t ridx = (size_t)(m0 + ty*4 + i) * N + n0 + tx*8;
        if (res) {
            #pragma unroll
            for (int j = 0; j < 4; j++) {
                u64 rv = *(const u64*)&res[ridx + 2*j];
                u64 s = ad2(acc[i][j], rv);
                *(float2*)&C[ridx + 2*j] = *(float2*)&s;
            }
        } else {
            #pragma unroll
            for (int j = 0; j < 4; j++) *(float2*)&C[ridx + 2*j] = *(float2*)&acc[i][j];
        }
    }
}

// ---------------- fused FFN stage A: MoE GEMM1 (512 blocks) + shared dual GEMM (128) ----------------
__global__ __launch_bounds__(256) void ffn_a(const float* __restrict__ w1e,
                                             const float* __restrict__ w3e,
                                             const float* __restrict__ sw1,
                                             const float* __restrict__ sw3) {
    __shared__ float As[2][16*68];
    __shared__ float B1s[2][16*64];
    __shared__ float B2s[2][16*64];
    __shared__ int s_p[64];
    int tid = threadIdx.x, ty = tid >> 4, tx = tid & 15;
    int amr = tid >> 2, akc = (tid & 3) * 4;
    int bkr = tid >> 4, bnc = (tid & 15) * 4;
    int bid = blockIdx.x;

    if (bid < NE*8) {
        // ---- MoE GEMM1 ----
        int e  = bid >> 3;
        int n0 = (bid & 7) * 64;
        int n = g_cnt[e];
        if (n == 0) return;
        const int* lst = &g_list[e*SS];
        const float* B1p0 = &w1e[(size_t)e * DM * HE + (size_t)bkr * HE + n0 + bnc];
        const float* B2p0 = &w3e[(size_t)e * DM * HE + (size_t)bkr * HE + n0 + bnc];
        for (int m0 = 0; m0 < n; m0 += 64) {
            if (tid < 64) s_p[tid] = (m0 + tid < n) ? lst[m0 + tid] : -1;
            __syncthreads();
            int pz = s_p[amr];
            const float* Arow = &g_z[(size_t)(pz < 0 ? 0 : pz / TOPK) * DM];
            u64 acc1[4][2] = {}; u64 acc3[4][2] = {};
            {
                float4 av = *(const float4*)&Arow[akc];
                float4 b1 = *(const float4*)B1p0;
                float4 b2 = *(const float4*)B2p0;
                STORE_A(As[0], av);
                *(float4*)&B1s[0][bkr*64 + bnc] = b1;
                *(float4*)&B2s[0][bkr*64 + bnc] = b2;
            }
            __syncthreads();
            int buf = 0;
            for (int k0 = 16; k0 <= DM; k0 += 16) {
                float4 nav, nb1, nb2;
                bool more = (k0 < DM);
                if (more) {
                    nav = *(const float4*)&Arow[k0 + akc];
                    nb1 = *(const float4*)(B1p0 + (size_t)k0 * HE);
                    nb2 = *(const float4*)(B2p0 + (size_t)k0 * HE);
                }
                #pragma unroll
                for (int k = 0; k < 16; k++) {
                    float4 a = *(const float4*)&As[buf][k*68 + ty*4];
                    u64 pa0 = pk2(a.x), pa1 = pk2(a.y), pa2 = pk2(a.z), pa3 = pk2(a.w);
                    ulonglong2 r1 = *(const ulonglong2*)&B1s[buf][k*64 + tx*4];
                    ulonglong2 r2 = *(const ulonglong2*)&B2s[buf][k*64 + tx*4];
                    fm2(acc1[0][0],pa0,r1.x); fm2(acc1[0][1],pa0,r1.y);
                    fm2(acc1[1][0],pa1,r1.x); fm2(acc1[1][1],pa1,r1.y);
                    fm2(acc1[2][0],pa2,r1.x); fm2(acc1[2][1],pa2,r1.y);
                    fm2(acc1[3][0],pa3,r1.x); fm2(acc1[3][1],pa3,r1.y);
                    fm2(acc3[0][0],pa0,r2.x); fm2(acc3[0][1],pa0,r2.y);
                    fm2(acc3[1][0],pa1,r2.x); fm2(acc3[1][1],pa1,r2.y);
                    fm2(acc3[2][0],pa2,r2.x); fm2(acc3[2][1],pa2,r2.y);
                    fm2(acc3[3][0],pa3,r2.x); fm2(acc3[3][1],pa3,r2.y);
                }
                if (more) {
                    STORE_A(As[buf^1], nav);
                    *(float4*)&B1s[buf^1][bkr*64 + bnc] = nb1;
                    *(float4*)&B2s[buf^1][bkr*64 + bnc] = nb2;
                }
                __syncthreads();
                buf ^= 1;
            }
            #pragma unroll
            for (int i = 0; i < 4; i++) {
                int pr = s_p[ty*4 + i];
                if (pr >= 0) {
                    float w = g_pairw[pr];
                    float* crow = &g_gbuf[(size_t)pr * HE + n0 + tx*4];
                    #pragma unroll
                    for (int p = 0; p < 2; p++) {
                        float x0,x1,y0,y1;
                        up2(x0,x1,acc1[i][p]); up2(y0,y1,acc3[i][p]);
                        float2 o;
                        o.x = (x0/(1.f+__expf(-x0))) * y0 * w;
                        o.y = (x1/(1.f+__expf(-x1))) * y1 * w;
                        *(float2*)&crow[2*p] = o;
                    }
                }
            }
            __syncthreads();
        }
    } else {
        // ---- shared expert dual GEMM: g_a1 = silu(z@sw1)*(z@sw3) ----
        int b = bid - NE*8;
        int n0 = (b & 7) * 64;
        int m0 = (b >> 3) * 64;
        const float* Arow = &g_z[(size_t)(m0 + amr) * DM];
        const float* B1p0 = &sw1[(size_t)bkr * HE + n0 + bnc];
        const float* B2p0 = &sw3[(size_t)bkr * HE + n0 + bnc];
        u64 acc1[4][2] = {}; u64 acc3[4][2] = {};
        {
            float4 av = *(const float4*)&Arow[akc];
            float4 b1 = *(const float4*)B1p0;
            float4 b2 = *(const float4*)B2p0;
            STORE_A(As[0], av);
            *(float4*)&B1s[0][bkr*64 + bnc] = b1;
            *(float4*)&B2s[0][bkr*64 + bnc] = b2;
        }
        __syncthreads();
        int buf = 0;
        for (int k0 = 16; k0 <= DM; k0 += 16) {
            float4 nav, nb1, nb2;
            bool more = (k0 < DM);
            if (more) {
                nav = *(const float4*)&Arow[k0 + akc];
                nb1 = *(const float4*)(B1p0 + (size_t)k0 * HE);
                nb2 = *(const float4*)(B2p0 + (size_t)k0 * HE);
            }
            #pragma unroll
            for (int k = 0; k < 16; k++) {
                float4 a = *(const float4*)&As[buf][k*68 + ty*4];
                u64 pa0 = pk2(a.x), pa1 = pk2(a.y), pa2 = pk2(a.z), pa3 = pk2(a.w);
                ulonglong2 r1 = *(const ulonglong2*)&B1s[buf][k*64 + tx*4];
                ulonglong2 r2 = *(const ulonglong2*)&B2s[buf][k*64 + tx*4];
                fm2(acc1[0][0],pa0,r1.x); fm2(acc1[0][1],pa0,r1.y);
                fm2(acc1[1][0],pa1,r1.x); fm2(acc1[1][1],pa1,r1.y);
                fm2(acc1[2][0],pa2,r1.x); fm2(acc1[2][1],pa2,r1.y);
                fm2(acc1[3][0],pa3,r1.x); fm2(acc1[3][1],pa3,r1.y);
                fm2(acc3[0][0],pa0,r2.x); fm2(acc3[0][1],pa0,r2.y);
                fm2(acc3[1][0],pa1,r2.x); fm2(acc3[1][1],pa1,r2.y);
                fm2(acc3[2][0],pa2,r2.x); fm2(acc3[2][1],pa2,r2.y);
                fm2(acc3[3][0],pa3,r2.x); fm2(acc3[3][1],pa3,r2.y);
            }
            if (more) {
                STORE_A(As[buf^1], nav);
                *(float4*)&B1s[buf^1][bkr*64 + bnc] = nb1;
                *(float4*)&B2s[buf^1][bkr*64 + bnc] = nb2;
            }
            __syncthreads();
            buf ^= 1;
        }
        #pragma unroll
        for (int i = 0; i < 4; i++) {
            float* crow = &g_a1[(size_t)(m0 + ty*4 + i) * HE + n0 + tx*4];
            #pragma unroll
            for (int p = 0; p < 2; p++) {
                float x0,x1,y0,y1;
                up2(x0,x1,acc1[i][p]); up2(y0,y1,acc3[i][p]);
                float2 o;
                o.x = (x0/(1.f+__expf(-x0))) * y0;
                o.y = (x1/(1.f+__expf(-x1))) * y1;
                *(float2*)&crow[2*p] = o;
            }
        }
    }
}

// ---------------- fused FFN stage B: MoE GEMM2 (512 blocks) + shared down proj (128) ----------------
__global__ __launch_bounds__(256) void ffn_b(const float* __restrict__ w2e,
                                             const float* __restrict__ sw2) {
    __shared__ float As[2][16*68];
    __shared__ float Bs[2][16*128];
    __shared__ int s_p[64];
    int tid = threadIdx.x, ty = tid >> 4, tx = tid & 15;
    int amr = tid >> 2, akc = (tid & 3) * 4;
    int bkr = tid >> 4, bnc = (tid & 15) * 8;
    int bid = blockIdx.x;

    if (bid < NE*8) {
        // ---- MoE GEMM2: g_g2[p] = g_gbuf[p] @ W2_e  (K=HE) ----
        int e  = bid >> 3;
        int n0 = (bid & 7) * 128;
        int n = g_cnt[e];
        if (n == 0) return;
        const int* lst = &g_list[e*SS];
        const float* Bp0 = &w2e[(size_t)e * HE * DM + (size_t)bkr * DM + n0 + bnc];
        for (int m0 = 0; m0 < n; m0 += 64) {
            if (tid < 64) s_p[tid] = (m0 + tid < n) ? lst[m0 + tid] : -1;
            __syncthreads();
            int pz = s_p[amr];
            const float* Arow = &g_gbuf[(size_t)(pz < 0 ? 0 : pz) * HE];
            u64 acc[4][4] = {};
            {
                float4 av = *(const float4*)&Arow[akc];
                float4 b0 = *(const float4*)Bp0;
                float4 b1 = *(const float4*)(Bp0 + 4);
                STORE_A(As[0], av);
                *(float4*)&Bs[0][bkr*128 + bnc]     = b0;
                *(float4*)&Bs[0][bkr*128 + bnc + 4] = b1;
            }
            __syncthreads();
            int buf = 0;
            for (int k0 = 16; k0 <= HE; k0 += 16) {
                float4 nav, nb0, nb1;
                bool more = (k0 < HE);
                if (more) {
                    nav = *(const float4*)&Arow[k0 + akc];
                    const float* bp = Bp0 + (size_t)k0 * DM;
                    nb0 = *(const float4*)bp;
                    nb1 = *(const float4*)(bp + 4);
                }
                #pragma unroll
                for (int k = 0; k < 16; k++) GEMM_K_STEP(As[buf], Bs[buf])
                if (more) {
                    STORE_A(As[buf^1], nav);
                    *(float4*)&Bs[buf^1][bkr*128 + bnc]     = nb0;
                    *(float4*)&Bs[buf^1][bkr*128 + bnc + 4] = nb1;
                }
                __syncthreads();
                buf ^= 1;
            }
            #pragma unroll
            for (int i = 0; i < 4; i++) {
                int pr = s_p[ty*4 + i];
                if (pr >= 0) {
                    float* crow = &g_g2[(size_t)pr * DM + n0 + tx*8];
                    #pragma unroll
                    for (int j = 0; j < 4; j++) *(float2*)&crow[2*j] = *(float2*)&acc[i][j];
                }
            }
            __syncthreads();
        }
    } else {
        // ---- shared expert down proj: g_sh = g_a1 @ sw2  (K=HE) ----
        int b = bid - NE*8;
        int n0 = (b & 7) * 128;
        int m0 = (b >> 3) * 64;
        const float* Arow = &g_a1[(size_t)(m0 + amr) * HE];
        const float* Bp0 = &sw2[(size_t)bkr * DM + n0 + bnc];
        u64 acc[4][4] = {};
        {
            float4 av = *(const float4*)&Arow[akc];
            float4 b0 = *(const float4*)Bp0;
            float4 b1 = *(const float4*)(Bp0 + 4);
            STORE_A(As[0], av);
            *(float4*)&Bs[0][bkr*128 + bnc]     = b0;
            *(float4*)&Bs[0][bkr*128 + bnc + 4] = b1;
        }
        __syncthreads();
        int buf = 0;
        for (int k0 = 16; k0 <= HE; k0 += 16) {
            float4 nav, nb0, nb1;
            bool more = (k0 < HE);
            if (more) {
                nav = *(const float4*)&Arow[k0 + akc];
                const float* bp = Bp0 + (size_t)k0 * DM;
                nb0 = *(const float4*)bp;
                nb1 = *(const float4*)(bp + 4);
            }
            #pragma unroll
            for (int k = 0; k < 16; k++) GEMM_K_STEP(As[buf], Bs[buf])
            if (more) {
                STORE_A(As[buf^1], nav);
                *(float4*)&Bs[buf^1][bkr*128 + bnc]     = nb0;
                *(float4*)&Bs[buf^1][bkr*128 + bnc + 4] = nb1;
            }
            __syncthreads();
            buf ^= 1;
        }
        #pragma unroll
        for (int i = 0; i < 4; i++) {
            float* crow = &g_sh[(size_t)(m0 + ty*4 + i) * DM + n0 + tx*8];
            #pragma unroll
            for (int j = 0; j < 4; j++) *(float2*)&crow[2*j] = *(float2*)&acc[i][j];
        }
    }
}

// ---------------- q/k rmsnorm + rope ----------------
__global__ __launch_bounds__(256) void qknorm_rope(const float* __restrict__ qw,
                                                   const float* __restrict__ kw,
                                                   const float* __restrict__ cosb,
                                                   const float* __restrict__ sinb) {
    int gw = (blockIdx.x * blockDim.x + threadIdx.x) >> 5;
    int lane = threadIdx.x & 31;
    if (gw >= SS * (NHQ + NKVH)) return;
    int t = gw / (NHQ + NKVH);
    int hh = gw % (NHQ + NKVH);
    float* base;
    const float* w;
    if (hh < NHQ) { base = &g_q[(size_t)t*(NHQ*HDIM) + hh*HDIM]; w = qw; }
    else          { base = &g_k[(size_t)t*(NKVH*HDIM) + (hh-NHQ)*HDIM]; w = kw; }
    int d0 = lane * 2;
    float v0 = base[d0], v1 = base[d0+1];
    float ss = v0*v0 + v1*v1;
    #pragma unroll
    for (int off = 16; off; off >>= 1) ss += __shfl_xor_sync(0xffffffffu, ss, off);
    float r = rsqrtf(ss * (1.0f/HDIM) + 1e-5f);
    float n0 = v0 * r * w[d0];
    float n1 = v1 * r * w[d0+1];
    float c = cosb[t*(HDIM/2) + lane];
    float s = sinb[t*(HDIM/2) + lane];
    base[d0]   = n0*c - n1*s;
    base[d0+1] = n0*s + n1*c;
}

// ---------------- flash attention (heavy blocks first) ----------------
#define FLASH_SMEM (4*64*65*4)
__global__ __launch_bounds__(256) void flash_attn() {
    extern __shared__ float smf[];
    float* Qs = smf;
    float* Ks = smf + 64*65;
    float* Vs = smf + 2*64*65;
    float* Ps = smf + 3*64*65;
    int qt = (int)gridDim.x - 1 - (int)blockIdx.x;
    int h = blockIdx.y;
    int kvh = h >> 2;
    int q0 = qt * 64;
    int tid = threadIdx.x;
    int tx = tid & 15, ty = tid >> 4;
    {
        int r = tid >> 2, c = (tid & 3) * 16;
        const float* src = &g_q[(size_t)(q0 + r)*(NHQ*HDIM) + h*HDIM + c];
        #pragma unroll
        for (int i = 0; i < 16; i += 4) {
            float4 vq = *(const float4*)(src + i);
            Qs[r*65+c+i]   = vq.x; Qs[r*65+c+i+1] = vq.y;
            Qs[r*65+c+i+2] = vq.z; Qs[r*65+c+i+3] = vq.w;
        }
    }
    float O[4][4] = {};
    float m_i[4] = {-1e30f,-1e30f,-1e30f,-1e30f};
    float l_i[4] = {};
    __syncthreads();
    for (int kt = 0; kt <= qt; kt++) {
        int k0 = kt * 64;
        {
            int r = tid >> 2, c = (tid & 3) * 16;
            const float* ksrc = &g_k[(size_t)(k0 + r)*(NKVH*HDIM) + kvh*HDIM + c];
            const float* vsrc = &g_v[(size_t)(k0 + r)*(NKVH*HDIM) + kvh*HDIM + c];
            #pragma unroll
            for (int i = 0; i < 16; i += 4) {
                float4 a = *(const float4*)(ksrc + i);
                float4 b = *(const float4*)(vsrc + i);
                Ks[r*65+c+i]=a.x; Ks[r*65+c+i+1]=a.y; Ks[r*65+c+i+2]=a.z; Ks[r*65+c+i+3]=a.w;
                Vs[r*65+c+i]=b.x; Vs[r*65+c+i+1]=b.y; Vs[r*65+c+i+2]=b.z; Vs[r*65+c+i+3]=b.w;
            }
        }
        __syncthreads();
        float s[4][4] = {};
        #pragma unroll 8
        for (int d = 0; d < 64; d++) {
            float qv[4], kv[4];
            #pragma unroll
            for (int i = 0; i < 4; i++) qv[i] = Qs[(ty*4+i)*65 + d];
            #pragma unroll
            for (int j = 0; j < 4; j++) kv[j] = Ks[(tx*4+j)*65 + d];
            #pragma unroll
            for (int i = 0; i < 4; i++)
                #pragma unroll
                for (int j = 0; j < 4; j++)
                    s[i][j] += qv[i]*kv[j];
        }
        const float sc = 0.125f;
        if (kt == qt) {
            #pragma unroll
            for (int i = 0; i < 4; i++)
                #pragma unroll
                for (int j = 0; j < 4; j++)
                    s[i][j] = (tx*4+j <= ty*4+i) ? s[i][j]*sc : -1e30f;
        } else {
            #pragma unroll
            for (int i = 0; i < 4; i++)
                #pragma unroll
                for (int j = 0; j < 4; j++)
                    s[i][j] *= sc;
        }
        #pragma unroll
        for (int i = 0; i < 4; i++) {
            float mx = fmaxf(fmaxf(s[i][0],s[i][1]), fmaxf(s[i][2],s[i][3]));
            mx = fmaxf(mx, __shfl_xor_sync(0xffffffffu, mx, 1));
            mx = fmaxf(mx, __shfl_xor_sync(0xffffffffu, mx, 2));
            mx = fmaxf(mx, __shfl_xor_sync(0xffffffffu, mx, 4));
            mx = fmaxf(mx, __shfl_xor_sync(0xffffffffu, mx, 8));
            float mn = fmaxf(m_i[i], mx);
            float scale = __expf(m_i[i] - mn);
            float rs = 0.f;
            #pragma unroll
            for (int j = 0; j < 4; j++) { float p = __expf(s[i][j]-mn); s[i][j]=p; rs += p; }
            rs += __shfl_xor_sync(0xffffffffu, rs, 1);
            rs += __shfl_xor_sync(0xffffffffu, rs, 2);
            rs += __shfl_xor_sync(0xffffffffu, rs, 4);
            rs += __shfl_xor_sync(0xffffffffu, rs, 8);
            l_i[i] = l_i[i]*scale + rs;
            m_i[i] = mn;
            #pragma unroll
            for (int j = 0; j < 4; j++) {
                O[i][j] *= scale;
                Ps[(ty*4+i)*65 + tx*4+j] = s[i][j];
            }
        }
        __syncthreads();
        #pragma unroll 4
        for (int jj = 0; jj < 64; jj++) {
            float pv[4], vv[4];
            #pragma unroll
            for (int i = 0; i < 4; i++) pv[i] = Ps[(ty*4+i)*65 + jj];
            #pragma unroll
            for (int j = 0; j < 4; j++) vv[j] = Vs[jj*65 + tx*4+j];
            #pragma unroll
            for (int i = 0; i < 4; i++)
                #pragma unroll
                for (int j = 0; j < 4; j++)
                    O[i][j] += pv[i]*vv[j];
        }
        __syncthreads();
    }
    #pragma unroll
    for (int i = 0; i < 4; i++) {
        float inv = 1.f / l_i[i];
        #pragma unroll
        for (int j = 0; j < 4; j++)
            g_attn[(size_t)(q0+ty*4+i)*(NHQ*HDIM) + h*HDIM + tx*4+j] = O[i][j]*inv;
    }
}

// ---------------- gate GEMM (N=64) ----------------
__global__ __launch_bounds__(256) void gemm64(const float* __restrict__ A,
                                              const float* __restrict__ B,
                                              float* __restrict__ C,
                                              int M, int N, int K) {
    __shared__ float As[16][64];
    __shared__ float Bs[16][64];
    int tid = threadIdx.x;
    int tx = tid & 15, ty = tid >> 4;
    int m0 = blockIdx.y * 64, n0 = blockIdx.x * 64;
    int ar = tid >> 2;
    int ac = (tid & 3) * 4;
    int br = tid >> 4;
    int bc = (tid & 15) * 4;
    float acc[4][4] = {};
    for (int k0 = 0; k0 < K; k0 += 16) {
        float4 av = *(const float4*)&A[(size_t)(m0 + ar)*K + k0 + ac];
        float4 bv = *(const float4*)&B[(size_t)(k0 + br)*N + n0 + bc];
        As[ac+0][ar] = av.x; As[ac+1][ar] = av.y;
        As[ac+2][ar] = av.z; As[ac+3][ar] = av.w;
        *(float4*)&Bs[br][bc] = bv;
        __syncthreads();
        #pragma unroll
        for (int k = 0; k < 16; k++) {
            float4 a = *(const float4*)&As[k][ty*4];
            float4 b = *(const float4*)&Bs[k][tx*4];
            float aa[4] = {a.x,a.y,a.z,a.w};
            float bb[4] = {b.x,b.y,b.z,b.w};
            #pragma unroll
            for (int i = 0; i < 4; i++)
                #pragma unroll
                for (int j = 0; j < 4; j++)
                    acc[i][j] += aa[i]*bb[j];
        }
        __syncthreads();
    }
    #pragma unroll
    for (int i = 0; i < 4; i++) {
        float4 ov = make_float4(acc[i][0],acc[i][1],acc[i][2],acc[i][3]);
        *(float4*)&C[(size_t)(m0 + ty*4 + i)*N + n0 + tx*4] = ov;
    }
}

// ---------------- routing ----------------
__global__ void zero_cnt_k() { if (threadIdx.x < NE) g_cnt[threadIdx.x] = 0; }

__global__ void route_k() {
    int t = blockIdx.x;
    int lane = threadIdx.x;
    float v0 = g_logits[t*NE + lane];
    float v1 = g_logits[t*NE + 32 + lane];
    float selv[TOPK]; int seli[TOPK];
    #pragma unroll
    for (int it = 0; it < TOPK; it++) {
        float best = (v0 >= v1) ? v0 : v1;
        int   bi   = (v0 >= v1) ? lane : lane + 32;
        #pragma unroll
        for (int off = 16; off; off >>= 1) {
            float ov = __shfl_xor_sync(0xffffffffu, best, off);
            int   oi = __shfl_xor_sync(0xffffffffu, bi, off);
            if (ov > best || (ov == best && oi < bi)) { best = ov; bi = oi; }
        }
        selv[it] = best; seli[it] = bi;
        if (bi == lane)      v0 = -1e30f;
        if (bi == lane + 32) v1 = -1e30f;
    }
    if (lane < TOPK) {
        float sum = 0.f;
        #pragma unroll
        for (int i = 0; i < TOPK; i++) sum += __expf(selv[i] - selv[0]);
        float w = __expf(selv[lane] - selv[0]) / sum;
        int e = seli[lane];
        int pos = atomicAdd(&g_cnt[e], 1);
        g_list[e*SS + pos] = t*TOPK + lane;
        g_pairw[t*TOPK + lane] = w;
    }
}

// ---------------- final ----------------
__global__ __launch_bounds__(256) void final_k(float* __restrict__ out) {
    int t = blockIdx.x;
    int c = threadIdx.x * 4;
    float4 a = *(const float4*)&g_h[(size_t)t*DM + c];
    float4 b = *(const float4*)&g_sh[(size_t)t*DM + c];
    a.x += b.x; a.y += b.y; a.z += b.z; a.w += b.w;
    #pragma unroll
    for (int kk = 0; kk < TOPK; kk++) {
        float4 gv = *(const float4*)&g_g2[(size_t)(t*TOPK+kk)*DM + c];
        a.x += gv.x; a.y += gv.y; a.z += gv.z; a.w += gv.w;
    }
    *(float4*)&out[(size_t)t*DM + c] = a;
}

// ---------------- host ----------------
extern "C" void kernel_launch(void* const* d_in, const int* in_sizes, int n_in,
                              void* d_out, int out_size) {
    const float* x   = (const float*)d_in[0];
    const float* fc  = (const float*)d_in[1];
    const float* fs  = (const float*)d_in[2];
    const float* anw = (const float*)d_in[3];
    const float* fnw = (const float*)d_in[4];
    const float* wq  = (const float*)d_in[5];
    const float* wk  = (const float*)d_in[6];
    const float* wv  = (const float*)d_in[7];
    const float* wo  = (const float*)d_in[8];
    const float* qnw = (const float*)d_in[9];
    const float* knw = (const float*)d_in[10];
    const float* gw  = (const float*)d_in[11];
    const float* w1e = (const float*)d_in[12];
    const float* w3e = (const float*)d_in[13];
    const float* w2e = (const float*)d_in[14];
    const float* sw1 = (const float*)d_in[15];
    const float* sw3 = (const float*)d_in[16];
    const float* sw2 = (const float*)d_in[17];
    float* out = (float*)d_out;

    float *hx,*attn,*h,*z,*logits;
    cudaGetSymbolAddress((void**)&hx, g_hx);
    cudaGetSymbolAddress((void**)&attn, g_attn);
    cudaGetSymbolAddress((void**)&h,  g_h);
    cudaGetSymbolAddress((void**)&z,  g_z);
    cudaGetSymbolAddress((void**)&logits, g_logits);

    cudaFuncSetAttribute(flash_attn, cudaFuncAttributeMaxDynamicSharedMemorySize, FLASH_SMEM);

    // attention branch
    rmsnorm_k<<<SS, 256>>>(x, anw, hx);
    qkv_gemm<<<dim3(12, 16), 256>>>(hx, wq, wk, wv);
    qknorm_rope<<<(SS*(NHQ+NKVH)*32)/256, 256>>>(qnw, knw, fc, fs);
    flash_attn<<<dim3(16,16), 256, FLASH_SMEM>>>();
    sgemm_res<<<dim3(8, 16), 256>>>(attn, wo, h, x, 1024, 1024);   // h = attn@wo + x

    // ffn branch
    rmsnorm_k<<<SS, 256>>>(h, fnw, z);
    gemm64<<<dim3(1, 16), 256>>>(z, gw, logits, SS, NE, DM);
    zero_cnt_k<<<1, 64>>>();
    route_k<<<SS, 32>>>();
    ffn_a<<<NE*8 + 128, 256>>>(w1e, w3e, sw1, sw3);   // MoE1 + shared dual, fused
    ffn_b<<<NE*8 + 128, 256>>>(w2e, sw2);             // MoE2 + shared down, fused

    final_k<<<SS, 256>>>(out);
}

// round 8
// speedup vs baseline: 2.4342x; 1.5524x over previous
#include <cuda_runtime.h>
#include <cuda_bf16.h>
#include <math.h>

#define SS 1024
#define DM 1024
#define NHQ 16
#define NKVH 4
#define HDIM 64
#define NE 64
#define TOPK 6
#define HE 512
#define NPAIR (SS*TOPK)

typedef unsigned long long u64;
typedef unsigned int u32;

// ---------------- packed f32x2 helpers ----------------
__device__ __forceinline__ u64 pk2(float x) {
    u64 r; asm("mov.b64 %0,{%1,%1};" : "=l"(r) : "f"(x)); return r;
}
__device__ __forceinline__ void fm2(u64 &d, u64 a, u64 b) {
    asm("fma.rn.f32x2 %0,%1,%2,%0;" : "+l"(d) : "l"(a), "l"(b));
}
__device__ __forceinline__ u64 ad2(u64 a, u64 b) {
    u64 d; asm("add.rn.f32x2 %0,%1,%2;" : "=l"(d) : "l"(a), "l"(b)); return d;
}

// ---------------- tensor-core helpers (bf16 mma + split) ----------------
__device__ __forceinline__ void mma_bf16(float* d, const u32* a, u32 b0, u32 b1) {
    asm volatile("mma.sync.aligned.m16n8k16.row.col.f32.bf16.bf16.f32 "
        "{%0,%1,%2,%3},{%4,%5,%6,%7},{%8,%9},{%0,%1,%2,%3};"
        : "+f"(d[0]),"+f"(d[1]),"+f"(d[2]),"+f"(d[3])
        : "r"(a[0]),"r"(a[1]),"r"(a[2]),"r"(a[3]), "r"(b0),"r"(b1));
}
__device__ __forceinline__ void ldsm4(u32* r, const __nv_bfloat16* p) {
    u32 a = (u32)__cvta_generic_to_shared(p);
    asm volatile("ldmatrix.sync.aligned.m8n8.x4.shared.b16 {%0,%1,%2,%3},[%4];"
        : "=r"(r[0]),"=r"(r[1]),"=r"(r[2]),"=r"(r[3]) : "r"(a));
}
__device__ __forceinline__ void ldsm2t(u32 &r0, u32 &r1, const __nv_bfloat16* p) {
    u32 a = (u32)__cvta_generic_to_shared(p);
    asm volatile("ldmatrix.sync.aligned.m8n8.x2.trans.shared.b16 {%0,%1},[%2];"
        : "=r"(r0),"=r"(r1) : "r"(a));
}
__device__ __forceinline__ u32 pkbf2(float x, float y) {
    __nv_bfloat162 h = __floats2bfloat162_rn(x, y);
    return *reinterpret_cast<u32*>(&h);
}
__device__ __forceinline__ void split8(float4 v0, float4 v1, uint4 &hi, uint4 &lo) {
    float f[8] = {v0.x,v0.y,v0.z,v0.w,v1.x,v1.y,v1.z,v1.w};
    float r[8];
    #pragma unroll
    for (int i = 0; i < 8; i++) r[i] = f[i] - __bfloat162float(__float2bfloat16(f[i]));
    hi = make_uint4(pkbf2(f[0],f[1]),pkbf2(f[2],f[3]),pkbf2(f[4],f[5]),pkbf2(f[6],f[7]));
    lo = make_uint4(pkbf2(r[0],r[1]),pkbf2(r[2],r[3]),pkbf2(r[4],r[5]),pkbf2(r[6],r[7]));
}

// ---------------- scratch ----------------
__device__ float g_hx[SS*DM];
__device__ float g_q[SS*NHQ*HDIM];
__device__ float g_k[SS*NKVH*HDIM];
__device__ float g_v[SS*NKVH*HDIM];
__device__ float g_attn[SS*NHQ*HDIM];
__device__ float g_h[SS*DM];
__device__ float g_z[SS*DM];
__device__ float g_logits[SS*NE];
__device__ float g_pairw[NPAIR];
__device__ int   g_cnt[NE];
__device__ int   g_list[NE*SS];
__device__ float g_gbuf[(size_t)NPAIR*HE];
__device__ float g_g2[(size_t)NPAIR*DM];
__device__ float g_a1[SS*HE];
__device__ float g_sh[SS*DM];

// ---------------- rmsnorm ----------------
__global__ __launch_bounds__(256) void rmsnorm_k(const float* __restrict__ x,
                                                 const float* __restrict__ w,
                                                 float* __restrict__ out) {
    int t = blockIdx.x;
    int tid = threadIdx.x;
    float4 xv = *(const float4*)&x[(size_t)t*DM + tid*4];
    float ss = xv.x*xv.x + xv.y*xv.y + xv.z*xv.z + xv.w*xv.w;
    #pragma unroll
    for (int off = 16; off; off >>= 1) ss += __shfl_xor_sync(0xffffffffu, ss, off);
    __shared__ float red[8];
    if ((tid & 31) == 0) red[tid >> 5] = ss;
    __syncthreads();
    float tot = 0.f;
    #pragma unroll
    for (int i = 0; i < 8; i++) tot += red[i];
    float r = rsqrtf(tot * (1.0f/DM) + 1e-5f);
    float4 wv = *(const float4*)&w[tid*4];
    float4 ov;
    ov.x = wv.x * (xv.x * r); ov.y = wv.y * (xv.y * r);
    ov.z = wv.z * (xv.z * r); ov.w = wv.w * (xv.w * r);
    *(float4*)&out[(size_t)t*DM + tid*4] = ov;
}

// ============ FFMA2 tile (attention branch, unchanged from R7 winner) ============
#define GEMM_K_STEP(Ap, Bp)                                                        \
    {                                                                              \
        float4 a = *(const float4*)&(Ap)[k*68 + ty*4];                             \
        u64 pa0 = pk2(a.x), pa1 = pk2(a.y), pa2 = pk2(a.z), pa3 = pk2(a.w);        \
        ulonglong2 q0 = *(const ulonglong2*)&(Bp)[k*128 + tx*8];                   \
        ulonglong2 q1 = *(const ulonglong2*)&(Bp)[k*128 + tx*8 + 4];               \
        fm2(acc[0][0],pa0,q0.x); fm2(acc[0][1],pa0,q0.y);                          \
        fm2(acc[0][2],pa0,q1.x); fm2(acc[0][3],pa0,q1.y);                          \
        fm2(acc[1][0],pa1,q0.x); fm2(acc[1][1],pa1,q0.y);                          \
        fm2(acc[1][2],pa1,q1.x); fm2(acc[1][3],pa1,q1.y);                          \
        fm2(acc[2][0],pa2,q0.x); fm2(acc[2][1],pa2,q0.y);                          \
        fm2(acc[2][2],pa2,q1.x); fm2(acc[2][3],pa2,q1.y);                          \
        fm2(acc[3][0],pa3,q0.x); fm2(acc[3][1],pa3,q0.y);                          \
        fm2(acc[3][2],pa3,q1.x); fm2(acc[3][3],pa3,q1.y);                          \
    }

#define STORE_A(Ap, av)                                                            \
    { (Ap)[(akc+0)*68 + amr] = (av).x; (Ap)[(akc+1)*68 + amr] = (av).y;            \
      (Ap)[(akc+2)*68 + amr] = (av).z; (Ap)[(akc+3)*68 + amr] = (av).w; }

__global__ __launch_bounds__(256) void qkv_gemm(const float* __restrict__ A,
                                                const float* __restrict__ wq,
                                                const float* __restrict__ wk,
                                                const float* __restrict__ wv) {
    __shared__ float As[2][16*68];
    __shared__ float Bs[2][16*128];
    int bn = blockIdx.x, m0 = blockIdx.y * 64;
    const float* B; float* C; int ldb; int col;
    if (bn < 8)       { B = wq; C = g_q; ldb = 1024; col = bn * 128; }
    else if (bn < 10) { B = wk; C = g_k; ldb = 256;  col = (bn - 8) * 128; }
    else              { B = wv; C = g_v; ldb = 256;  col = (bn - 10) * 128; }
    int tid = threadIdx.x, ty = tid >> 4, tx = tid & 15;
    int amr = tid >> 2, akc = (tid & 3) * 4;
    int bkr = tid >> 4, bnc = (tid & 15) * 8;
    const float* Arow = &A[(size_t)(m0 + amr) * DM];
    const float* Bp0 = &B[(size_t)bkr * ldb + col + bnc];
    u64 acc[4][4] = {};
    {
        float4 av = *(const float4*)&Arow[akc];
        float4 b0 = *(const float4*)Bp0;
        float4 b1 = *(const float4*)(Bp0 + 4);
        STORE_A(As[0], av);
        *(float4*)&Bs[0][bkr*128 + bnc]     = b0;
        *(float4*)&Bs[0][bkr*128 + bnc + 4] = b1;
    }
    __syncthreads();
    int buf = 0;
    for (int k0 = 16; k0 <= DM; k0 += 16) {
        float4 nav, nb0, nb1;
        bool more = (k0 < DM);
        if (more) {
            nav = *(const float4*)&Arow[k0 + akc];
            const float* bp = Bp0 + (size_t)k0 * ldb;
            nb0 = *(const float4*)bp;
            nb1 = *(const float4*)(bp + 4);
        }
        #pragma unroll
        for (int k = 0; k < 16; k++) GEMM_K_STEP(As[buf], Bs[buf])
        if (more) {
            STORE_A(As[buf^1], nav);
            *(float4*)&Bs[buf^1][bkr*128 + bnc]     = nb0;
            *(float4*)&Bs[buf^1][bkr*128 + bnc + 4] = nb1;
        }
        __syncthreads();
        buf ^= 1;
    }
    #pragma unroll
    for (int i = 0; i < 4; i++) {
        float* crow = &C[(size_t)(m0 + ty*4 + i) * ldb + col + tx*8];
        #pragma unroll
        for (int j = 0; j < 4; j++) *(float2*)&crow[2*j] = *(float2*)&acc[i][j];
    }
}

__global__ __launch_bounds__(256) void sgemm_res(const float* __restrict__ A,
                                                 const float* __restrict__ B,
                                                 float* __restrict__ C,
                                                 const float* __restrict__ res,
                                                 int N, int K) {
    __shared__ float As[2][16*68];
    __shared__ float Bs[2][16*128];
    int n0 = blockIdx.x * 128, m0 = blockIdx.y * 64;
    int tid = threadIdx.x, ty = tid >> 4, tx = tid & 15;
    int amr = tid >> 2, akc = (tid & 3) * 4;
    int bkr = tid >> 4, bnc = (tid & 15) * 8;
    const float* Arow = &A[(size_t)(m0 + amr) * K];
    const float* Bp0 = &B[(size_t)bkr * N + n0 + bnc];
    u64 acc[4][4] = {};
    {
        float4 av = *(const float4*)&Arow[akc];
        float4 b0 = *(const float4*)Bp0;
        float4 b1 = *(const float4*)(Bp0 + 4);
        STORE_A(As[0], av);
        *(float4*)&Bs[0][bkr*128 + bnc]     = b0;
        *(float4*)&Bs[0][bkr*128 + bnc + 4] = b1;
    }
    __syncthreads();
    int buf = 0;
    for (int k0 = 16; k0 <= K; k0 += 16) {
        float4 nav, nb0, nb1;
        bool more = (k0 < K);
        if (more) {
            nav = *(const float4*)&Arow[k0 + akc];
            const float* bp = Bp0 + (size_t)k0 * N;
            nb0 = *(const float4*)bp;
            nb1 = *(const float4*)(bp + 4);
        }
        #pragma unroll
        for (int k = 0; k < 16; k++) GEMM_K_STEP(As[buf], Bs[buf])
        if (more) {
            STORE_A(As[buf^1], nav);
            *(float4*)&Bs[buf^1][bkr*128 + bnc]     = nb0;
            *(float4*)&Bs[buf^1][bkr*128 + bnc + 4] = nb1;
        }
        __syncthreads();
        buf ^= 1;
    }
    #pragma unroll
    for (int i = 0; i < 4; i++) {
        size_t ridx = (size_t)(m0 + ty*4 + i) * N + n0 + tx*8;
        if (res) {
            #pragma unroll
            for (int j = 0; j < 4; j++) {
                u64 rv = *(const u64*)&res[ridx + 2*j];
                u64 s = ad2(acc[i][j], rv);
                *(float2*)&C[ridx + 2*j] = *(float2*)&s;
            }
        } else {
            #pragma unroll
            for (int j = 0; j < 4; j++) *(float2*)&C[ridx + 2*j] = *(float2*)&acc[i][j];
        }
    }
}

// ============ FFN stage A (tensor cores): MoE GEMM1 + shared dual GEMM ============
// BM=64, BN=64 (dual W1/W3), BK=32. 8 warps: rb=(w&3)*16 rows, ch=w>>2 col-half.
// smem bf16 layout per buffer: Ahi 64x40 @0, Alo @2560, B1hi 32x72 @5120,
// B1lo @7424, B3hi @9728, B3lo @12032; buffer stride 14336 elems.
#define FA_BYTES (2*14336*2 + 512)
__global__ __launch_bounds__(256) void ffn_a(const float* __restrict__ w1e,
                                             const float* __restrict__ w3e,
                                             const float* __restrict__ sw1,
                                             const float* __restrict__ sw3) {
    extern __shared__ __align__(16) char dyn[];
    __nv_bfloat16* sm = (__nv_bfloat16*)dyn;
    int* s_arow = (int*)(dyn + 2*14336*2);
    int* s_orow = s_arow + 64;

    int tid = threadIdx.x, w = tid >> 5, lane = tid & 31;
    int bid = blockIdx.x;

    int ar = tid >> 2, ac = (tid & 3) * 8;                 // A loader
    int bmat = tid >> 7, br = (tid & 127) >> 2, bc = (tid & 3) * 16;  // B loader
    int rb = (w & 3) * 16, ch = w >> 2;                    // compute map

    bool gather = (bid < NE*8);
    const float* B1g; const float* B3g;
    float* outb; const float* pw; int n0; int mTot; int mshb = 0;
    const int* lst = nullptr; int nrows = 0;

    if (gather) {
        int e = bid >> 3; n0 = (bid & 7) * 64;
        nrows = g_cnt[e];
        if (nrows == 0) return;
        lst = &g_list[e*SS];
        B1g = w1e + (size_t)e*DM*HE + n0;
        B3g = w3e + (size_t)e*DM*HE + n0;
        outb = g_gbuf; pw = g_pairw; mTot = nrows;
    } else {
        int b = bid - NE*8;
        n0 = (b & 7) * 64; mshb = (b >> 3) * 64;
        B1g = sw1 + n0; B3g = sw3 + n0;
        outb = g_a1; pw = nullptr; mTot = 64;
    }
    const float* Bgm = bmat ? B3g : B1g;
    int bhio = 5120 + bmat*4608, blio = bhio + 2304;

    int a_row_f = rb + (lane & 7) + ((lane >> 3) & 1) * 8;
    int a_col_s = ((lane >> 4) & 1) * 8;
    int b_row_s = lane & 15;
    int cB = ch * 32;

    for (int m0 = 0; m0 < mTot; m0 += 64) {
        __syncthreads();
        if (tid < 64) {
            int arow, orow;
            if (gather) {
                int p = (m0 + tid < nrows) ? lst[m0 + tid] : -1;
                arow = (p < 0) ? 0 : p / TOPK; orow = p;
            } else { arow = mshb + tid; orow = mshb + tid; }
            s_arow[tid] = arow; s_orow[tid] = orow;
        }
        __syncthreads();
        const float* arp = g_z + (size_t)s_arow[ar]*DM + ac;
        const float* brp = Bgm + (size_t)br*HE + bc;

        float acc1[4][4] = {}; float acc3[4][4] = {};

        {   // prologue: k-tile 0
            float4 va0 = *(const float4*)arp;
            float4 va1 = *(const float4*)(arp + 4);
            float4 vb0 = *(const float4*)brp;
            float4 vb1 = *(const float4*)(brp + 4);
            float4 vb2 = *(const float4*)(brp + 8);
            float4 vb3 = *(const float4*)(brp + 12);
            uint4 h, l;
            split8(va0, va1, h, l);
            *(uint4*)(sm + ar*40 + ac) = h;
            *(uint4*)(sm + 2560 + ar*40 + ac) = l;
            split8(vb0, vb1, h, l);
            *(uint4*)(sm + bhio + br*72 + bc) = h;
            *(uint4*)(sm + blio + br*72 + bc) = l;
            split8(vb2, vb3, h, l);
            *(uint4*)(sm + bhio + br*72 + bc + 8) = h;
            *(uint4*)(sm + blio + br*72 + bc + 8) = l;
        }
        __syncthreads();
        int buf = 0;
        for (int kt = 1; kt <= 32; kt++) {
            bool more = (kt < 32);
            float4 na0, na1, nb0, nb1, nb2, nb3;
            if (more) {
                int k0 = kt * 32;
                na0 = *(const float4*)(arp + k0);
                na1 = *(const float4*)(arp + k0 + 4);
                const float* bp = brp + (size_t)k0 * HE;
                nb0 = *(const float4*)bp;  nb1 = *(const float4*)(bp + 4);
                nb2 = *(const float4*)(bp + 8); nb3 = *(const float4*)(bp + 12);
            }
            {
                const __nv_bfloat16* base = sm + buf*14336;
                #pragma unroll
                for (int kf = 0; kf < 2; kf++) {
                    u32 ah[4], al[4];
                    ldsm4(ah, base + a_row_f*40 + kf*16 + a_col_s);
                    ldsm4(al, base + 2560 + a_row_f*40 + kf*16 + a_col_s);
                    int rB = kf*16 + b_row_s;
                    #pragma unroll
                    for (int nf = 0; nf < 4; nf++) {
                        u32 bh0, bh1, bl0, bl1;
                        const __nv_bfloat16* pB1 = base + 5120 + rB*72 + cB + nf*8;
                        ldsm2t(bh0, bh1, pB1);
                        ldsm2t(bl0, bl1, pB1 + 2304);
                        mma_bf16(acc1[nf], ah, bh0, bh1);
                        mma_bf16(acc1[nf], ah, bl0, bl1);
                        mma_bf16(acc1[nf], al, bh0, bh1);
                        const __nv_bfloat16* pB3 = pB1 + 4608;
                        ldsm2t(bh0, bh1, pB3);
                        ldsm2t(bl0, bl1, pB3 + 2304);
                        mma_bf16(acc3[nf], ah, bh0, bh1);
                        mma_bf16(acc3[nf], ah, bl0, bl1);
                        mma_bf16(acc3[nf], al, bh0, bh1);
                    }
                }
            }
            if (more) {
                __nv_bfloat16* d = sm + (buf^1)*14336;
                uint4 h, l;
                split8(na0, na1, h, l);
                *(uint4*)(d + ar*40 + ac) = h;
                *(uint4*)(d + 2560 + ar*40 + ac) = l;
                split8(nb0, nb1, h, l);
                *(uint4*)(d + bhio + br*72 + bc) = h;
                *(uint4*)(d + blio + br*72 + bc) = l;
                split8(nb2, nb3, h, l);
                *(uint4*)(d + bhio + br*72 + bc + 8) = h;
                *(uint4*)(d + blio + br*72 + bc + 8) = l;
            }
            __syncthreads();
            buf ^= 1;
        }
        // epilogue: silu(h1)*h3*(weight)
        int r0 = rb + (lane >> 2);
        int o0 = s_orow[r0], o1 = s_orow[r0 + 8];
        float wt0 = pw ? (o0 >= 0 ? pw[o0] : 0.f) : 1.f;
        float wt1 = pw ? (o1 >= 0 ? pw[o1] : 0.f) : 1.f;
        #pragma unroll
        for (int nf = 0; nf < 4; nf++) {
            int c = n0 + cB + nf*8 + (lane & 3)*2;
            if (o0 >= 0) {
                float x0 = acc1[nf][0], x1 = acc1[nf][1];
                float2 o;
                o.x = (x0/(1.f+__expf(-x0))) * acc3[nf][0] * wt0;
                o.y = (x1/(1.f+__expf(-x1))) * acc3[nf][1] * wt0;
                *(float2*)&outb[(size_t)o0*HE + c] = o;
            }
            if (o1 >= 0) {
                float x2 = acc1[nf][2], x3 = acc1[nf][3];
                float2 o;
                o.x = (x2/(1.f+__expf(-x2))) * acc3[nf][2] * wt1;
                o.y = (x3/(1.f+__expf(-x3))) * acc3[nf][3] * wt1;
                *(float2*)&outb[(size_t)o1*HE + c] = o;
            }
        }
    }
}

// ============ FFN stage B (tensor cores): MoE GEMM2 + shared down proj ============
// BM=64, BN=128, BK=32, K=HE. smem per buffer: Ahi 64x40 @0, Alo @2560,
// Bhi 32x136 @5120, Blo @9472; buffer stride 13824 elems.
#define FB_BYTES (2*13824*2 + 512)
__global__ __launch_bounds__(256) void ffn_b(const float* __restrict__ w2e,
                                             const float* __restrict__ sw2) {
    extern __shared__ __align__(16) char dyn[];
    __nv_bfloat16* sm = (__nv_bfloat16*)dyn;
    int* s_arow = (int*)(dyn + 2*13824*2);
    int* s_orow = s_arow + 64;

    int tid = threadIdx.x, w = tid >> 5, lane = tid & 31;
    int bid = blockIdx.x;

    int ar = tid >> 2, ac = (tid & 3) * 8;             // A loader
    int br2 = tid >> 3, bc2 = (tid & 7) * 16;          // B loader
    int rb = (w & 3) * 16, ch = (w >> 2) * 64;         // compute map

    bool gather = (bid < NE*8);
    const float* Ag; const float* Bg;
    float* outb; int n0; int mTot; int mshb = 0;
    const int* lst = nullptr; int nrows = 0;

    if (gather) {
        int e = bid >> 3; n0 = (bid & 7) * 128;
        nrows = g_cnt[e];
        if (nrows == 0) return;
        lst = &g_list[e*SS];
        Ag = g_gbuf;
        Bg = w2e + (size_t)e*HE*DM + n0;
        outb = g_g2; mTot = nrows;
    } else {
        int b = bid - NE*8;
        n0 = (b & 7) * 128; mshb = (b >> 3) * 64;
        Ag = g_a1; Bg = sw2 + n0;
        outb = g_sh; mTot = 64;
    }

    int a_row_f = rb + (lane & 7) + ((lane >> 3) & 1) * 8;
    int a_col_s = ((lane >> 4) & 1) * 8;
    int b_row_s = lane & 15;

    for (int m0 = 0; m0 < mTot; m0 += 64) {
        __syncthreads();
        if (tid < 64) {
            int arow, orow;
            if (gather) {
                int p = (m0 + tid < nrows) ? lst[m0 + tid] : -1;
                arow = (p < 0) ? 0 : p; orow = p;
            } else { arow = mshb + tid; orow = mshb + tid; }
            s_arow[tid] = arow; s_orow[tid] = orow;
        }
        __syncthreads();
        const float* arp = Ag + (size_t)s_arow[ar]*HE + ac;
        const float* brp = Bg + (size_t)br2*DM + bc2;

        float acc[8][4] = {};

        {   // prologue
            float4 va0 = *(const float4*)arp;
            float4 va1 = *(const float4*)(arp + 4);
            float4 vb0 = *(const float4*)brp;
            float4 vb1 = *(const float4*)(brp + 4);
            float4 vb2 = *(const float4*)(brp + 8);
            float4 vb3 = *(const float4*)(brp + 12);
            uint4 h, l;
            split8(va0, va1, h, l);
            *(uint4*)(sm + ar*40 + ac) = h;
            *(uint4*)(sm + 2560 + ar*40 + ac) = l;
            split8(vb0, vb1, h, l);
            *(uint4*)(sm + 5120 + br2*136 + bc2) = h;
            *(uint4*)(sm + 9472 + br2*136 + bc2) = l;
            split8(vb2, vb3, h, l);
            *(uint4*)(sm + 5120 + br2*136 + bc2 + 8) = h;
            *(uint4*)(sm + 9472 + br2*136 + bc2 + 8) = l;
        }
        __syncthreads();
        int buf = 0;
        for (int kt = 1; kt <= 16; kt++) {
            bool more = (kt < 16);
            float4 na0, na1, nb0, nb1, nb2, nb3;
            if (more) {
                int k0 = kt * 32;
                na0 = *(const float4*)(arp + k0);
                na1 = *(const float4*)(arp + k0 + 4);
                const float* bp = brp + (size_t)k0 * DM;
                nb0 = *(const float4*)bp;  nb1 = *(const float4*)(bp + 4);
                nb2 = *(const float4*)(bp + 8); nb3 = *(const float4*)(bp + 12);
            }
            {
                const __nv_bfloat16* base = sm + buf*13824;
                #pragma unroll
                for (int kf = 0; kf < 2; kf++) {
                    u32 ah[4], al[4];
                    ldsm4(ah, base + a_row_f*40 + kf*16 + a_col_s);
                    ldsm4(al, base + 2560 + a_row_f*40 + kf*16 + a_col_s);
                    int rB = kf*16 + b_row_s;
                    #pragma unroll
                    for (int nf = 0; nf < 8; nf++) {
                        u32 bh0, bh1, bl0, bl1;
                        const __nv_bfloat16* pB = base + 5120 + rB*136 + ch + nf*8;
                        ldsm2t(bh0, bh1, pB);
                        ldsm2t(bl0, bl1, pB + 4352);
                        mma_bf16(acc[nf], ah, bh0, bh1);
                        mma_bf16(acc[nf], ah, bl0, bl1);
                        mma_bf16(acc[nf], al, bh0, bh1);
                    }
                }
            }
            if (more) {
                __nv_bfloat16* d = sm + (buf^1)*13824;
                uint4 h, l;
                split8(na0, na1, h, l);
                *(uint4*)(d + ar*40 + ac) = h;
                *(uint4*)(d + 2560 + ar*40 + ac) = l;
                split8(nb0, nb1, h, l);
                *(uint4*)(d + 5120 + br2*136 + bc2) = h;
                *(uint4*)(d + 9472 + br2*136 + bc2) = l;
                split8(nb2, nb3, h, l);
                *(uint4*)(d + 5120 + br2*136 + bc2 + 8) = h;
                *(uint4*)(d + 9472 + br2*136 + bc2 + 8) = l;
            }
            __syncthreads();
            buf ^= 1;
        }
        int r0 = rb + (lane >> 2);
        int o0 = s_orow[r0], o1 = s_orow[r0 + 8];
        #pragma unroll
        for (int nf = 0; nf < 8; nf++) {
            int c = n0 + ch + nf*8 + (lane & 3)*2;
            if (o0 >= 0) {
                float2 o = make_float2(acc[nf][0], acc[nf][1]);
                *(float2*)&outb[(size_t)o0*DM + c] = o;
            }
            if (o1 >= 0) {
                float2 o = make_float2(acc[nf][2], acc[nf][3]);
                *(float2*)&outb[(size_t)o1*DM + c] = o;
            }
        }
    }
}

// ---------------- q/k rmsnorm + rope ----------------
__global__ __launch_bounds__(256) void qknorm_rope(const float* __restrict__ qw,
                                                   const float* __restrict__ kw,
                                                   const float* __restrict__ cosb,
                                                   const float* __restrict__ sinb) {
    int gw = (blockIdx.x * blockDim.x + threadIdx.x) >> 5;
    int lane = threadIdx.x & 31;
    if (gw >= SS * (NHQ + NKVH)) return;
    int t = gw / (NHQ + NKVH);
    int hh = gw % (NHQ + NKVH);
    float* base;
    const float* w;
    if (hh < NHQ) { base = &g_q[(size_t)t*(NHQ*HDIM) + hh*HDIM]; w = qw; }
    else          { base = &g_k[(size_t)t*(NKVH*HDIM) + (hh-NHQ)*HDIM]; w = kw; }
    int d0 = lane * 2;
    float v0 = base[d0], v1 = base[d0+1];
    float ss = v0*v0 + v1*v1;
    #pragma unroll
    for (int off = 16; off; off >>= 1) ss += __shfl_xor_sync(0xffffffffu, ss, off);
    float r = rsqrtf(ss * (1.0f/HDIM) + 1e-5f);
    float n0 = v0 * r * w[d0];
    float n1 = v1 * r * w[d0+1];
    float c = cosb[t*(HDIM/2) + lane];
    float s = sinb[t*(HDIM/2) + lane];
    base[d0]   = n0*c - n1*s;
    base[d0+1] = n0*s + n1*c;
}

// ---------------- flash attention ----------------
#define FLASH_SMEM (4*64*65*4)
__global__ __launch_bounds__(256) void flash_attn() {
    extern __shared__ float smf[];
    float* Qs = smf;
    float* Ks = smf + 64*65;
    float* Vs = smf + 2*64*65;
    float* Ps = smf + 3*64*65;
    int qt = (int)gridDim.x - 1 - (int)blockIdx.x;
    int h = blockIdx.y;
    int kvh = h >> 2;
    int q0 = qt * 64;
    int tid = threadIdx.x;
    int tx = tid & 15, ty = tid >> 4;
    {
        int r = tid >> 2, c = (tid & 3) * 16;
        const float* src = &g_q[(size_t)(q0 + r)*(NHQ*HDIM) + h*HDIM + c];
        #pragma unroll
        for (int i = 0; i < 16; i += 4) {
            float4 vq = *(const float4*)(src + i);
            Qs[r*65+c+i]   = vq.x; Qs[r*65+c+i+1] = vq.y;
            Qs[r*65+c+i+2] = vq.z; Qs[r*65+c+i+3] = vq.w;
        }
    }
    float O[4][4] = {};
    float m_i[4] = {-1e30f,-1e30f,-1e30f,-1e30f};
    float l_i[4] = {};
    __syncthreads();
    for (int kt = 0; kt <= qt; kt++) {
        int k0 = kt * 64;
        {
            int r = tid >> 2, c = (tid & 3) * 16;
            const float* ksrc = &g_k[(size_t)(k0 + r)*(NKVH*HDIM) + kvh*HDIM + c];
            const float* vsrc = &g_v[(size_t)(k0 + r)*(NKVH*HDIM) + kvh*HDIM + c];
            #pragma unroll
            for (int i = 0; i < 16; i += 4) {
                float4 a = *(const float4*)(ksrc + i);
                float4 b = *(const float4*)(vsrc + i);
                Ks[r*65+c+i]=a.x; Ks[r*65+c+i+1]=a.y; Ks[r*65+c+i+2]=a.z; Ks[r*65+c+i+3]=a.w;
                Vs[r*65+c+i]=b.x; Vs[r*65+c+i+1]=b.y; Vs[r*65+c+i+2]=b.z; Vs[r*65+c+i+3]=b.w;
            }
        }
        __syncthreads();
        float s[4][4] = {};
        #pragma unroll 8
        for (int d = 0; d < 64; d++) {
            float qv[4], kv[4];
            #pragma unroll
            for (int i = 0; i < 4; i++) qv[i] = Qs[(ty*4+i)*65 + d];
            #pragma unroll
            for (int j = 0; j < 4; j++) kv[j] = Ks[(tx*4+j)*65 + d];
            #pragma unroll
            for (int i = 0; i < 4; i++)
                #pragma unroll
                for (int j = 0; j < 4; j++)
                    s[i][j] += qv[i]*kv[j];
        }
        const float sc = 0.125f;
        if (kt == qt) {
            #pragma unroll
            for (int i = 0; i < 4; i++)
                #pragma unroll
                for (int j = 0; j < 4; j++)
                    s[i][j] = (tx*4+j <= ty*4+i) ? s[i][j]*sc : -1e30f;
        } else {
            #pragma unroll
            for (int i = 0; i < 4; i++)
                #pragma unroll
                for (int j = 0; j < 4; j++)
                    s[i][j] *= sc;
        }
        #pragma unroll
        for (int i = 0; i < 4; i++) {
            float mx = fmaxf(fmaxf(s[i][0],s[i][1]), fmaxf(s[i][2],s[i][3]));
            mx = fmaxf(mx, __shfl_xor_sync(0xffffffffu, mx, 1));
            mx = fmaxf(mx, __shfl_xor_sync(0xffffffffu, mx, 2));
            mx = fmaxf(mx, __shfl_xor_sync(0xffffffffu, mx, 4));
            mx = fmaxf(mx, __shfl_xor_sync(0xffffffffu, mx, 8));
            float mn = fmaxf(m_i[i], mx);
            float scale = __expf(m_i[i] - mn);
            float rs = 0.f;
            #pragma unroll
            for (int j = 0; j < 4; j++) { float p = __expf(s[i][j]-mn); s[i][j]=p; rs += p; }
            rs += __shfl_xor_sync(0xffffffffu, rs, 1);
            rs += __shfl_xor_sync(0xffffffffu, rs, 2);
            rs += __shfl_xor_sync(0xffffffffu, rs, 4);
            rs += __shfl_xor_sync(0xffffffffu, rs, 8);
            l_i[i] = l_i[i]*scale + rs;
            m_i[i] = mn;
            #pragma unroll
            for (int j = 0; j < 4; j++) {
                O[i][j] *= scale;
                Ps[(ty*4+i)*65 + tx*4+j] = s[i][j];
            }
        }
        __syncthreads();
        #pragma unroll 4
        for (int jj = 0; jj < 64; jj++) {
            float pv[4], vv[4];
            #pragma unroll
            for (int i = 0; i < 4; i++) pv[i] = Ps[(ty*4+i)*65 + jj];
            #pragma unroll
            for (int j = 0; j < 4; j++) vv[j] = Vs[jj*65 + tx*4+j];
            #pragma unroll
            for (int i = 0; i < 4; i++)
                #pragma unroll
                for (int j = 0; j < 4; j++)
                    O[i][j] += pv[i]*vv[j];
        }
        __syncthreads();
    }
    #pragma unroll
    for (int i = 0; i < 4; i++) {
        float inv = 1.f / l_i[i];
        #pragma unroll
        for (int j = 0; j < 4; j++)
            g_attn[(size_t)(q0+ty*4+i)*(NHQ*HDIM) + h*HDIM + tx*4+j] = O[i][j]*inv;
    }
}

// ---------------- gate GEMM (N=64) ----------------
__global__ __launch_bounds__(256) void gemm64(const float* __restrict__ A,
                                              const float* __restrict__ B,
                                              float* __restrict__ C,
                                              int M, int N, int K) {
    __shared__ float As[16][64];
    __shared__ float Bs[16][64];
    int tid = threadIdx.x;
    int tx = tid & 15, ty = tid >> 4;
    int m0 = blockIdx.y * 64, n0 = blockIdx.x * 64;
    int ar = tid >> 2;
    int ac = (tid & 3) * 4;
    int br = tid >> 4;
    int bc = (tid & 15) * 4;
    float acc[4][4] = {};
    for (int k0 = 0; k0 < K; k0 += 16) {
        float4 av = *(const float4*)&A[(size_t)(m0 + ar)*K + k0 + ac];
        float4 bv = *(const float4*)&B[(size_t)(k0 + br)*N + n0 + bc];
        As[ac+0][ar] = av.x; As[ac+1][ar] = av.y;
        As[ac+2][ar] = av.z; As[ac+3][ar] = av.w;
        *(float4*)&Bs[br][bc] = bv;
        __syncthreads();
        #pragma unroll
        for (int k = 0; k < 16; k++) {
            float4 a = *(const float4*)&As[k][ty*4];
            float4 b = *(const float4*)&Bs[k][tx*4];
            float aa[4] = {a.x,a.y,a.z,a.w};
            float bb[4] = {b.x,b.y,b.z,b.w};
            #pragma unroll
            for (int i = 0; i < 4; i++)
                #pragma unroll
                for (int j = 0; j < 4; j++)
                    acc[i][j] += aa[i]*bb[j];
        }
        __syncthreads();
    }
    #pragma unroll
    for (int i = 0; i < 4; i++) {
        float4 ov = make_float4(acc[i][0],acc[i][1],acc[i][2],acc[i][3]);
        *(float4*)&C[(size_t)(m0 + ty*4 + i)*N + n0 + tx*4] = ov;
    }
}

// ---------------- routing ----------------
__global__ void zero_cnt_k() { if (threadIdx.x < NE) g_cnt[threadIdx.x] = 0; }

__global__ void route_k() {
    int t = blockIdx.x;
    int lane = threadIdx.x;
    float v0 = g_logits[t*NE + lane];
    float v1 = g_logits[t*NE + 32 + lane];
    float selv[TOPK]; int seli[TOPK];
    #pragma unroll
    for (int it = 0; it < TOPK; it++) {
        float best = (v0 >= v1) ? v0 : v1;
        int   bi   = (v0 >= v1) ? lane : lane + 32;
        #pragma unroll
        for (int off = 16; off; off >>= 1) {
            float ov = __shfl_xor_sync(0xffffffffu, best, off);
            int   oi = __shfl_xor_sync(0xffffffffu, bi, off);
            if (ov > best || (ov == best && oi < bi)) { best = ov; bi = oi; }
        }
        selv[it] = best; seli[it] = bi;
        if (bi == lane)      v0 = -1e30f;
        if (bi == lane + 32) v1 = -1e30f;
    }
    if (lane < TOPK) {
        float sum = 0.f;
        #pragma unroll
        for (int i = 0; i < TOPK; i++) sum += __expf(selv[i] - selv[0]);
        float w = __expf(selv[lane] - selv[0]) / sum;
        int e = seli[lane];
        int pos = atomicAdd(&g_cnt[e], 1);
        g_list[e*SS + pos] = t*TOPK + lane;
        g_pairw[t*TOPK + lane] = w;
    }
}

// ---------------- final ----------------
__global__ __launch_bounds__(256) void final_k(float* __restrict__ out) {
    int t = blockIdx.x;
    int c = threadIdx.x * 4;
    float4 a = *(const float4*)&g_h[(size_t)t*DM + c];
    float4 b = *(const float4*)&g_sh[(size_t)t*DM + c];
    a.x += b.x; a.y += b.y; a.z += b.z; a.w += b.w;
    #pragma unroll
    for (int kk = 0; kk < TOPK; kk++) {
        float4 gv = *(const float4*)&g_g2[(size_t)(t*TOPK+kk)*DM + c];
        a.x += gv.x; a.y += gv.y; a.z += gv.z; a.w += gv.w;
    }
    *(float4*)&out[(size_t)t*DM + c] = a;
}

// ---------------- host ----------------
extern "C" void kernel_launch(void* const* d_in, const int* in_sizes, int n_in,
                              void* d_out, int out_size) {
    const float* x   = (const float*)d_in[0];
    const float* fc  = (const float*)d_in[1];
    const float* fs  = (const float*)d_in[2];
    const float* anw = (const float*)d_in[3];
    const float* fnw = (const float*)d_in[4];
    const float* wq  = (const float*)d_in[5];
    const float* wk  = (const float*)d_in[6];
    const float* wv  = (const float*)d_in[7];
    const float* wo  = (const float*)d_in[8];
    const float* qnw = (const float*)d_in[9];
    const float* knw = (const float*)d_in[10];
    const float* gw  = (const float*)d_in[11];
    const float* w1e = (const float*)d_in[12];
    const float* w3e = (const float*)d_in[13];
    const float* w2e = (const float*)d_in[14];
    const float* sw1 = (const float*)d_in[15];
    const float* sw3 = (const float*)d_in[16];
    const float* sw2 = (const float*)d_in[17];
    float* out = (float*)d_out;

    float *hx,*attn,*h,*z,*logits;
    cudaGetSymbolAddress((void**)&hx, g_hx);
    cudaGetSymbolAddress((void**)&attn, g_attn);
    cudaGetSymbolAddress((void**)&h,  g_h);
    cudaGetSymbolAddress((void**)&z,  g_z);
    cudaGetSymbolAddress((void**)&logits, g_logits);

    cudaFuncSetAttribute(flash_attn, cudaFuncAttributeMaxDynamicSharedMemorySize, FLASH_SMEM);
    cudaFuncSetAttribute(ffn_a, cudaFuncAttributeMaxDynamicSharedMemorySize, FA_BYTES);
    cudaFuncSetAttribute(ffn_b, cudaFuncAttributeMaxDynamicSharedMemorySize, FB_BYTES);

    // attention branch
    rmsnorm_k<<<SS, 256>>>(x, anw, hx);
    qkv_gemm<<<dim3(12, 16), 256>>>(hx, wq, wk, wv);
    qknorm_rope<<<(SS*(NHQ+NKVH)*32)/256, 256>>>(qnw, knw, fc, fs);
    flash_attn<<<dim3(16,16), 256, FLASH_SMEM>>>();
    sgemm_res<<<dim3(8, 16), 256>>>(attn, wo, h, x, 1024, 1024);   // h = attn@wo + x

    // ffn branch
    rmsnorm_k<<<SS, 256>>>(h, fnw, z);
    gemm64<<<dim3(1, 16), 256>>>(z, gw, logits, SS, NE, DM);
    zero_cnt_k<<<1, 64>>>();
    route_k<<<SS, 32>>>();
    ffn_a<<<NE*8 + 128, 256, FA_BYTES>>>(w1e, w3e, sw1, sw3);  // MoE1 + shared dual (tensor)
    ffn_b<<<NE*8 + 128, 256, FB_BYTES>>>(w2e, sw2);            // MoE2 + shared down (tensor)

    final_k<<<SS, 256>>>(out);
}

// round 11
// speedup vs baseline: 2.5821x; 1.0608x over previous
#include <cuda_runtime.h>
#include <cuda_bf16.h>
#include <math.h>

#define SS 1024
#define DM 1024
#define NHQ 16
#define NKVH 4
#define HDIM 64
#define NE 64
#define TOPK 6
#define HE 512
#define NPAIR (SS*TOPK)

typedef unsigned long long u64;
typedef unsigned int u32;

// ---------------- packed f32x2 helpers (FFMA2 path) ----------------
__device__ __forceinline__ u64 pk2(float x) {
    u64 r; asm("mov.b64 %0,{%1,%1};" : "=l"(r) : "f"(x)); return r;
}
__device__ __forceinline__ void fm2(u64 &d, u64 a, u64 b) {
    asm("fma.rn.f32x2 %0,%1,%2,%0;" : "+l"(d) : "l"(a), "l"(b));
}

// ---------------- tensor-core helpers (bf16 mma + split) ----------------
__device__ __forceinline__ void mma_bf16(float* d, const u32* a, u32 b0, u32 b1) {
    asm volatile("mma.sync.aligned.m16n8k16.row.col.f32.bf16.bf16.f32 "
        "{%0,%1,%2,%3},{%4,%5,%6,%7},{%8,%9},{%0,%1,%2,%3};"
        : "+f"(d[0]),"+f"(d[1]),"+f"(d[2]),"+f"(d[3])
        : "r"(a[0]),"r"(a[1]),"r"(a[2]),"r"(a[3]), "r"(b0),"r"(b1));
}
__device__ __forceinline__ void ldsm4(u32* r, const __nv_bfloat16* p) {
    u32 a = (u32)__cvta_generic_to_shared(p);
    asm volatile("ldmatrix.sync.aligned.m8n8.x4.shared.b16 {%0,%1,%2,%3},[%4];"
        : "=r"(r[0]),"=r"(r[1]),"=r"(r[2]),"=r"(r[3]) : "r"(a));
}
__device__ __forceinline__ void ldsm2t(u32 &r0, u32 &r1, const __nv_bfloat16* p) {
    u32 a = (u32)__cvta_generic_to_shared(p);
    asm volatile("ldmatrix.sync.aligned.m8n8.x2.trans.shared.b16 {%0,%1},[%2];"
        : "=r"(r0),"=r"(r1) : "r"(a));
}
__device__ __forceinline__ u32 pkbf2(float x, float y) {
    __nv_bfloat162 h = __floats2bfloat162_rn(x, y);
    return *reinterpret_cast<u32*>(&h);
}
__device__ __forceinline__ void split8(float4 v0, float4 v1, uint4 &hi, uint4 &lo) {
    float f[8] = {v0.x,v0.y,v0.z,v0.w,v1.x,v1.y,v1.z,v1.w};
    float r[8];
    #pragma unroll
    for (int i = 0; i < 8; i++) r[i] = f[i] - __bfloat162float(__float2bfloat16(f[i]));
    hi = make_uint4(pkbf2(f[0],f[1]),pkbf2(f[2],f[3]),pkbf2(f[4],f[5]),pkbf2(f[6],f[7]));
    lo = make_uint4(pkbf2(r[0],r[1]),pkbf2(r[2],r[3]),pkbf2(r[4],r[5]),pkbf2(r[6],r[7]));
}

// ---------------- scratch ----------------
__device__ float g_hx[SS*DM];
__device__ float g_q[SS*NHQ*HDIM];
__device__ float g_k[SS*NKVH*HDIM];
__device__ float g_v[SS*NKVH*HDIM];
__device__ float g_attn[SS*NHQ*HDIM];
__device__ float g_h[SS*DM];
__device__ float g_z[SS*DM];
__device__ float g_logits[SS*NE];
__device__ float g_pairw[NPAIR];
__device__ int   g_cnt[NE];
__device__ int   g_list[NE*SS];
__device__ float g_gbuf[(size_t)NPAIR*HE];
__device__ float g_g2[(size_t)NPAIR*DM];
__device__ float g_a1[SS*HE];
__device__ float g_sh[SS*DM];

// ---------------- rmsnorm ----------------
__global__ __launch_bounds__(256) void rmsnorm_k(const float* __restrict__ x,
                                                 const float* __restrict__ w,
                                                 float* __restrict__ out) {
    int t = blockIdx.x;
    int tid = threadIdx.x;
    float4 xv = *(const float4*)&x[(size_t)t*DM + tid*4];
    float ss = xv.x*xv.x + xv.y*xv.y + xv.z*xv.z + xv.w*xv.w;
    #pragma unroll
    for (int off = 16; off; off >>= 1) ss += __shfl_xor_sync(0xffffffffu, ss, off);
    __shared__ float red[8];
    if ((tid & 31) == 0) red[tid >> 5] = ss;
    __syncthreads();
    float tot = 0.f;
    #pragma unroll
    for (int i = 0; i < 8; i++) tot += red[i];
    float r = rsqrtf(tot * (1.0f/DM) + 1e-5f);
    float4 wv = *(const float4*)&w[tid*4];
    float4 ov;
    ov.x = wv.x * (xv.x * r); ov.y = wv.y * (xv.y * r);
    ov.z = wv.z * (xv.z * r); ov.w = wv.w * (xv.w * r);
    *(float4*)&out[(size_t)t*DM + tid*4] = ov;
}

// ============ FFMA2 tile (qkv, proven R7/R8) ============
#define GEMM_K_STEP(Ap, Bp)                                                        \
    {                                                                              \
        float4 a = *(const float4*)&(Ap)[k*68 + ty*4];                             \
        u64 pa0 = pk2(a.x), pa1 = pk2(a.y), pa2 = pk2(a.z), pa3 = pk2(a.w);        \
        ulonglong2 q0 = *(const ulonglong2*)&(Bp)[k*128 + tx*8];                   \
        ulonglong2 q1 = *(const ulonglong2*)&(Bp)[k*128 + tx*8 + 4];               \
        fm2(acc[0][0],pa0,q0.x); fm2(acc[0][1],pa0,q0.y);                          \
        fm2(acc[0][2],pa0,q1.x); fm2(acc[0][3],pa0,q1.y);                          \
        fm2(acc[1][0],pa1,q0.x); fm2(acc[1][1],pa1,q0.y);                          \
        fm2(acc[1][2],pa1,q1.x); fm2(acc[1][3],pa1,q1.y);                          \
        fm2(acc[2][0],pa2,q0.x); fm2(acc[2][1],pa2,q0.y);                          \
        fm2(acc[2][2],pa2,q1.x); fm2(acc[2][3],pa2,q1.y);                          \
        fm2(acc[3][0],pa3,q0.x); fm2(acc[3][1],pa3,q0.y);                          \
        fm2(acc[3][2],pa3,q1.x); fm2(acc[3][3],pa3,q1.y);                          \
    }

#define STORE_A(Ap, av)                                                            \
    { (Ap)[(akc+0)*68 + amr] = (av).x; (Ap)[(akc+1)*68 + amr] = (av).y;            \
      (Ap)[(akc+2)*68 + amr] = (av).z; (Ap)[(akc+3)*68 + amr] = (av).w; }

__global__ __launch_bounds__(256) void qkv_gemm(const float* __restrict__ A,
                                                const float* __restrict__ wq,
                                                const float* __restrict__ wk,
                                                const float* __restrict__ wv) {
    __shared__ float As[2][16*68];
    __shared__ float Bs[2][16*128];
    int bn = blockIdx.x, m0 = blockIdx.y * 64;
    const float* B; float* C; int ldb; int col;
    if (bn < 8)       { B = wq; C = g_q; ldb = 1024; col = bn * 128; }
    else if (bn < 10) { B = wk; C = g_k; ldb = 256;  col = (bn - 8) * 128; }
    else              { B = wv; C = g_v; ldb = 256;  col = (bn - 10) * 128; }
    int tid = threadIdx.x, ty = tid >> 4, tx = tid & 15;
    int amr = tid >> 2, akc = (tid & 3) * 4;
    int bkr = tid >> 4, bnc = (tid & 15) * 8;
    const float* Arow = &A[(size_t)(m0 + amr) * DM];
    const float* Bp0 = &B[(size_t)bkr * ldb + col + bnc];
    u64 acc[4][4] = {};
    {
        float4 av = *(const float4*)&Arow[akc];
        float4 b0 = *(const float4*)Bp0;
        float4 b1 = *(const float4*)(Bp0 + 4);
        STORE_A(As[0], av);
        *(float4*)&Bs[0][bkr*128 + bnc]     = b0;
        *(float4*)&Bs[0][bkr*128 + bnc + 4] = b1;
    }
    __syncthreads();
    int buf = 0;
    for (int k0 = 16; k0 <= DM; k0 += 16) {
        float4 nav, nb0, nb1;
        bool more = (k0 < DM);
        if (more) {
            nav = *(const float4*)&Arow[k0 + akc];
            const float* bp = Bp0 + (size_t)k0 * ldb;
            nb0 = *(const float4*)bp;
            nb1 = *(const float4*)(bp + 4);
        }
        #pragma unroll
        for (int k = 0; k < 16; k++) GEMM_K_STEP(As[buf], Bs[buf])
        if (more) {
            STORE_A(As[buf^1], nav);
            *(float4*)&Bs[buf^1][bkr*128 + bnc]     = nb0;
            *(float4*)&Bs[buf^1][bkr*128 + bnc + 4] = nb1;
        }
        __syncthreads();
        buf ^= 1;
    }
    #pragma unroll
    for (int i = 0; i < 4; i++) {
        float* crow = &C[(size_t)(m0 + ty*4 + i) * ldb + col + tx*8];
        #pragma unroll
        for (int j = 0; j < 4; j++) *(float2*)&crow[2*j] = *(float2*)&acc[i][j];
    }
}

// ============ split-bf16 tensor GEMM core macros ============
#define FB_BYTES (2*13824*2 + 512)

#define TC_PROLOGUE(dst)                                                      \
    {   float4 va0 = *(const float4*)arp;                                     \
        float4 va1 = *(const float4*)(arp + 4);                               \
        float4 vb0 = *(const float4*)brp;                                     \
        float4 vb1 = *(const float4*)(brp + 4);                               \
        float4 vb2 = *(const float4*)(brp + 8);                               \
        float4 vb3 = *(const float4*)(brp + 12);                              \
        uint4 h, l;                                                           \
        split8(va0, va1, h, l);                                               \
        *(uint4*)((dst) + ar*40 + ac) = h;                                    \
        *(uint4*)((dst) + 2560 + ar*40 + ac) = l;                             \
        split8(vb0, vb1, h, l);                                               \
        *(uint4*)((dst) + 5120 + br2*136 + bc2) = h;                          \
        *(uint4*)((dst) + 9472 + br2*136 + bc2) = l;                          \
        split8(vb2, vb3, h, l);                                               \
        *(uint4*)((dst) + 5120 + br2*136 + bc2 + 8) = h;                      \
        *(uint4*)((dst) + 9472 + br2*136 + bc2 + 8) = l;                      \
    }

#define TC_STORE_NEXT(dst)                                                    \
    {   uint4 h, l;                                                           \
        split8(na0, na1, h, l);                                               \
        *(uint4*)((dst) + ar*40 + ac) = h;                                    \
        *(uint4*)((dst) + 2560 + ar*40 + ac) = l;                             \
        split8(nb0, nb1, h, l);                                               \
        *(uint4*)((dst) + 5120 + br2*136 + bc2) = h;                          \
        *(uint4*)((dst) + 9472 + br2*136 + bc2) = l;                          \
        split8(nb2, nb3, h, l);                                               \
        *(uint4*)((dst) + 5120 + br2*136 + bc2 + 8) = h;                      \
        *(uint4*)((dst) + 9472 + br2*136 + bc2 + 8) = l;                      \
    }

#define TC_COMPUTE(base)                                                      \
    {   _Pragma("unroll")                                                     \
        for (int kf = 0; kf < 2; kf++) {                                      \
            u32 ah[4], al[4];                                                 \
            ldsm4(ah, (base) + a_row_f*40 + kf*16 + a_col_s);                 \
            ldsm4(al, (base) + 2560 + a_row_f*40 + kf*16 + a_col_s);          \
            int rB = kf*16 + b_row_s;                                         \
            _Pragma("unroll")                                                 \
            for (int nf = 0; nf < 8; nf++) {                                  \
                u32 bh0, bh1, bl0, bl1;                                       \
                const __nv_bfloat16* pB = (base) + 5120 + rB*136 + ch + nf*8; \
                ldsm2t(bh0, bh1, pB);                                         \
                ldsm2t(bl0, bl1, pB + 4352);                                  \
                mma_bf16(acc[nf], ah, bh0, bh1);                              \
                mma_bf16(acc[nf], ah, bl0, bl1);                              \
                mma_bf16(acc[nf], al, bh0, bh1);                              \
            }                                                                 \
        }                                                                     \
    }

// ---------------- tensor GEMM + residual (wo only this round) ----------------
__global__ __launch_bounds__(256) void tc_gemm_res(const float* __restrict__ A,
                                                   const float* __restrict__ B,
                                                   float* __restrict__ C,
                                                   const float* __restrict__ res,
                                                   int N, int K) {
    extern __shared__ __align__(16) char dyn[];
    __nv_bfloat16* sm = (__nv_bfloat16*)dyn;
    int tid = threadIdx.x, w = tid >> 5, lane = tid & 31;
    int n0 = blockIdx.x * 128, m0 = blockIdx.y * 64;

    int ar = tid >> 2, ac = (tid & 3) * 8;
    int br2 = tid >> 3, bc2 = (tid & 7) * 16;
    int rb = (w & 3) * 16, ch = (w >> 2) * 64;
    int a_row_f = rb + (lane & 7) + ((lane >> 3) & 1) * 8;
    int a_col_s = ((lane >> 4) & 1) * 8;
    int b_row_s = lane & 15;

    const float* arp = A + (size_t)(m0 + ar)*K + ac;
    const float* brp = B + (size_t)br2*N + n0 + bc2;
    float acc[8][4] = {};

    TC_PROLOGUE(sm)
    __syncthreads();
    int buf = 0;
    int nkt = K / 32;
    for (int kt = 1; kt <= nkt; kt++) {
        bool more = (kt < nkt);
        float4 na0, na1, nb0, nb1, nb2, nb3;
        if (more) {
            int k0 = kt * 32;
            na0 = *(const float4*)(arp + k0);
            na1 = *(const float4*)(arp + k0 + 4);
            const float* bp = brp + (size_t)k0 * N;
            nb0 = *(const float4*)bp;  nb1 = *(const float4*)(bp + 4);
            nb2 = *(const float4*)(bp + 8); nb3 = *(const float4*)(bp + 12);
        }
        const __nv_bfloat16* base = sm + buf*13824;
        TC_COMPUTE(base)
        if (more) { __nv_bfloat16* d = sm + (buf^1)*13824; TC_STORE_NEXT(d) }
        __syncthreads();
        buf ^= 1;
    }
    int r0 = m0 + rb + (lane >> 2);
    #pragma unroll
    for (int nf = 0; nf < 8; nf++) {
        int c = n0 + ch + nf*8 + (lane & 3)*2;
        float2 v0 = make_float2(acc[nf][0], acc[nf][1]);
        float2 v1 = make_float2(acc[nf][2], acc[nf][3]);
        if (res) {
            float2 q0 = *(const float2*)&res[(size_t)r0*N + c];
            float2 q1 = *(const float2*)&res[(size_t)(r0+8)*N + c];
            v0.x += q0.x; v0.y += q0.y; v1.x += q1.x; v1.y += q1.y;
        }
        *(float2*)&C[(size_t)r0*N + c]     = v0;
        *(float2*)&C[(size_t)(r0+8)*N + c] = v1;
    }
}

// ============ FFN stage A (tensor cores): MoE GEMM1 + shared dual GEMM (R8-proven) ============
#define FA_BYTES (2*14336*2 + 512)
__global__ __launch_bounds__(256) void ffn_a(const float* __restrict__ w1e,
                                             const float* __restrict__ w3e,
                                             const float* __restrict__ sw1,
                                             const float* __restrict__ sw3) {
    extern __shared__ __align__(16) char dyn[];
    __nv_bfloat16* sm = (__nv_bfloat16*)dyn;
    int* s_arow = (int*)(dyn + 2*14336*2);
    int* s_orow = s_arow + 64;

    int tid = threadIdx.x, w = tid >> 5, lane = tid & 31;
    int bid = blockIdx.x;

    int ar = tid >> 2, ac = (tid & 3) * 8;
    int bmat = tid >> 7, br = (tid & 127) >> 2, bc = (tid & 3) * 16;
    int rb = (w & 3) * 16, ch = w >> 2;

    bool gather = (bid < NE*8);
    const float* B1g; const float* B3g;
    float* outb; const float* pw; int n0; int mTot; int mshb = 0;
    const int* lst = nullptr; int nrows = 0;

    if (gather) {
        int e = bid >> 3; n0 = (bid & 7) * 64;
        nrows = g_cnt[e];
        if (nrows == 0) return;
        lst = &g_list[e*SS];
        B1g = w1e + (size_t)e*DM*HE + n0;
        B3g = w3e + (size_t)e*DM*HE + n0;
        outb = g_gbuf; pw = g_pairw; mTot = nrows;
    } else {
        int b = bid - NE*8;
        n0 = (b & 7) * 64; mshb = (b >> 3) * 64;
        B1g = sw1 + n0; B3g = sw3 + n0;
        outb = g_a1; pw = nullptr; mTot = 64;
    }
    const float* Bgm = bmat ? B3g : B1g;
    int bhio = 5120 + bmat*4608, blio = bhio + 2304;

    int a_row_f = rb + (lane & 7) + ((lane >> 3) & 1) * 8;
    int a_col_s = ((lane >> 4) & 1) * 8;
    int b_row_s = lane & 15;
    int cB = ch * 32;

    for (int m0 = 0; m0 < mTot; m0 += 64) {
        __syncthreads();
        if (tid < 64) {
            int arow, orow;
            if (gather) {
                int p = (m0 + tid < nrows) ? lst[m0 + tid] : -1;
                arow = (p < 0) ? 0 : p / TOPK; orow = p;
            } else { arow = mshb + tid; orow = mshb + tid; }
            s_arow[tid] = arow; s_orow[tid] = orow;
        }
        __syncthreads();
        const float* arp = g_z + (size_t)s_arow[ar]*DM + ac;
        const float* brp = Bgm + (size_t)br*HE + bc;

        float acc1[4][4] = {}; float acc3[4][4] = {};

        {
            float4 va0 = *(const float4*)arp;
            float4 va1 = *(const float4*)(arp + 4);
            float4 vb0 = *(const float4*)brp;
            float4 vb1 = *(const float4*)(brp + 4);
            float4 vb2 = *(const float4*)(brp + 8);
            float4 vb3 = *(const float4*)(brp + 12);
            uint4 h, l;
            split8(va0, va1, h, l);
            *(uint4*)(sm + ar*40 + ac) = h;
            *(uint4*)(sm + 2560 + ar*40 + ac) = l;
            split8(vb0, vb1, h, l);
            *(uint4*)(sm + bhio + br*72 + bc) = h;
            *(uint4*)(sm + blio + br*72 + bc) = l;
            split8(vb2, vb3, h, l);
            *(uint4*)(sm + bhio + br*72 + bc + 8) = h;
            *(uint4*)(sm + blio + br*72 + bc + 8) = l;
        }
        __syncthreads();
        int buf = 0;
        for (int kt = 1; kt <= 32; kt++) {
            bool more = (kt < 32);
            float4 na0, na1, nb0, nb1, nb2, nb3;
            if (more) {
                int k0 = kt * 32;
                na0 = *(const float4*)(arp + k0);
                na1 = *(const float4*)(arp + k0 + 4);
                const float* bp = brp + (size_t)k0 * HE;
                nb0 = *(const float4*)bp;  nb1 = *(const float4*)(bp + 4);
                nb2 = *(const float4*)(bp + 8); nb3 = *(const float4*)(bp + 12);
            }
            {
                const __nv_bfloat16* base = sm + buf*14336;
                #pragma unroll
                for (int kf = 0; kf < 2; kf++) {
                    u32 ah[4], al[4];
                    ldsm4(ah, base + a_row_f*40 + kf*16 + a_col_s);
                    ldsm4(al, base + 2560 + a_row_f*40 + kf*16 + a_col_s);
                    int rB = kf*16 + b_row_s;
                    #pragma unroll
                    for (int nf = 0; nf < 4; nf++) {
                        u32 bh0, bh1, bl0, bl1;
                        const __nv_bfloat16* pB1 = base + 5120 + rB*72 + cB + nf*8;
                        ldsm2t(bh0, bh1, pB1);
                        ldsm2t(bl0, bl1, pB1 + 2304);
                        mma_bf16(acc1[nf], ah, bh0, bh1);
                        mma_bf16(acc1[nf], ah, bl0, bl1);
                        mma_bf16(acc1[nf], al, bh0, bh1);
                        const __nv_bfloat16* pB3 = pB1 + 4608;
                        ldsm2t(bh0, bh1, pB3);
                        ldsm2t(bl0, bl1, pB3 + 2304);
                        mma_bf16(acc3[nf], ah, bh0, bh1);
                        mma_bf16(acc3[nf], ah, bl0, bl1);
                        mma_bf16(acc3[nf], al, bh0, bh1);
                    }
                }
            }
            if (more) {
                __nv_bfloat16* d = sm + (buf^1)*14336;
                uint4 h, l;
                split8(na0, na1, h, l);
                *(uint4*)(d + ar*40 + ac) = h;
                *(uint4*)(d + 2560 + ar*40 + ac) = l;
                split8(nb0, nb1, h, l);
                *(uint4*)(d + bhio + br*72 + bc) = h;
                *(uint4*)(d + blio + br*72 + bc) = l;
                split8(nb2, nb3, h, l);
                *(uint4*)(d + bhio + br*72 + bc + 8) = h;
                *(uint4*)(d + blio + br*72 + bc + 8) = l;
            }
            __syncthreads();
            buf ^= 1;
        }
        int r0 = rb + (lane >> 2);
        int o0 = s_orow[r0], o1 = s_orow[r0 + 8];
        float wt0 = pw ? (o0 >= 0 ? pw[o0] : 0.f) : 1.f;
        float wt1 = pw ? (o1 >= 0 ? pw[o1] : 0.f) : 1.f;
        #pragma unroll
        for (int nf = 0; nf < 4; nf++) {
            int c = n0 + cB + nf*8 + (lane & 3)*2;
            if (o0 >= 0) {
                float x0 = acc1[nf][0], x1 = acc1[nf][1];
                float2 o;
                o.x = (x0/(1.f+__expf(-x0))) * acc3[nf][0] * wt0;
                o.y = (x1/(1.f+__expf(-x1))) * acc3[nf][1] * wt0;
                *(float2*)&outb[(size_t)o0*HE + c] = o;
            }
            if (o1 >= 0) {
                float x2 = acc1[nf][2], x3 = acc1[nf][3];
                float2 o;
                o.x = (x2/(1.f+__expf(-x2))) * acc3[nf][2] * wt1;
                o.y = (x3/(1.f+__expf(-x3))) * acc3[nf][3] * wt1;
                *(float2*)&outb[(size_t)o1*HE + c] = o;
            }
        }
    }
}

// ============ FFN stage B (tensor cores): MoE GEMM2 + shared down proj (R8-proven) ============
__global__ __launch_bounds__(256) void ffn_b(const float* __restrict__ w2e,
                                             const float* __restrict__ sw2) {
    extern __shared__ __align__(16) char dyn[];
    __nv_bfloat16* sm = (__nv_bfloat16*)dyn;
    int* s_arow = (int*)(dyn + 2*13824*2);
    int* s_orow = s_arow + 64;

    int tid = threadIdx.x, w = tid >> 5, lane = tid & 31;
    int bid = blockIdx.x;

    int ar = tid >> 2, ac = (tid & 3) * 8;
    int br2 = tid >> 3, bc2 = (tid & 7) * 16;
    int rb = (w & 3) * 16, ch = (w >> 2) * 64;

    bool gather = (bid < NE*8);
    const float* Ag; const float* Bg;
    float* outb; int n0; int mTot; int mshb = 0;
    const int* lst = nullptr; int nrows = 0;

    if (gather) {
        int e = bid >> 3; n0 = (bid & 7) * 128;
        nrows = g_cnt[e];
        if (nrows == 0) return;
        lst = &g_list[e*SS];
        Ag = g_gbuf;
        Bg = w2e + (size_t)e*HE*DM + n0;
        outb = g_g2; mTot = nrows;
    } else {
        int b = bid - NE*8;
        n0 = (b & 7) * 128; mshb = (b >> 3) * 64;
        Ag = g_a1; Bg = sw2 + n0;
        outb = g_sh; mTot = 64;
    }

    int a_row_f = rb + (lane & 7) + ((lane >> 3) & 1) * 8;
    int a_col_s = ((lane >> 4) & 1) * 8;
    int b_row_s = lane & 15;

    for (int m0 = 0; m0 < mTot; m0 += 64) {
        __syncthreads();
        if (tid < 64) {
            int arow, orow;
            if (gather) {
                int p = (m0 + tid < nrows) ? lst[m0 + tid] : -1;
                arow = (p < 0) ? 0 : p; orow = p;
            } else { arow = mshb + tid; orow = mshb + tid; }
            s_arow[tid] = arow; s_orow[tid] = orow;
        }
        __syncthreads();
        const float* arp = Ag + (size_t)s_arow[ar]*HE + ac;
        const float* brp = Bg + (size_t)br2*DM + bc2;

        float acc[8][4] = {};

        TC_PROLOGUE(sm)
        __syncthreads();
        int buf = 0;
        for (int kt = 1; kt <= 16; kt++) {
            bool more = (kt < 16);
            float4 na0, na1, nb0, nb1, nb2, nb3;
            if (more) {
                int k0 = kt * 32;
                na0 = *(const float4*)(arp + k0);
                na1 = *(const float4*)(arp + k0 + 4);
                const float* bp = brp + (size_t)k0 * DM;
                nb0 = *(const float4*)bp;  nb1 = *(const float4*)(bp + 4);
                nb2 = *(const float4*)(bp + 8); nb3 = *(const float4*)(bp + 12);
            }
            const __nv_bfloat16* base = sm + buf*13824;
            TC_COMPUTE(base)
            if (more) { __nv_bfloat16* d = sm + (buf^1)*13824; TC_STORE_NEXT(d) }
            __syncthreads();
            buf ^= 1;
        }
        int r0 = rb + (lane >> 2);
        int o0 = s_orow[r0], o1 = s_orow[r0 + 8];
        #pragma unroll
        for (int nf = 0; nf < 8; nf++) {
            int c = n0 + ch + nf*8 + (lane & 3)*2;
            if (o0 >= 0)
                *(float2*)&outb[(size_t)o0*DM + c] = make_float2(acc[nf][0], acc[nf][1]);
            if (o1 >= 0)
                *(float2*)&outb[(size_t)o1*DM + c] = make_float2(acc[nf][2], acc[nf][3]);
        }
    }
}

// ---------------- q/k rmsnorm + rope ----------------
__global__ __launch_bounds__(256) void qknorm_rope(const float* __restrict__ qw,
                                                   const float* __restrict__ kw,
                                                   const float* __restrict__ cosb,
                                                   const float* __restrict__ sinb) {
    int gw = (blockIdx.x * blockDim.x + threadIdx.x) >> 5;
    int lane = threadIdx.x & 31;
    if (gw >= SS * (NHQ + NKVH)) return;
    int t = gw / (NHQ + NKVH);
    int hh = gw % (NHQ + NKVH);
    float* base;
    const float* w;
    if (hh < NHQ) { base = &g_q[(size_t)t*(NHQ*HDIM) + hh*HDIM]; w = qw; }
    else          { base = &g_k[(size_t)t*(NKVH*HDIM) + (hh-NHQ)*HDIM]; w = kw; }
    int d0 = lane * 2;
    float v0 = base[d0], v1 = base[d0+1];
    float ss = v0*v0 + v1*v1;
    #pragma unroll
    for (int off = 16; off; off >>= 1) ss += __shfl_xor_sync(0xffffffffu, ss, off);
    float r = rsqrtf(ss * (1.0f/HDIM) + 1e-5f);
    float n0 = v0 * r * w[d0];
    float n1 = v1 * r * w[d0+1];
    float c = cosb[t*(HDIM/2) + lane];
    float s = sinb[t*(HDIM/2) + lane];
    base[d0]   = n0*c - n1*s;
    base[d0+1] = n0*s + n1*c;
}

// ---------------- flash attention ----------------
#define FLASH_SMEM (4*64*65*4)
__global__ __launch_bounds__(256) void flash_attn() {
    extern __shared__ float smf[];
    float* Qs = smf;
    float* Ks = smf + 64*65;
    float* Vs = smf + 2*64*65;
    float* Ps = smf + 3*64*65;
    int qt = (int)gridDim.x - 1 - (int)blockIdx.x;
    int h = blockIdx.y;
    int kvh = h >> 2;
    int q0 = qt * 64;
    int tid = threadIdx.x;
    int tx = tid & 15, ty = tid >> 4;
    {
        int r = tid >> 2, c = (tid & 3) * 16;
        const float* src = &g_q[(size_t)(q0 + r)*(NHQ*HDIM) + h*HDIM + c];
        #pragma unroll
        for (int i = 0; i < 16; i += 4) {
            float4 vq = *(const float4*)(src + i);
            Qs[r*65+c+i]   = vq.x; Qs[r*65+c+i+1] = vq.y;
            Qs[r*65+c+i+2] = vq.z; Qs[r*65+c+i+3] = vq.w;
        }
    }
    float O[4][4] = {};
    float m_i[4] = {-1e30f,-1e30f,-1e30f,-1e30f};
    float l_i[4] = {};
    __syncthreads();
    for (int kt = 0; kt <= qt; kt++) {
        int k0 = kt * 64;
        {
            int r = tid >> 2, c = (tid & 3) * 16;
            const float* ksrc = &g_k[(size_t)(k0 + r)*(NKVH*HDIM) + kvh*HDIM + c];
            const float* vsrc = &g_v[(size_t)(k0 + r)*(NKVH*HDIM) + kvh*HDIM + c];
            #pragma unroll
            for (int i = 0; i < 16; i += 4) {
                float4 a = *(const float4*)(ksrc + i);
                float4 b = *(const float4*)(vsrc + i);
                Ks[r*65+c+i]=a.x; Ks[r*65+c+i+1]=a.y; Ks[r*65+c+i+2]=a.z; Ks[r*65+c+i+3]=a.w;
                Vs[r*65+c+i]=b.x; Vs[r*65+c+i+1]=b.y; Vs[r*65+c+i+2]=b.z; Vs[r*65+c+i+3]=b.w;
            }
        }
        __syncthreads();
        float s[4][4] = {};
        #pragma unroll 8
        for (int d = 0; d < 64; d++) {
            float qv[4], kv[4];
            #pragma unroll
            for (int i = 0; i < 4; i++) qv[i] = Qs[(ty*4+i)*65 + d];
            #pragma unroll
            for (int j = 0; j < 4; j++) kv[j] = Ks[(tx*4+j)*65 + d];
            #pragma unroll
            for (int i = 0; i < 4; i++)
                #pragma unroll
                for (int j = 0; j < 4; j++)
                    s[i][j] += qv[i]*kv[j];
        }
        const float sc = 0.125f;
        if (kt == qt) {
            #pragma unroll
            for (int i = 0; i < 4; i++)
                #pragma unroll
                for (int j = 0; j < 4; j++)
                    s[i][j] = (tx*4+j <= ty*4+i) ? s[i][j]*sc : -1e30f;
        } else {
            #pragma unroll
            for (int i = 0; i < 4; i++)
                #pragma unroll
                for (int j = 0; j < 4; j++)
                    s[i][j] *= sc;
        }
        #pragma unroll
        for (int i = 0; i < 4; i++) {
            float mx = fmaxf(fmaxf(s[i][0],s[i][1]), fmaxf(s[i][2],s[i][3]));
            mx = fmaxf(mx, __shfl_xor_sync(0xffffffffu, mx, 1));
            mx = fmaxf(mx, __shfl_xor_sync(0xffffffffu, mx, 2));
            mx = fmaxf(mx, __shfl_xor_sync(0xffffffffu, mx, 4));
            mx = fmaxf(mx, __shfl_xor_sync(0xffffffffu, mx, 8));
            float mn = fmaxf(m_i[i], mx);
            float scale = __expf(m_i[i] - mn);
            float rs = 0.f;
            #pragma unroll
            for (int j = 0; j < 4; j++) { float p = __expf(s[i][j]-mn); s[i][j]=p; rs += p; }
            rs += __shfl_xor_sync(0xffffffffu, rs, 1);
            rs += __shfl_xor_sync(0xffffffffu, rs, 2);
            rs += __shfl_xor_sync(0xffffffffu, rs, 4);
            rs += __shfl_xor_sync(0xffffffffu, rs, 8);
            l_i[i] = l_i[i]*scale + rs;
            m_i[i] = mn;
            #pragma unroll
            for (int j = 0; j < 4; j++) {
                O[i][j] *= scale;
                Ps[(ty*4+i)*65 + tx*4+j] = s[i][j];
            }
        }
        __syncthreads();
        #pragma unroll 4
        for (int jj = 0; jj < 64; jj++) {
            float pv[4], vv[4];
            #pragma unroll
            for (int i = 0; i < 4; i++) pv[i] = Ps[(ty*4+i)*65 + jj];
            #pragma unroll
            for (int j = 0; j < 4; j++) vv[j] = Vs[jj*65 + tx*4+j];
            #pragma unroll
            for (int i = 0; i < 4; i++)
                #pragma unroll
                for (int j = 0; j < 4; j++)
                    O[i][j] += pv[i]*vv[j];
        }
        __syncthreads();
    }
    #pragma unroll
    for (int i = 0; i < 4; i++) {
        float inv = 1.f / l_i[i];
        #pragma unroll
        for (int j = 0; j < 4; j++)
            g_attn[(size_t)(q0+ty*4+i)*(NHQ*HDIM) + h*HDIM + tx*4+j] = O[i][j]*inv;
    }
}

// ---------------- gate GEMM (N=64) ----------------
__global__ __launch_bounds__(256) void gemm64(const float* __restrict__ A,
                                              const float* __restrict__ B,
                                              float* __restrict__ C,
                                              int M, int N, int K) {
    __shared__ float As[16][64];
    __shared__ float Bs[16][64];
    int tid = threadIdx.x;
    int tx = tid & 15, ty = tid >> 4;
    int m0 = blockIdx.y * 64, n0 = blockIdx.x * 64;
    int ar = tid >> 2;
    int ac = (tid & 3) * 4;
    int br = tid >> 4;
    int bc = (tid & 15) * 4;
    float acc[4][4] = {};
    for (int k0 = 0; k0 < K; k0 += 16) {
        float4 av = *(const float4*)&A[(size_t)(m0 + ar)*K + k0 + ac];
        float4 bv = *(const float4*)&B[(size_t)(k0 + br)*N + n0 + bc];
        As[ac+0][ar] = av.x; As[ac+1][ar] = av.y;
        As[ac+2][ar] = av.z; As[ac+3][ar] = av.w;
        *(float4*)&Bs[br][bc] = bv;
        __syncthreads();
        #pragma unroll
        for (int k = 0; k < 16; k++) {
            float4 a = *(const float4*)&As[k][ty*4];
            float4 b = *(const float4*)&Bs[k][tx*4];
            float aa[4] = {a.x,a.y,a.z,a.w};
            float bb[4] = {b.x,b.y,b.z,b.w};
            #pragma unroll
            for (int i = 0; i < 4; i++)
                #pragma unroll
                for (int j = 0; j < 4; j++)
                    acc[i][j] += aa[i]*bb[j];
        }
        __syncthreads();
    }
    #pragma unroll
    for (int i = 0; i < 4; i++) {
        float4 ov = make_float4(acc[i][0],acc[i][1],acc[i][2],acc[i][3]);
        *(float4*)&C[(size_t)(m0 + ty*4 + i)*N + n0 + tx*4] = ov;
    }
}

// ---------------- routing ----------------
__global__ void zero_cnt_k() { if (threadIdx.x < NE) g_cnt[threadIdx.x] = 0; }

__global__ void route_k() {
    int t = blockIdx.x;
    int lane = threadIdx.x;
    float v0 = g_logits[t*NE + lane];
    float v1 = g_logits[t*NE + 32 + lane];
    float selv[TOPK]; int seli[TOPK];
    #pragma unroll
    for (int it = 0; it < TOPK; it++) {
        float best = (v0 >= v1) ? v0 : v1;
        int   bi   = (v0 >= v1) ? lane : lane + 32;
        #pragma unroll
        for (int off = 16; off; off >>= 1) {
            float ov = __shfl_xor_sync(0xffffffffu, best, off);
            int   oi = __shfl_xor_sync(0xffffffffu, bi, off);
            if (ov > best || (ov == best && oi < bi)) { best = ov; bi = oi; }
        }
        selv[it] = best; seli[it] = bi;
        if (bi == lane)      v0 = -1e30f;
        if (bi == lane + 32) v1 = -1e30f;
    }
    if (lane < TOPK) {
        float sum = 0.f;
        #pragma unroll
        for (int i = 0; i < TOPK; i++) sum += __expf(selv[i] - selv[0]);
        float w = __expf(selv[lane] - selv[0]) / sum;
        int e = seli[lane];
        int pos = atomicAdd(&g_cnt[e], 1);
        g_list[e*SS + pos] = t*TOPK + lane;
        g_pairw[t*TOPK + lane] = w;
    }
}

// ---------------- final ----------------
__global__ __launch_bounds__(256) void final_k(float* __restrict__ out) {
    int t = blockIdx.x;
    int c = threadIdx.x * 4;
    float4 a = *(const float4*)&g_h[(size_t)t*DM + c];
    float4 b = *(const float4*)&g_sh[(size_t)t*DM + c];
    a.x += b.x; a.y += b.y; a.z += b.z; a.w += b.w;
    #pragma unroll
    for (int kk = 0; kk < TOPK; kk++) {
        float4 gv = *(const float4*)&g_g2[(size_t)(t*TOPK+kk)*DM + c];
        a.x += gv.x; a.y += gv.y; a.z += gv.z; a.w += gv.w;
    }
    *(float4*)&out[(size_t)t*DM + c] = a;
}

// ---------------- host ----------------
extern "C" void kernel_launch(void* const* d_in, const int* in_sizes, int n_in,
                              void* d_out, int out_size) {
    const float* x   = (const float*)d_in[0];
    const float* fc  = (const float*)d_in[1];
    const float* fs  = (const float*)d_in[2];
    const float* anw = (const float*)d_in[3];
    const float* fnw = (const float*)d_in[4];
    const float* wq  = (const float*)d_in[5];
    const float* wk  = (const float*)d_in[6];
    const float* wv  = (const float*)d_in[7];
    const float* wo  = (const float*)d_in[8];
    const float* qnw = (const float*)d_in[9];
    const float* knw = (const float*)d_in[10];
    const float* gw  = (const float*)d_in[11];
    const float* w1e = (const float*)d_in[12];
    const float* w3e = (const float*)d_in[13];
    const float* w2e = (const float*)d_in[14];
    const float* sw1 = (const float*)d_in[15];
    const float* sw3 = (const float*)d_in[16];
    const float* sw2 = (const float*)d_in[17];
    float* out = (float*)d_out;

    float *hx,*attn,*h,*z,*logits;
    cudaGetSymbolAddress((void**)&hx, g_hx);
    cudaGetSymbolAddress((void**)&attn, g_attn);
    cudaGetSymbolAddress((void**)&h,  g_h);
    cudaGetSymbolAddress((void**)&z,  g_z);
    cudaGetSymbolAddress((void**)&logits, g_logits);

    cudaFuncSetAttribute(flash_attn, cudaFuncAttributeMaxDynamicSharedMemorySize, FLASH_SMEM);
    cudaFuncSetAttribute(ffn_a, cudaFuncAttributeMaxDynamicSharedMemorySize, FA_BYTES);
    cudaFuncSetAttribute(ffn_b, cudaFuncAttributeMaxDynamicSharedMemorySize, FB_BYTES);
    cudaFuncSetAttribute(tc_gemm_res, cudaFuncAttributeMaxDynamicSharedMemorySize, FB_BYTES);

    // attention branch
    rmsnorm_k<<<SS, 256>>>(x, anw, hx);
    qkv_gemm<<<dim3(12, 16), 256>>>(hx, wq, wk, wv);                      // FFMA2 (proven)
    qknorm_rope<<<(SS*(NHQ+NKVH)*32)/256, 256>>>(qnw, knw, fc, fs);
    flash_attn<<<dim3(16,16), 256, FLASH_SMEM>>>();
    tc_gemm_res<<<dim3(8, 16), 256, FB_BYTES>>>(attn, wo, h, x, 1024, 1024);  // TC wo (new, under test)

    // ffn branch
    rmsnorm_k<<<SS, 256>>>(h, fnw, z);
    gemm64<<<dim3(1, 16), 256>>>(z, gw, logits, SS, NE, DM);
    zero_cnt_k<<<1, 64>>>();
    route_k<<<SS, 32>>>();
    ffn_a<<<NE*8 + 128, 256, FA_BYTES>>>(w1e, w3e, sw1, sw3);
    ffn_b<<<NE*8 + 128, 256, FB_BYTES>>>(w2e, sw2);

    final_k<<<SS, 256>>>(out);
}

// round 12
// speedup vs baseline: 2.9618x; 1.1470x over previous
#include <cuda_runtime.h>
#include <cuda_bf16.h>
#include <math.h>

#define SS 1024
#define DM 1024
#define NHQ 16
#define NKVH 4
#define HDIM 64
#define NE 64
#define TOPK 6
#define HE 512
#define NPAIR (SS*TOPK)

typedef unsigned long long u64;
typedef unsigned int u32;

// ---------------- tensor-core helpers (bf16 mma + split) ----------------
__device__ __forceinline__ void mma_bf16(float* d, const u32* a, u32 b0, u32 b1) {
    asm volatile("mma.sync.aligned.m16n8k16.row.col.f32.bf16.bf16.f32 "
        "{%0,%1,%2,%3},{%4,%5,%6,%7},{%8,%9},{%0,%1,%2,%3};"
        : "+f"(d[0]),"+f"(d[1]),"+f"(d[2]),"+f"(d[3])
        : "r"(a[0]),"r"(a[1]),"r"(a[2]),"r"(a[3]), "r"(b0),"r"(b1));
}
__device__ __forceinline__ void ldsm4(u32* r, const __nv_bfloat16* p) {
    u32 a = (u32)__cvta_generic_to_shared(p);
    asm volatile("ldmatrix.sync.aligned.m8n8.x4.shared.b16 {%0,%1,%2,%3},[%4];"
        : "=r"(r[0]),"=r"(r[1]),"=r"(r[2]),"=r"(r[3]) : "r"(a));
}
__device__ __forceinline__ void ldsm2t(u32 &r0, u32 &r1, const __nv_bfloat16* p) {
    u32 a = (u32)__cvta_generic_to_shared(p);
    asm volatile("ldmatrix.sync.aligned.m8n8.x2.trans.shared.b16 {%0,%1},[%2];"
        : "=r"(r0),"=r"(r1) : "r"(a));
}
__device__ __forceinline__ u32 pkbf2(float x, float y) {
    __nv_bfloat162 h = __floats2bfloat162_rn(x, y);
    return *reinterpret_cast<u32*>(&h);
}
__device__ __forceinline__ void split8(float4 v0, float4 v1, uint4 &hi, uint4 &lo) {
    float f[8] = {v0.x,v0.y,v0.z,v0.w,v1.x,v1.y,v1.z,v1.w};
    float r[8];
    #pragma unroll
    for (int i = 0; i < 8; i++) r[i] = f[i] - __bfloat162float(__float2bfloat16(f[i]));
    hi = make_uint4(pkbf2(f[0],f[1]),pkbf2(f[2],f[3]),pkbf2(f[4],f[5]),pkbf2(f[6],f[7]));
    lo = make_uint4(pkbf2(r[0],r[1]),pkbf2(r[2],r[3]),pkbf2(r[4],r[5]),pkbf2(r[6],r[7]));
}

// ---------------- scratch ----------------
__device__ float g_hx[SS*DM];
__device__ float g_q[SS*NHQ*HDIM];
__device__ float g_k[SS*NKVH*HDIM];
__device__ float g_v[SS*NKVH*HDIM];
__device__ float g_attn[SS*NHQ*HDIM];
__device__ float g_h[SS*DM];
__device__ float g_z[SS*DM];
__device__ float g_logits[SS*NE];
__device__ float g_pairw[NPAIR];
__device__ int   g_cnt[NE];
__device__ int   g_list[NE*SS];
__device__ float g_gbuf[(size_t)NPAIR*HE];
__device__ float g_g2[(size_t)NPAIR*DM];
__device__ float g_a1[SS*HE];
__device__ float g_sh[SS*DM];

// ---------------- rmsnorm ----------------
__global__ __launch_bounds__(256) void rmsnorm_k(const float* __restrict__ x,
                                                 const float* __restrict__ w,
                                                 float* __restrict__ out) {
    int t = blockIdx.x;
    int tid = threadIdx.x;
    float4 xv = *(const float4*)&x[(size_t)t*DM + tid*4];
    float ss = xv.x*xv.x + xv.y*xv.y + xv.z*xv.z + xv.w*xv.w;
    #pragma unroll
    for (int off = 16; off; off >>= 1) ss += __shfl_xor_sync(0xffffffffu, ss, off);
    __shared__ float red[8];
    if ((tid & 31) == 0) red[tid >> 5] = ss;
    __syncthreads();
    float tot = 0.f;
    #pragma unroll
    for (int i = 0; i < 8; i++) tot += red[i];
    float r = rsqrtf(tot * (1.0f/DM) + 1e-5f);
    float4 wv = *(const float4*)&w[tid*4];
    float4 ov;
    ov.x = wv.x * (xv.x * r); ov.y = wv.y * (xv.y * r);
    ov.z = wv.z * (xv.z * r); ov.w = wv.w * (xv.w * r);
    *(float4*)&out[(size_t)t*DM + tid*4] = ov;
}

// ============ split-bf16 tensor GEMM core macros ============
// BM=64, BN=128, BK=32, 256 threads, 8 warps: rb=(w&3)*16 rows, ch=(w>>2)*64 cols.
// smem per buffer (bf16 elems): Ahi 64x40 @0, Alo @2560, Bhi 32x136 @5120, Blo @9472;
// buffer stride 13824. FB_BYTES total.
#define FB_BYTES (2*13824*2 + 512)

#define TC_PROLOGUE(dst)                                                      \
    {   float4 va0 = *(const float4*)arp;                                     \
        float4 va1 = *(const float4*)(arp + 4);                               \
        float4 vb0 = *(const float4*)brp;                                     \
        float4 vb1 = *(const float4*)(brp + 4);                               \
        float4 vb2 = *(const float4*)(brp + 8);                               \
        float4 vb3 = *(const float4*)(brp + 12);                              \
        uint4 h, l;                                                           \
        split8(va0, va1, h, l);                                               \
        *(uint4*)((dst) + ar*40 + ac) = h;                                    \
        *(uint4*)((dst) + 2560 + ar*40 + ac) = l;                             \
        split8(vb0, vb1, h, l);                                               \
        *(uint4*)((dst) + 5120 + br2*136 + bc2) = h;                          \
        *(uint4*)((dst) + 9472 + br2*136 + bc2) = l;                          \
        split8(vb2, vb3, h, l);                                               \
        *(uint4*)((dst) + 5120 + br2*136 + bc2 + 8) = h;                      \
        *(uint4*)((dst) + 9472 + br2*136 + bc2 + 8) = l;                      \
    }

#define TC_STORE_NEXT(dst)                                                    \
    {   uint4 h, l;                                                           \
        split8(na0, na1, h, l);                                               \
        *(uint4*)((dst) + ar*40 + ac) = h;                                    \
        *(uint4*)((dst) + 2560 + ar*40 + ac) = l;                             \
        split8(nb0, nb1, h, l);                                               \
        *(uint4*)((dst) + 5120 + br2*136 + bc2) = h;                          \
        *(uint4*)((dst) + 9472 + br2*136 + bc2) = l;                          \
        split8(nb2, nb3, h, l);                                               \
        *(uint4*)((dst) + 5120 + br2*136 + bc2 + 8) = h;                      \
        *(uint4*)((dst) + 9472 + br2*136 + bc2 + 8) = l;                      \
    }

#define TC_COMPUTE(base)                                                      \
    {   _Pragma("unroll")                                                     \
        for (int kf = 0; kf < 2; kf++) {                                      \
            u32 ah[4], al[4];                                                 \
            ldsm4(ah, (base) + a_row_f*40 + kf*16 + a_col_s);                 \
            ldsm4(al, (base) + 2560 + a_row_f*40 + kf*16 + a_col_s);          \
            int rB = kf*16 + b_row_s;                                         \
            _Pragma("unroll")                                                 \
            for (int nf = 0; nf < 8; nf++) {                                  \
                u32 bh0, bh1, bl0, bl1;                                       \
                const __nv_bfloat16* pB = (base) + 5120 + rB*136 + ch + nf*8; \
                ldsm2t(bh0, bh1, pB);                                         \
                ldsm2t(bl0, bl1, pB + 4352);                                  \
                mma_bf16(acc[nf], ah, bh0, bh1);                              \
                mma_bf16(acc[nf], ah, bl0, bl1);                              \
                mma_bf16(acc[nf], al, bh0, bh1);                              \
            }                                                                 \
        }                                                                     \
    }

// ---------------- fused QKV GEMM (tensor cores) ----------------
__global__ __launch_bounds__(256) void tc_qkv(const float* __restrict__ A,
                                              const float* __restrict__ wq,
                                              const float* __restrict__ wk,
                                              const float* __restrict__ wv) {
    extern __shared__ __align__(16) char dyn[];
    __nv_bfloat16* sm = (__nv_bfloat16*)dyn;
    int tid = threadIdx.x, w = tid >> 5, lane = tid & 31;
    int bn = blockIdx.x, m0 = blockIdx.y * 64;
    const float* B; float* C; int ldb; int col;
    if (bn < 8)       { B = wq; C = g_q; ldb = 1024; col = bn * 128; }
    else if (bn < 10) { B = wk; C = g_k; ldb = 256;  col = (bn - 8) * 128; }
    else              { B = wv; C = g_v; ldb = 256;  col = (bn - 10) * 128; }

    int ar = tid >> 2, ac = (tid & 3) * 8;
    int br2 = tid >> 3, bc2 = (tid & 7) * 16;
    int rb = (w & 3) * 16, ch = (w >> 2) * 64;
    int a_row_f = rb + (lane & 7) + ((lane >> 3) & 1) * 8;
    int a_col_s = ((lane >> 4) & 1) * 8;
    int b_row_s = lane & 15;

    const float* arp = A + (size_t)(m0 + ar)*DM + ac;
    const float* brp = B + (size_t)br2*ldb + col + bc2;
    float acc[8][4] = {};

    TC_PROLOGUE(sm)
    __syncthreads();
    int buf = 0;
    for (int kt = 1; kt <= 32; kt++) {
        bool more = (kt < 32);
        float4 na0, na1, nb0, nb1, nb2, nb3;
        if (more) {
            int k0 = kt * 32;
            na0 = *(const float4*)(arp + k0);
            na1 = *(const float4*)(arp + k0 + 4);
            const float* bp = brp + (size_t)k0 * ldb;
            nb0 = *(const float4*)bp;  nb1 = *(const float4*)(bp + 4);
            nb2 = *(const float4*)(bp + 8); nb3 = *(const float4*)(bp + 12);
        }
        const __nv_bfloat16* base = sm + buf*13824;
        TC_COMPUTE(base)
        if (more) { __nv_bfloat16* d = sm + (buf^1)*13824; TC_STORE_NEXT(d) }
        __syncthreads();
        buf ^= 1;
    }
    int r0 = m0 + rb + (lane >> 2);
    #pragma unroll
    for (int nf = 0; nf < 8; nf++) {
        int c = col + ch + nf*8 + (lane & 3)*2;
        *(float2*)&C[(size_t)r0*ldb + c]     = make_float2(acc[nf][0], acc[nf][1]);
        *(float2*)&C[(size_t)(r0+8)*ldb + c] = make_float2(acc[nf][2], acc[nf][3]);
    }
}

// ---------------- tensor GEMM + residual (wo; passed R11) ----------------
__global__ __launch_bounds__(256) void tc_gemm_res(const float* __restrict__ A,
                                                   const float* __restrict__ B,
                                                   float* __restrict__ C,
                                                   const float* __restrict__ res,
                                                   int N, int K) {
    extern __shared__ __align__(16) char dyn[];
    __nv_bfloat16* sm = (__nv_bfloat16*)dyn;
    int tid = threadIdx.x, w = tid >> 5, lane = tid & 31;
    int n0 = blockIdx.x * 128, m0 = blockIdx.y * 64;

    int ar = tid >> 2, ac = (tid & 3) * 8;
    int br2 = tid >> 3, bc2 = (tid & 7) * 16;
    int rb = (w & 3) * 16, ch = (w >> 2) * 64;
    int a_row_f = rb + (lane & 7) + ((lane >> 3) & 1) * 8;
    int a_col_s = ((lane >> 4) & 1) * 8;
    int b_row_s = lane & 15;

    const float* arp = A + (size_t)(m0 + ar)*K + ac;
    const float* brp = B + (size_t)br2*N + n0 + bc2;
    float acc[8][4] = {};

    TC_PROLOGUE(sm)
    __syncthreads();
    int buf = 0;
    int nkt = K / 32;
    for (int kt = 1; kt <= nkt; kt++) {
        bool more = (kt < nkt);
        float4 na0, na1, nb0, nb1, nb2, nb3;
        if (more) {
            int k0 = kt * 32;
            na0 = *(const float4*)(arp + k0);
            na1 = *(const float4*)(arp + k0 + 4);
            const float* bp = brp + (size_t)k0 * N;
            nb0 = *(const float4*)bp;  nb1 = *(const float4*)(bp + 4);
            nb2 = *(const float4*)(bp + 8); nb3 = *(const float4*)(bp + 12);
        }
        const __nv_bfloat16* base = sm + buf*13824;
        TC_COMPUTE(base)
        if (more) { __nv_bfloat16* d = sm + (buf^1)*13824; TC_STORE_NEXT(d) }
        __syncthreads();
        buf ^= 1;
    }
    int r0 = m0 + rb + (lane >> 2);
    #pragma unroll
    for (int nf = 0; nf < 8; nf++) {
        int c = n0 + ch + nf*8 + (lane & 3)*2;
        float2 v0 = make_float2(acc[nf][0], acc[nf][1]);
        float2 v1 = make_float2(acc[nf][2], acc[nf][3]);
        if (res) {
            float2 q0 = *(const float2*)&res[(size_t)r0*N + c];
            float2 q1 = *(const float2*)&res[(size_t)(r0+8)*N + c];
            v0.x += q0.x; v0.y += q0.y; v1.x += q1.x; v1.y += q1.y;
        }
        *(float2*)&C[(size_t)r0*N + c]     = v0;
        *(float2*)&C[(size_t)(r0+8)*N + c] = v1;
    }
}

// ============ FFN stage A (tensor cores): MoE GEMM1 + shared dual GEMM (proven) ============
#define FA_BYTES (2*14336*2 + 512)
__global__ __launch_bounds__(256) void ffn_a(const float* __restrict__ w1e,
                                             const float* __restrict__ w3e,
                                             const float* __restrict__ sw1,
                                             const float* __restrict__ sw3) {
    extern __shared__ __align__(16) char dyn[];
    __nv_bfloat16* sm = (__nv_bfloat16*)dyn;
    int* s_arow = (int*)(dyn + 2*14336*2);
    int* s_orow = s_arow + 64;

    int tid = threadIdx.x, w = tid >> 5, lane = tid & 31;
    int bid = blockIdx.x;

    int ar = tid >> 2, ac = (tid & 3) * 8;
    int bmat = tid >> 7, br = (tid & 127) >> 2, bc = (tid & 3) * 16;
    int rb = (w & 3) * 16, ch = w >> 2;

    bool gather = (bid < NE*8);
    const float* B1g; const float* B3g;
    float* outb; const float* pw; int n0; int mTot; int mshb = 0;
    const int* lst = nullptr; int nrows = 0;

    if (gather) {
        int e = bid >> 3; n0 = (bid & 7) * 64;
        nrows = g_cnt[e];
        if (nrows == 0) return;
        lst = &g_list[e*SS];
        B1g = w1e + (size_t)e*DM*HE + n0;
        B3g = w3e + (size_t)e*DM*HE + n0;
        outb = g_gbuf; pw = g_pairw; mTot = nrows;
    } else {
        int b = bid - NE*8;
        n0 = (b & 7) * 64; mshb = (b >> 3) * 64;
        B1g = sw1 + n0; B3g = sw3 + n0;
        outb = g_a1; pw = nullptr; mTot = 64;
    }
    const float* Bgm = bmat ? B3g : B1g;
    int bhio = 5120 + bmat*4608, blio = bhio + 2304;

    int a_row_f = rb + (lane & 7) + ((lane >> 3) & 1) * 8;
    int a_col_s = ((lane >> 4) & 1) * 8;
    int b_row_s = lane & 15;
    int cB = ch * 32;

    for (int m0 = 0; m0 < mTot; m0 += 64) {
        __syncthreads();
        if (tid < 64) {
            int arow, orow;
            if (gather) {
                int p = (m0 + tid < nrows) ? lst[m0 + tid] : -1;
                arow = (p < 0) ? 0 : p / TOPK; orow = p;
            } else { arow = mshb + tid; orow = mshb + tid; }
            s_arow[tid] = arow; s_orow[tid] = orow;
        }
        __syncthreads();
        const float* arp = g_z + (size_t)s_arow[ar]*DM + ac;
        const float* brp = Bgm + (size_t)br*HE + bc;

        float acc1[4][4] = {}; float acc3[4][4] = {};

        {
            float4 va0 = *(const float4*)arp;
            float4 va1 = *(const float4*)(arp + 4);
            float4 vb0 = *(const float4*)brp;
            float4 vb1 = *(const float4*)(brp + 4);
            float4 vb2 = *(const float4*)(brp + 8);
            float4 vb3 = *(const float4*)(brp + 12);
            uint4 h, l;
            split8(va0, va1, h, l);
            *(uint4*)(sm + ar*40 + ac) = h;
            *(uint4*)(sm + 2560 + ar*40 + ac) = l;
            split8(vb0, vb1, h, l);
            *(uint4*)(sm + bhio + br*72 + bc) = h;
            *(uint4*)(sm + blio + br*72 + bc) = l;
            split8(vb2, vb3, h, l);
            *(uint4*)(sm + bhio + br*72 + bc + 8) = h;
            *(uint4*)(sm + blio + br*72 + bc + 8) = l;
        }
        __syncthreads();
        int buf = 0;
        for (int kt = 1; kt <= 32; kt++) {
            bool more = (kt < 32);
            float4 na0, na1, nb0, nb1, nb2, nb3;
            if (more) {
                int k0 = kt * 32;
                na0 = *(const float4*)(arp + k0);
                na1 = *(const float4*)(arp + k0 + 4);
                const float* bp = brp + (size_t)k0 * HE;
                nb0 = *(const float4*)bp;  nb1 = *(const float4*)(bp + 4);
                nb2 = *(const float4*)(bp + 8); nb3 = *(const float4*)(bp + 12);
            }
            {
                const __nv_bfloat16* base = sm + buf*14336;
                #pragma unroll
                for (int kf = 0; kf < 2; kf++) {
                    u32 ah[4], al[4];
                    ldsm4(ah, base + a_row_f*40 + kf*16 + a_col_s);
                    ldsm4(al, base + 2560 + a_row_f*40 + kf*16 + a_col_s);
                    int rB = kf*16 + b_row_s;
                    #pragma unroll
                    for (int nf = 0; nf < 4; nf++) {
                        u32 bh0, bh1, bl0, bl1;
                        const __nv_bfloat16* pB1 = base + 5120 + rB*72 + cB + nf*8;
                        ldsm2t(bh0, bh1, pB1);
                        ldsm2t(bl0, bl1, pB1 + 2304);
                        mma_bf16(acc1[nf], ah, bh0, bh1);
                        mma_bf16(acc1[nf], ah, bl0, bl1);
                        mma_bf16(acc1[nf], al, bh0, bh1);
                        const __nv_bfloat16* pB3 = pB1 + 4608;
                        ldsm2t(bh0, bh1, pB3);
                        ldsm2t(bl0, bl1, pB3 + 2304);
                        mma_bf16(acc3[nf], ah, bh0, bh1);
                        mma_bf16(acc3[nf], ah, bl0, bl1);
                        mma_bf16(acc3[nf], al, bh0, bh1);
                    }
                }
            }
            if (more) {
                __nv_bfloat16* d = sm + (buf^1)*14336;
                uint4 h, l;
                split8(na0, na1, h, l);
                *(uint4*)(d + ar*40 + ac) = h;
                *(uint4*)(d + 2560 + ar*40 + ac) = l;
                split8(nb0, nb1, h, l);
                *(uint4*)(d + bhio + br*72 + bc) = h;
                *(uint4*)(d + blio + br*72 + bc) = l;
                split8(nb2, nb3, h, l);
                *(uint4*)(d + bhio + br*72 + bc + 8) = h;
                *(uint4*)(d + blio + br*72 + bc + 8) = l;
            }
            __syncthreads();
            buf ^= 1;
        }
        int r0 = rb + (lane >> 2);
        int o0 = s_orow[r0], o1 = s_orow[r0 + 8];
        float wt0 = pw ? (o0 >= 0 ? pw[o0] : 0.f) : 1.f;
        float wt1 = pw ? (o1 >= 0 ? pw[o1] : 0.f) : 1.f;
        #pragma unroll
        for (int nf = 0; nf < 4; nf++) {
            int c = n0 + cB + nf*8 + (lane & 3)*2;
            if (o0 >= 0) {
                float x0 = acc1[nf][0], x1 = acc1[nf][1];
                float2 o;
                o.x = (x0/(1.f+__expf(-x0))) * acc3[nf][0] * wt0;
                o.y = (x1/(1.f+__expf(-x1))) * acc3[nf][1] * wt0;
                *(float2*)&outb[(size_t)o0*HE + c] = o;
            }
            if (o1 >= 0) {
                float x2 = acc1[nf][2], x3 = acc1[nf][3];
                float2 o;
                o.x = (x2/(1.f+__expf(-x2))) * acc3[nf][2] * wt1;
                o.y = (x3/(1.f+__expf(-x3))) * acc3[nf][3] * wt1;
                *(float2*)&outb[(size_t)o1*HE + c] = o;
            }
        }
    }
}

// ============ FFN stage B (tensor cores): MoE GEMM2 + shared down proj (proven) ============
__global__ __launch_bounds__(256) void ffn_b(const float* __restrict__ w2e,
                                             const float* __restrict__ sw2) {
    extern __shared__ __align__(16) char dyn[];
    __nv_bfloat16* sm = (__nv_bfloat16*)dyn;
    int* s_arow = (int*)(dyn + 2*13824*2);
    int* s_orow = s_arow + 64;

    int tid = threadIdx.x, w = tid >> 5, lane = tid & 31;
    int bid = blockIdx.x;

    int ar = tid >> 2, ac = (tid & 3) * 8;
    int br2 = tid >> 3, bc2 = (tid & 7) * 16;
    int rb = (w & 3) * 16, ch = (w >> 2) * 64;

    bool gather = (bid < NE*8);
    const float* Ag; const float* Bg;
    float* outb; int n0; int mTot; int mshb = 0;
    const int* lst = nullptr; int nrows = 0;

    if (gather) {
        int e = bid >> 3; n0 = (bid & 7) * 128;
        nrows = g_cnt[e];
        if (nrows == 0) return;
        lst = &g_list[e*SS];
        Ag = g_gbuf;
        Bg = w2e + (size_t)e*HE*DM + n0;
        outb = g_g2; mTot = nrows;
    } else {
        int b = bid - NE*8;
        n0 = (b & 7) * 128; mshb = (b >> 3) * 64;
        Ag = g_a1; Bg = sw2 + n0;
        outb = g_sh; mTot = 64;
    }

    int a_row_f = rb + (lane & 7) + ((lane >> 3) & 1) * 8;
    int a_col_s = ((lane >> 4) & 1) * 8;
    int b_row_s = lane & 15;

    for (int m0 = 0; m0 < mTot; m0 += 64) {
        __syncthreads();
        if (tid < 64) {
            int arow, orow;
            if (gather) {
                int p = (m0 + tid < nrows) ? lst[m0 + tid] : -1;
                arow = (p < 0) ? 0 : p; orow = p;
            } else { arow = mshb + tid; orow = mshb + tid; }
            s_arow[tid] = arow; s_orow[tid] = orow;
        }
        __syncthreads();
        const float* arp = Ag + (size_t)s_arow[ar]*HE + ac;
        const float* brp = Bg + (size_t)br2*DM + bc2;

        float acc[8][4] = {};

        TC_PROLOGUE(sm)
        __syncthreads();
        int buf = 0;
        for (int kt = 1; kt <= 16; kt++) {
            bool more = (kt < 16);
            float4 na0, na1, nb0, nb1, nb2, nb3;
            if (more) {
                int k0 = kt * 32;
                na0 = *(const float4*)(arp + k0);
                na1 = *(const float4*)(arp + k0 + 4);
                const float* bp = brp + (size_t)k0 * DM;
                nb0 = *(const float4*)bp;  nb1 = *(const float4*)(bp + 4);
                nb2 = *(const float4*)(bp + 8); nb3 = *(const float4*)(bp + 12);
            }
            const __nv_bfloat16* base = sm + buf*13824;
            TC_COMPUTE(base)
            if (more) { __nv_bfloat16* d = sm + (buf^1)*13824; TC_STORE_NEXT(d) }
            __syncthreads();
            buf ^= 1;
        }
        int r0 = rb + (lane >> 2);
        int o0 = s_orow[r0], o1 = s_orow[r0 + 8];
        #pragma unroll
        for (int nf = 0; nf < 8; nf++) {
            int c = n0 + ch + nf*8 + (lane & 3)*2;
            if (o0 >= 0)
                *(float2*)&outb[(size_t)o0*DM + c] = make_float2(acc[nf][0], acc[nf][1]);
            if (o1 >= 0)
                *(float2*)&outb[(size_t)o1*DM + c] = make_float2(acc[nf][2], acc[nf][3]);
        }
    }
}

// ---------------- q/k rmsnorm + rope ----------------
__global__ __launch_bounds__(256) void qknorm_rope(const float* __restrict__ qw,
                                                   const float* __restrict__ kw,
                                                   const float* __restrict__ cosb,
                                                   const float* __restrict__ sinb) {
    int gw = (blockIdx.x * blockDim.x + threadIdx.x) >> 5;
    int lane = threadIdx.x & 31;
    if (gw >= SS * (NHQ + NKVH)) return;
    int t = gw / (NHQ + NKVH);
    int hh = gw % (NHQ + NKVH);
    float* base;
    const float* w;
    if (hh < NHQ) { base = &g_q[(size_t)t*(NHQ*HDIM) + hh*HDIM]; w = qw; }
    else          { base = &g_k[(size_t)t*(NKVH*HDIM) + (hh-NHQ)*HDIM]; w = kw; }
    int d0 = lane * 2;
    float v0 = base[d0], v1 = base[d0+1];
    float ss = v0*v0 + v1*v1;
    #pragma unroll
    for (int off = 16; off; off >>= 1) ss += __shfl_xor_sync(0xffffffffu, ss, off);
    float r = rsqrtf(ss * (1.0f/HDIM) + 1e-5f);
    float n0 = v0 * r * w[d0];
    float n1 = v1 * r * w[d0+1];
    float c = cosb[t*(HDIM/2) + lane];
    float s = sinb[t*(HDIM/2) + lane];
    base[d0]   = n0*c - n1*s;
    base[d0+1] = n0*s + n1*c;
}

// ---------------- flash attention ----------------
#define FLASH_SMEM (4*64*65*4)
__global__ __launch_bounds__(256) void flash_attn() {
    extern __shared__ float smf[];
    float* Qs = smf;
    float* Ks = smf + 64*65;
    float* Vs = smf + 2*64*65;
    float* Ps = smf + 3*64*65;
    int qt = (int)gridDim.x - 1 - (int)blockIdx.x;
    int h = blockIdx.y;
    int kvh = h >> 2;
    int q0 = qt * 64;
    int tid = threadIdx.x;
    int tx = tid & 15, ty = tid >> 4;
    {
        int r = tid >> 2, c = (tid & 3) * 16;
        const float* src = &g_q[(size_t)(q0 + r)*(NHQ*HDIM) + h*HDIM + c];
        #pragma unroll
        for (int i = 0; i < 16; i += 4) {
            float4 vq = *(const float4*)(src + i);
            Qs[r*65+c+i]   = vq.x; Qs[r*65+c+i+1] = vq.y;
            Qs[r*65+c+i+2] = vq.z; Qs[r*65+c+i+3] = vq.w;
        }
    }
    float O[4][4] = {};
    float m_i[4] = {-1e30f,-1e30f,-1e30f,-1e30f};
    float l_i[4] = {};
    __syncthreads();
    for (int kt = 0; kt <= qt; kt++) {
        int k0 = kt * 64;
        {
            int r = tid >> 2, c = (tid & 3) * 16;
            const float* ksrc = &g_k[(size_t)(k0 + r)*(NKVH*HDIM) + kvh*HDIM + c];
            const float* vsrc = &g_v[(size_t)(k0 + r)*(NKVH*HDIM) + kvh*HDIM + c];
            #pragma unroll
            for (int i = 0; i < 16; i += 4) {
                float4 a = *(const float4*)(ksrc + i);
                float4 b = *(const float4*)(vsrc + i);
                Ks[r*65+c+i]=a.x; Ks[r*65+c+i+1]=a.y; Ks[r*65+c+i+2]=a.z; Ks[r*65+c+i+3]=a.w;
                Vs[r*65+c+i]=b.x; Vs[r*65+c+i+1]=b.y; Vs[r*65+c+i+2]=b.z; Vs[r*65+c+i+3]=b.w;
            }
        }
        __syncthreads();
        float s[4][4] = {};
        #pragma unroll 8
        for (int d = 0; d < 64; d++) {
            float qv[4], kv[4];
            #pragma unroll
            for (int i = 0; i < 4; i++) qv[i] = Qs[(ty*4+i)*65 + d];
            #pragma unroll
            for (int j = 0; j < 4; j++) kv[j] = Ks[(tx*4+j)*65 + d];
            #pragma unroll
            for (int i = 0; i < 4; i++)
                #pragma unroll
                for (int j = 0; j < 4; j++)
                    s[i][j] += qv[i]*kv[j];
        }
        const float sc = 0.125f;
        if (kt == qt) {
            #pragma unroll
            for (int i = 0; i < 4; i++)
                #pragma unroll
                for (int j = 0; j < 4; j++)
                    s[i][j] = (tx*4+j <= ty*4+i) ? s[i][j]*sc : -1e30f;
        } else {
            #pragma unroll
            for (int i = 0; i < 4; i++)
                #pragma unroll
                for (int j = 0; j < 4; j++)
                    s[i][j] *= sc;
        }
        #pragma unroll
        for (int i = 0; i < 4; i++) {
            float mx = fmaxf(fmaxf(s[i][0],s[i][1]), fmaxf(s[i][2],s[i][3]));
            mx = fmaxf(mx, __shfl_xor_sync(0xffffffffu, mx, 1));
            mx = fmaxf(mx, __shfl_xor_sync(0xffffffffu, mx, 2));
            mx = fmaxf(mx, __shfl_xor_sync(0xffffffffu, mx, 4));
            mx = fmaxf(mx, __shfl_xor_sync(0xffffffffu, mx, 8));
            float mn = fmaxf(m_i[i], mx);
            float scale = __expf(m_i[i] - mn);
            float rs = 0.f;
            #pragma unroll
            for (int j = 0; j < 4; j++) { float p = __expf(s[i][j]-mn); s[i][j]=p; rs += p; }
            rs += __shfl_xor_sync(0xffffffffu, rs, 1);
            rs += __shfl_xor_sync(0xffffffffu, rs, 2);
            rs += __shfl_xor_sync(0xffffffffu, rs, 4);
            rs += __shfl_xor_sync(0xffffffffu, rs, 8);
            l_i[i] = l_i[i]*scale + rs;
            m_i[i] = mn;
            #pragma unroll
            for (int j = 0; j < 4; j++) {
                O[i][j] *= scale;
                Ps[(ty*4+i)*65 + tx*4+j] = s[i][j];
            }
        }
        __syncthreads();
        #pragma unroll 4
        for (int jj = 0; jj < 64; jj++) {
            float pv[4], vv[4];
            #pragma unroll
            for (int i = 0; i < 4; i++) pv[i] = Ps[(ty*4+i)*65 + jj];
            #pragma unroll
            for (int j = 0; j < 4; j++) vv[j] = Vs[jj*65 + tx*4+j];
            #pragma unroll
            for (int i = 0; i < 4; i++)
                #pragma unroll
                for (int j = 0; j < 4; j++)
                    O[i][j] += pv[i]*vv[j];
        }
        __syncthreads();
    }
    #pragma unroll
    for (int i = 0; i < 4; i++) {
        float inv = 1.f / l_i[i];
        #pragma unroll
        for (int j = 0; j < 4; j++)
            g_attn[(size_t)(q0+ty*4+i)*(NHQ*HDIM) + h*HDIM + tx*4+j] = O[i][j]*inv;
    }
}

// ---------------- gate GEMM (N=64) ----------------
__global__ __launch_bounds__(256) void gemm64(const float* __restrict__ A,
                                              const float* __restrict__ B,
                                              float* __restrict__ C,
                                              int M, int N, int K) {
    __shared__ float As[16][64];
    __shared__ float Bs[16][64];
    int tid = threadIdx.x;
    int tx = tid & 15, ty = tid >> 4;
    int m0 = blockIdx.y * 64, n0 = blockIdx.x * 64;
    int ar = tid >> 2;
    int ac = (tid & 3) * 4;
    int br = tid >> 4;
    int bc = (tid & 15) * 4;
    float acc[4][4] = {};
    for (int k0 = 0; k0 < K; k0 += 16) {
        float4 av = *(const float4*)&A[(size_t)(m0 + ar)*K + k0 + ac];
        float4 bv = *(const float4*)&B[(size_t)(k0 + br)*N + n0 + bc];
        As[ac+0][ar] = av.x; As[ac+1][ar] = av.y;
        As[ac+2][ar] = av.z; As[ac+3][ar] = av.w;
        *(float4*)&Bs[br][bc] = bv;
        __syncthreads();
        #pragma unroll
        for (int k = 0; k < 16; k++) {
            float4 a = *(const float4*)&As[k][ty*4];
            float4 b = *(const float4*)&Bs[k][tx*4];
            float aa[4] = {a.x,a.y,a.z,a.w};
            float bb[4] = {b.x,b.y,b.z,b.w};
            #pragma unroll
            for (int i = 0; i < 4; i++)
                #pragma unroll
                for (int j = 0; j < 4; j++)
                    acc[i][j] += aa[i]*bb[j];
        }
        __syncthreads();
    }
    #pragma unroll
    for (int i = 0; i < 4; i++) {
        float4 ov = make_float4(acc[i][0],acc[i][1],acc[i][2],acc[i][3]);
        *(float4*)&C[(size_t)(m0 + ty*4 + i)*N + n0 + tx*4] = ov;
    }
}

// ---------------- routing ----------------
__global__ void zero_cnt_k() { if (threadIdx.x < NE) g_cnt[threadIdx.x] = 0; }

__global__ void route_k() {
    int t = blockIdx.x;
    int lane = threadIdx.x;
    float v0 = g_logits[t*NE + lane];
    float v1 = g_logits[t*NE + 32 + lane];
    float selv[TOPK]; int seli[TOPK];
    #pragma unroll
    for (int it = 0; it < TOPK; it++) {
        float best = (v0 >= v1) ? v0 : v1;
        int   bi   = (v0 >= v1) ? lane : lane + 32;
        #pragma unroll
        for (int off = 16; off; off >>= 1) {
            float ov = __shfl_xor_sync(0xffffffffu, best, off);
            int   oi = __shfl_xor_sync(0xffffffffu, bi, off);
            if (ov > best || (ov == best && oi < bi)) { best = ov; bi = oi; }
        }
        selv[it] = best; seli[it] = bi;
        if (bi == lane)      v0 = -1e30f;
        if (bi == lane + 32) v1 = -1e30f;
    }
    if (lane < TOPK) {
        float sum = 0.f;
        #pragma unroll
        for (int i = 0; i < TOPK; i++) sum += __expf(selv[i] - selv[0]);
        float w = __expf(selv[lane] - selv[0]) / sum;
        int e = seli[lane];
        int pos = atomicAdd(&g_cnt[e], 1);
        g_list[e*SS + pos] = t*TOPK + lane;
        g_pairw[t*TOPK + lane] = w;
    }
}

// ---------------- final ----------------
__global__ __launch_bounds__(256) void final_k(float* __restrict__ out) {
    int t = blockIdx.x;
    int c = threadIdx.x * 4;
    float4 a = *(const float4*)&g_h[(size_t)t*DM + c];
    float4 b = *(const float4*)&g_sh[(size_t)t*DM + c];
    a.x += b.x; a.y += b.y; a.z += b.z; a.w += b.w;
    #pragma unroll
    for (int kk = 0; kk < TOPK; kk++) {
        float4 gv = *(const float4*)&g_g2[(size_t)(t*TOPK+kk)*DM + c];
        a.x += gv.x; a.y += gv.y; a.z += gv.z; a.w += gv.w;
    }
    *(float4*)&out[(size_t)t*DM + c] = a;
}

// ---------------- host ----------------
extern "C" void kernel_launch(void* const* d_in, const int* in_sizes, int n_in,
                              void* d_out, int out_size) {
    const float* x   = (const float*)d_in[0];
    const float* fc  = (const float*)d_in[1];
    const float* fs  = (const float*)d_in[2];
    const float* anw = (const float*)d_in[3];
    const float* fnw = (const float*)d_in[4];
    const float* wq  = (const float*)d_in[5];
    const float* wk  = (const float*)d_in[6];
    const float* wv  = (const float*)d_in[7];
    const float* wo  = (const float*)d_in[8];
    const float* qnw = (const float*)d_in[9];
    const float* knw = (const float*)d_in[10];
    const float* gw  = (const float*)d_in[11];
    const float* w1e = (const float*)d_in[12];
    const float* w3e = (const float*)d_in[13];
    const float* w2e = (const float*)d_in[14];
    const float* sw1 = (const float*)d_in[15];
    const float* sw3 = (const float*)d_in[16];
    const float* sw2 = (const float*)d_in[17];
    float* out = (float*)d_out;

    float *hx,*attn,*h,*z,*logits;
    cudaGetSymbolAddress((void**)&hx, g_hx);
    cudaGetSymbolAddress((void**)&attn, g_attn);
    cudaGetSymbolAddress((void**)&h,  g_h);
    cudaGetSymbolAddress((void**)&z,  g_z);
    cudaGetSymbolAddress((void**)&logits, g_logits);

    cudaFuncSetAttribute(flash_attn, cudaFuncAttributeMaxDynamicSharedMemorySize, FLASH_SMEM);
    cudaFuncSetAttribute(ffn_a, cudaFuncAttributeMaxDynamicSharedMemorySize, FA_BYTES);
    cudaFuncSetAttribute(ffn_b, cudaFuncAttributeMaxDynamicSharedMemorySize, FB_BYTES);
    cudaFuncSetAttribute(tc_qkv, cudaFuncAttributeMaxDynamicSharedMemorySize, FB_BYTES);
    cudaFuncSetAttribute(tc_gemm_res, cudaFuncAttributeMaxDynamicSharedMemorySize, FB_BYTES);

    // attention branch
    rmsnorm_k<<<SS, 256>>>(x, anw, hx);
    tc_qkv<<<dim3(12, 16), 256, FB_BYTES>>>(hx, wq, wk, wv);              // TC qkv (bisect step 2)
    qknorm_rope<<<(SS*(NHQ+NKVH)*32)/256, 256>>>(qnw, knw, fc, fs);
    flash_attn<<<dim3(16,16), 256, FLASH_SMEM>>>();
    tc_gemm_res<<<dim3(8, 16), 256, FB_BYTES>>>(attn, wo, h, x, 1024, 1024);  // TC wo (proven R11)

    // ffn branch
    rmsnorm_k<<<SS, 256>>>(h, fnw, z);
    gemm64<<<dim3(1, 16), 256>>>(z, gw, logits, SS, NE, DM);
    zero_cnt_k<<<1, 64>>>();
    route_k<<<SS, 32>>>();
    ffn_a<<<NE*8 + 128, 256, FA_BYTES>>>(w1e, w3e, sw1, sw3);
    ffn_b<<<NE*8 + 128, 256, FB_BYTES>>>(w2e, sw2);

    final_k<<<SS, 256>>>(out);
}

// round 14
// speedup vs baseline: 3.2643x; 1.1021x over previous
#include <cuda_runtime.h>
#include <cuda_bf16.h>
#include <math.h>

#define SS 1024
#define DM 1024
#define NHQ 16
#define NKVH 4
#define HDIM 64
#define NE 64
#define TOPK 6
#define HE 512
#define NPAIR (SS*TOPK)

typedef unsigned long long u64;
typedef unsigned int u32;

// ---------------- tensor-core helpers (bf16 mma + split) ----------------
__device__ __forceinline__ void mma_bf16(float* d, const u32* a, u32 b0, u32 b1) {
    asm volatile("mma.sync.aligned.m16n8k16.row.col.f32.bf16.bf16.f32 "
        "{%0,%1,%2,%3},{%4,%5,%6,%7},{%8,%9},{%0,%1,%2,%3};"
        : "+f"(d[0]),"+f"(d[1]),"+f"(d[2]),"+f"(d[3])
        : "r"(a[0]),"r"(a[1]),"r"(a[2]),"r"(a[3]), "r"(b0),"r"(b1));
}
__device__ __forceinline__ void ldsm4(u32* r, const __nv_bfloat16* p) {
    u32 a = (u32)__cvta_generic_to_shared(p);
    asm volatile("ldmatrix.sync.aligned.m8n8.x4.shared.b16 {%0,%1,%2,%3},[%4];"
        : "=r"(r[0]),"=r"(r[1]),"=r"(r[2]),"=r"(r[3]) : "r"(a));
}
__device__ __forceinline__ void ldsm2(u32 &r0, u32 &r1, const __nv_bfloat16* p) {
    u32 a = (u32)__cvta_generic_to_shared(p);
    asm volatile("ldmatrix.sync.aligned.m8n8.x2.shared.b16 {%0,%1},[%2];"
        : "=r"(r0),"=r"(r1) : "r"(a));
}
__device__ __forceinline__ void ldsm2t(u32 &r0, u32 &r1, const __nv_bfloat16* p) {
    u32 a = (u32)__cvta_generic_to_shared(p);
    asm volatile("ldmatrix.sync.aligned.m8n8.x2.trans.shared.b16 {%0,%1},[%2];"
        : "=r"(r0),"=r"(r1) : "r"(a));
}
__device__ __forceinline__ u32 pkbf2(float x, float y) {
    __nv_bfloat162 h = __floats2bfloat162_rn(x, y);
    return *reinterpret_cast<u32*>(&h);
}
__device__ __forceinline__ u32 pkres2(float x, float y) {
    float rx = x - __bfloat162float(__float2bfloat16(x));
    float ry = y - __bfloat162float(__float2bfloat16(y));
    return pkbf2(rx, ry);
}
__device__ __forceinline__ void split8(float4 v0, float4 v1, uint4 &hi, uint4 &lo) {
    float f[8] = {v0.x,v0.y,v0.z,v0.w,v1.x,v1.y,v1.z,v1.w};
    float r[8];
    #pragma unroll
    for (int i = 0; i < 8; i++) r[i] = f[i] - __bfloat162float(__float2bfloat16(f[i]));
    hi = make_uint4(pkbf2(f[0],f[1]),pkbf2(f[2],f[3]),pkbf2(f[4],f[5]),pkbf2(f[6],f[7]));
    lo = make_uint4(pkbf2(r[0],r[1]),pkbf2(r[2],r[3]),pkbf2(r[4],r[5]),pkbf2(r[6],r[7]));
}

// ---------------- scratch ----------------
__device__ float g_hx[SS*DM];
__device__ float g_q[SS*NHQ*HDIM];
__device__ float g_k[SS*NKVH*HDIM];
__device__ float g_v[SS*NKVH*HDIM];
__device__ float g_attn[SS*NHQ*HDIM];
__device__ float g_h[SS*DM];
__device__ float g_z[SS*DM];
__device__ float g_logits[SS*NE];
__device__ float g_pairw[NPAIR];
__device__ int   g_cnt[NE];
__device__ int   g_list[NE*SS];
__device__ float g_gbuf[(size_t)NPAIR*HE];
__device__ float g_g2[(size_t)NPAIR*DM];
__device__ float g_a1[SS*HE];
__device__ float g_sh[SS*DM];

// ---------------- rmsnorm ----------------
__global__ __launch_bounds__(256) void rmsnorm_k(const float* __restrict__ x,
                                                 const float* __restrict__ w,
                                                 float* __restrict__ out) {
    int t = blockIdx.x;
    int tid = threadIdx.x;
    float4 xv = *(const float4*)&x[(size_t)t*DM + tid*4];
    float ss = xv.x*xv.x + xv.y*xv.y + xv.z*xv.z + xv.w*xv.w;
    #pragma unroll
    for (int off = 16; off; off >>= 1) ss += __shfl_xor_sync(0xffffffffu, ss, off);
    __shared__ float red[8];
    if ((tid & 31) == 0) red[tid >> 5] = ss;
    __syncthreads();
    float tot = 0.f;
    #pragma unroll
    for (int i = 0; i < 8; i++) tot += red[i];
    float r = rsqrtf(tot * (1.0f/DM) + 1e-5f);
    float4 wv = *(const float4*)&w[tid*4];
    float4 ov;
    ov.x = wv.x * (xv.x * r); ov.y = wv.y * (xv.y * r);
    ov.z = wv.z * (xv.z * r); ov.w = wv.w * (xv.w * r);
    *(float4*)&out[(size_t)t*DM + tid*4] = ov;
}

// ============ split-bf16 tensor GEMM core macros ============
#define FB_BYTES (2*13824*2 + 512)

#define TC_PROLOGUE(dst)                                                      \
    {   float4 va0 = *(const float4*)arp;                                     \
        float4 va1 = *(const float4*)(arp + 4);                               \
        float4 vb0 = *(const float4*)brp;                                     \
        float4 vb1 = *(const float4*)(brp + 4);                               \
        float4 vb2 = *(const float4*)(brp + 8);                               \
        float4 vb3 = *(const float4*)(brp + 12);                              \
        uint4 h, l;                                                           \
        split8(va0, va1, h, l);                                               \
        *(uint4*)((dst) + ar*40 + ac) = h;                                    \
        *(uint4*)((dst) + 2560 + ar*40 + ac) = l;                             \
        split8(vb0, vb1, h, l);                                               \
        *(uint4*)((dst) + 5120 + br2*136 + bc2) = h;                          \
        *(uint4*)((dst) + 9472 + br2*136 + bc2) = l;                          \
        split8(vb2, vb3, h, l);                                               \
        *(uint4*)((dst) + 5120 + br2*136 + bc2 + 8) = h;                      \
        *(uint4*)((dst) + 9472 + br2*136 + bc2 + 8) = l;                      \
    }

#define TC_STORE_NEXT(dst)                                                    \
    {   uint4 h, l;                                                           \
        split8(na0, na1, h, l);                                               \
        *(uint4*)((dst) + ar*40 + ac) = h;                                    \
        *(uint4*)((dst) + 2560 + ar*40 + ac) = l;                             \
        split8(nb0, nb1, h, l);                                               \
        *(uint4*)((dst) + 5120 + br2*136 + bc2) = h;                          \
        *(uint4*)((dst) + 9472 + br2*136 + bc2) = l;                          \
        split8(nb2, nb3, h, l);                                               \
        *(uint4*)((dst) + 5120 + br2*136 + bc2 + 8) = h;                      \
        *(uint4*)((dst) + 9472 + br2*136 + bc2 + 8) = l;                      \
    }

#define TC_COMPUTE(base)                                                      \
    {   _Pragma("unroll")                                                     \
        for (int kf = 0; kf < 2; kf++) {                                      \
            u32 ah[4], al[4];                                                 \
            ldsm4(ah, (base) + a_row_f*40 + kf*16 + a_col_s);                 \
            ldsm4(al, (base) + 2560 + a_row_f*40 + kf*16 + a_col_s);          \
            int rB = kf*16 + b_row_s;                                         \
            _Pragma("unroll")                                                 \
            for (int nf = 0; nf < 8; nf++) {                                  \
                u32 bh0, bh1, bl0, bl1;                                       \
                const __nv_bfloat16* pB = (base) + 5120 + rB*136 + ch + nf*8; \
                ldsm2t(bh0, bh1, pB);                                         \
                ldsm2t(bl0, bl1, pB + 4352);                                  \
                mma_bf16(acc[nf], ah, bh0, bh1);                              \
                mma_bf16(acc[nf], ah, bl0, bl1);                              \
                mma_bf16(acc[nf], al, bh0, bh1);                              \
            }                                                                 \
        }                                                                     \
    }

// ---------------- fused QKV GEMM (tensor cores, proven R12) ----------------
__global__ __launch_bounds__(256) void tc_qkv(const float* __restrict__ A,
                                              const float* __restrict__ wq,
                                              const float* __restrict__ wk,
                                              const float* __restrict__ wv) {
    extern __shared__ __align__(16) char dyn[];
    __nv_bfloat16* sm = (__nv_bfloat16*)dyn;
    int tid = threadIdx.x, w = tid >> 5, lane = tid & 31;
    int bn = blockIdx.x, m0 = blockIdx.y * 64;
    const float* B; float* C; int ldb; int col;
    if (bn < 8)       { B = wq; C = g_q; ldb = 1024; col = bn * 128; }
    else if (bn < 10) { B = wk; C = g_k; ldb = 256;  col = (bn - 8) * 128; }
    else              { B = wv; C = g_v; ldb = 256;  col = (bn - 10) * 128; }

    int ar = tid >> 2, ac = (tid & 3) * 8;
    int br2 = tid >> 3, bc2 = (tid & 7) * 16;
    int rb = (w & 3) * 16, ch = (w >> 2) * 64;
    int a_row_f = rb + (lane & 7) + ((lane >> 3) & 1) * 8;
    int a_col_s = ((lane >> 4) & 1) * 8;
    int b_row_s = lane & 15;

    const float* arp = A + (size_t)(m0 + ar)*DM + ac;
    const float* brp = B + (size_t)br2*ldb + col + bc2;
    float acc[8][4] = {};

    TC_PROLOGUE(sm)
    __syncthreads();
    int buf = 0;
    for (int kt = 1; kt <= 32; kt++) {
        bool more = (kt < 32);
        float4 na0, na1, nb0, nb1, nb2, nb3;
        if (more) {
            int k0 = kt * 32;
            na0 = *(const float4*)(arp + k0);
            na1 = *(const float4*)(arp + k0 + 4);
            const float* bp = brp + (size_t)k0 * ldb;
            nb0 = *(const float4*)bp;  nb1 = *(const float4*)(bp + 4);
            nb2 = *(const float4*)(bp + 8); nb3 = *(const float4*)(bp + 12);
        }
        const __nv_bfloat16* base = sm + buf*13824;
        TC_COMPUTE(base)
        if (more) { __nv_bfloat16* d = sm + (buf^1)*13824; TC_STORE_NEXT(d) }
        __syncthreads();
        buf ^= 1;
    }
    int r0 = m0 + rb + (lane >> 2);
    #pragma unroll
    for (int nf = 0; nf < 8; nf++) {
        int c = col + ch + nf*8 + (lane & 3)*2;
        *(float2*)&C[(size_t)r0*ldb + c]     = make_float2(acc[nf][0], acc[nf][1]);
        *(float2*)&C[(size_t)(r0+8)*ldb + c] = make_float2(acc[nf][2], acc[nf][3]);
    }
}

// ---------------- tensor GEMM + residual (wo; proven R11) ----------------
__global__ __launch_bounds__(256) void tc_gemm_res(const float* __restrict__ A,
                                                   const float* __restrict__ B,
                                                   float* __restrict__ C,
                                                   const float* __restrict__ res,
                                                   int N, int K) {
    extern __shared__ __align__(16) char dyn[];
    __nv_bfloat16* sm = (__nv_bfloat16*)dyn;
    int tid = threadIdx.x, w = tid >> 5, lane = tid & 31;
    int n0 = blockIdx.x * 128, m0 = blockIdx.y * 64;

    int ar = tid >> 2, ac = (tid & 3) * 8;
    int br2 = tid >> 3, bc2 = (tid & 7) * 16;
    int rb = (w & 3) * 16, ch = (w >> 2) * 64;
    int a_row_f = rb + (lane & 7) + ((lane >> 3) & 1) * 8;
    int a_col_s = ((lane >> 4) & 1) * 8;
    int b_row_s = lane & 15;

    const float* arp = A + (size_t)(m0 + ar)*K + ac;
    const float* brp = B + (size_t)br2*N + n0 + bc2;
    float acc[8][4] = {};

    TC_PROLOGUE(sm)
    __syncthreads();
    int buf = 0;
    int nkt = K / 32;
    for (int kt = 1; kt <= nkt; kt++) {
        bool more = (kt < nkt);
        float4 na0, na1, nb0, nb1, nb2, nb3;
        if (more) {
            int k0 = kt * 32;
            na0 = *(const float4*)(arp + k0);
            na1 = *(const float4*)(arp + k0 + 4);
            const float* bp = brp + (size_t)k0 * N;
            nb0 = *(const float4*)bp;  nb1 = *(const float4*)(bp + 4);
            nb2 = *(const float4*)(bp + 8); nb3 = *(const float4*)(bp + 12);
        }
        const __nv_bfloat16* base = sm + buf*13824;
        TC_COMPUTE(base)
        if (more) { __nv_bfloat16* d = sm + (buf^1)*13824; TC_STORE_NEXT(d) }
        __syncthreads();
        buf ^= 1;
    }
    int r0 = m0 + rb + (lane >> 2);
    #pragma unroll
    for (int nf = 0; nf < 8; nf++) {
        int c = n0 + ch + nf*8 + (lane & 3)*2;
        float2 v0 = make_float2(acc[nf][0], acc[nf][1]);
        float2 v1 = make_float2(acc[nf][2], acc[nf][3]);
        if (res) {
            float2 q0 = *(const float2*)&res[(size_t)r0*N + c];
            float2 q1 = *(const float2*)&res[(size_t)(r0+8)*N + c];
            v0.x += q0.x; v0.y += q0.y; v1.x += q1.x; v1.y += q1.y;
        }
        *(float2*)&C[(size_t)r0*N + c]     = v0;
        *(float2*)&C[(size_t)(r0+8)*N + c] = v1;
    }
}

// ============ FFN stage A (tensor cores, proven) ============
#define FA_BYTES (2*14336*2 + 512)
__global__ __launch_bounds__(256) void ffn_a(const float* __restrict__ w1e,
                                             const float* __restrict__ w3e,
                                             const float* __restrict__ sw1,
                                             const float* __restrict__ sw3) {
    extern __shared__ __align__(16) char dyn[];
    __nv_bfloat16* sm = (__nv_bfloat16*)dyn;
    int* s_arow = (int*)(dyn + 2*14336*2);
    int* s_orow = s_arow + 64;

    int tid = threadIdx.x, w = tid >> 5, lane = tid & 31;
    int bid = blockIdx.x;

    int ar = tid >> 2, ac = (tid & 3) * 8;
    int bmat = tid >> 7, br = (tid & 127) >> 2, bc = (tid & 3) * 16;
    int rb = (w & 3) * 16, ch = w >> 2;

    bool gather = (bid < NE*8);
    const float* B1g; const float* B3g;
    float* outb; const float* pw; int n0; int mTot; int mshb = 0;
    const int* lst = nullptr; int nrows = 0;

    if (gather) {
        int e = bid >> 3; n0 = (bid & 7) * 64;
        nrows = g_cnt[e];
        if (nrows == 0) return;
        lst = &g_list[e*SS];
        B1g = w1e + (size_t)e*DM*HE + n0;
        B3g = w3e + (size_t)e*DM*HE + n0;
        outb = g_gbuf; pw = g_pairw; mTot = nrows;
    } else {
        int b = bid - NE*8;
        n0 = (b & 7) * 64; mshb = (b >> 3) * 64;
        B1g = sw1 + n0; B3g = sw3 + n0;
        outb = g_a1; pw = nullptr; mTot = 64;
    }
    const float* Bgm = bmat ? B3g : B1g;
    int bhio = 5120 + bmat*4608, blio = bhio + 2304;

    int a_row_f = rb + (lane & 7) + ((lane >> 3) & 1) * 8;
    int a_col_s = ((lane >> 4) & 1) * 8;
    int b_row_s = lane & 15;
    int cB = ch * 32;

    for (int m0 = 0; m0 < mTot; m0 += 64) {
        __syncthreads();
        if (tid < 64) {
            int arow, orow;
            if (gather) {
                int p = (m0 + tid < nrows) ? lst[m0 + tid] : -1;
                arow = (p < 0) ? 0 : p / TOPK; orow = p;
            } else { arow = mshb + tid; orow = mshb + tid; }
            s_arow[tid] = arow; s_orow[tid] = orow;
        }
        __syncthreads();
        const float* arp = g_z + (size_t)s_arow[ar]*DM + ac;
        const float* brp = Bgm + (size_t)br*HE + bc;

        float acc1[4][4] = {}; float acc3[4][4] = {};

        {
            float4 va0 = *(const float4*)arp;
            float4 va1 = *(const float4*)(arp + 4);
            float4 vb0 = *(const float4*)brp;
            float4 vb1 = *(const float4*)(brp + 4);
            float4 vb2 = *(const float4*)(brp + 8);
            float4 vb3 = *(const float4*)(brp + 12);
            uint4 h, l;
            split8(va0, va1, h, l);
            *(uint4*)(sm + ar*40 + ac) = h;
            *(uint4*)(sm + 2560 + ar*40 + ac) = l;
            split8(vb0, vb1, h, l);
            *(uint4*)(sm + bhio + br*72 + bc) = h;
            *(uint4*)(sm + blio + br*72 + bc) = l;
            split8(vb2, vb3, h, l);
            *(uint4*)(sm + bhio + br*72 + bc + 8) = h;
            *(uint4*)(sm + blio + br*72 + bc + 8) = l;
        }
        __syncthreads();
        int buf = 0;
        for (int kt = 1; kt <= 32; kt++) {
            bool more = (kt < 32);
            float4 na0, na1, nb0, nb1, nb2, nb3;
            if (more) {
                int k0 = kt * 32;
                na0 = *(const float4*)(arp + k0);
                na1 = *(const float4*)(arp + k0 + 4);
                const float* bp = brp + (size_t)k0 * HE;
                nb0 = *(const float4*)bp;  nb1 = *(const float4*)(bp + 4);
                nb2 = *(const float4*)(bp + 8); nb3 = *(const float4*)(bp + 12);
            }
            {
                const __nv_bfloat16* base = sm + buf*14336;
                #pragma unroll
                for (int kf = 0; kf < 2; kf++) {
                    u32 ah[4], al[4];
                    ldsm4(ah, base + a_row_f*40 + kf*16 + a_col_s);
                    ldsm4(al, base + 2560 + a_row_f*40 + kf*16 + a_col_s);
                    int rB = kf*16 + b_row_s;
                    #pragma unroll
                    for (int nf = 0; nf < 4; nf++) {
                        u32 bh0, bh1, bl0, bl1;
                        const __nv_bfloat16* pB1 = base + 5120 + rB*72 + cB + nf*8;
                        ldsm2t(bh0, bh1, pB1);
                        ldsm2t(bl0, bl1, pB1 + 2304);
                        mma_bf16(acc1[nf], ah, bh0, bh1);
                        mma_bf16(acc1[nf], ah, bl0, bl1);
                        mma_bf16(acc1[nf], al, bh0, bh1);
                        const __nv_bfloat16* pB3 = pB1 + 4608;
                        ldsm2t(bh0, bh1, pB3);
                        ldsm2t(bl0, bl1, pB3 + 2304);
                        mma_bf16(acc3[nf], ah, bh0, bh1);
                        mma_bf16(acc3[nf], ah, bl0, bl1);
                        mma_bf16(acc3[nf], al, bh0, bh1);
                    }
                }
            }
            if (more) {
                __nv_bfloat16* d = sm + (buf^1)*14336;
                uint4 h, l;
                split8(na0, na1, h, l);
                *(uint4*)(d + ar*40 + ac) = h;
                *(uint4*)(d + 2560 + ar*40 + ac) = l;
                split8(nb0, nb1, h, l);
                *(uint4*)(d + bhio + br*72 + bc) = h;
                *(uint4*)(d + blio + br*72 + bc) = l;
                split8(nb2, nb3, h, l);
                *(uint4*)(d + bhio + br*72 + bc + 8) = h;
                *(uint4*)(d + blio + br*72 + bc + 8) = l;
            }
            __syncthreads();
            buf ^= 1;
        }
        int r0 = rb + (lane >> 2);
        int o0 = s_orow[r0], o1 = s_orow[r0 + 8];
        float wt0 = pw ? (o0 >= 0 ? pw[o0] : 0.f) : 1.f;
        float wt1 = pw ? (o1 >= 0 ? pw[o1] : 0.f) : 1.f;
        #pragma unroll
        for (int nf = 0; nf < 4; nf++) {
            int c = n0 + cB + nf*8 + (lane & 3)*2;
            if (o0 >= 0) {
                float x0 = acc1[nf][0], x1 = acc1[nf][1];
                float2 o;
                o.x = (x0/(1.f+__expf(-x0))) * acc3[nf][0] * wt0;
                o.y = (x1/(1.f+__expf(-x1))) * acc3[nf][1] * wt0;
                *(float2*)&outb[(size_t)o0*HE + c] = o;
            }
            if (o1 >= 0) {
                float x2 = acc1[nf][2], x3 = acc1[nf][3];
                float2 o;
                o.x = (x2/(1.f+__expf(-x2))) * acc3[nf][2] * wt1;
                o.y = (x3/(1.f+__expf(-x3))) * acc3[nf][3] * wt1;
                *(float2*)&outb[(size_t)o1*HE + c] = o;
            }
        }
    }
}

// ============ FFN stage B (tensor cores, proven) ============
__global__ __launch_bounds__(256) void ffn_b(const float* __restrict__ w2e,
                                             const float* __restrict__ sw2) {
    extern __shared__ __align__(16) char dyn[];
    __nv_bfloat16* sm = (__nv_bfloat16*)dyn;
    int* s_arow = (int*)(dyn + 2*13824*2);
    int* s_orow = s_arow + 64;

    int tid = threadIdx.x, w = tid >> 5, lane = tid & 31;
    int bid = blockIdx.x;

    int ar = tid >> 2, ac = (tid & 3) * 8;
    int br2 = tid >> 3, bc2 = (tid & 7) * 16;
    int rb = (w & 3) * 16, ch = (w >> 2) * 64;

    bool gather = (bid < NE*8);
    const float* Ag; const float* Bg;
    float* outb; int n0; int mTot; int mshb = 0;
    const int* lst = nullptr; int nrows = 0;

    if (gather) {
        int e = bid >> 3; n0 = (bid & 7) * 128;
        nrows = g_cnt[e];
        if (nrows == 0) return;
        lst = &g_list[e*SS];
        Ag = g_gbuf;
        Bg = w2e + (size_t)e*HE*DM + n0;
        outb = g_g2; mTot = nrows;
    } else {
        int b = bid - NE*8;
        n0 = (b & 7) * 128; mshb = (b >> 3) * 64;
        Ag = g_a1; Bg = sw2 + n0;
        outb = g_sh; mTot = 64;
    }

    int a_row_f = rb + (lane & 7) + ((lane >> 3) & 1) * 8;
    int a_col_s = ((lane >> 4) & 1) * 8;
    int b_row_s = lane & 15;

    for (int m0 = 0; m0 < mTot; m0 += 64) {
        __syncthreads();
        if (tid < 64) {
            int arow, orow;
            if (gather) {
                int p = (m0 + tid < nrows) ? lst[m0 + tid] : -1;
                arow = (p < 0) ? 0 : p; orow = p;
            } else { arow = mshb + tid; orow = mshb + tid; }
            s_arow[tid] = arow; s_orow[tid] = orow;
        }
        __syncthreads();
        const float* arp = Ag + (size_t)s_arow[ar]*HE + ac;
        const float* brp = Bg + (size_t)br2*DM + bc2;

        float acc[8][4] = {};

        TC_PROLOGUE(sm)
        __syncthreads();
        int buf = 0;
        for (int kt = 1; kt <= 16; kt++) {
            bool more = (kt < 16);
            float4 na0, na1, nb0, nb1, nb2, nb3;
            if (more) {
                int k0 = kt * 32;
                na0 = *(const float4*)(arp + k0);
                na1 = *(const float4*)(arp + k0 + 4);
                const float* bp = brp + (size_t)k0 * DM;
                nb0 = *(const float4*)bp;  nb1 = *(const float4*)(bp + 4);
                nb2 = *(const float4*)(bp + 8); nb3 = *(const float4*)(bp + 12);
            }
            const __nv_bfloat16* base = sm + buf*13824;
            TC_COMPUTE(base)
            if (more) { __nv_bfloat16* d = sm + (buf^1)*13824; TC_STORE_NEXT(d) }
            __syncthreads();
            buf ^= 1;
        }
        int r0 = rb + (lane >> 2);
        int o0 = s_orow[r0], o1 = s_orow[r0 + 8];
        #pragma unroll
        for (int nf = 0; nf < 8; nf++) {
            int c = n0 + ch + nf*8 + (lane & 3)*2;
            if (o0 >= 0)
                *(float2*)&outb[(size_t)o0*DM + c] = make_float2(acc[nf][0], acc[nf][1]);
            if (o1 >= 0)
                *(float2*)&outb[(size_t)o1*DM + c] = make_float2(acc[nf][2], acc[nf][3]);
        }
    }
}

// ---------------- q/k rmsnorm + rope ----------------
__global__ __launch_bounds__(256) void qknorm_rope(const float* __restrict__ qw,
                                                   const float* __restrict__ kw,
                                                   const float* __restrict__ cosb,
                                                   const float* __restrict__ sinb) {
    int gw = (blockIdx.x * blockDim.x + threadIdx.x) >> 5;
    int lane = threadIdx.x & 31;
    if (gw >= SS * (NHQ + NKVH)) return;
    int t = gw / (NHQ + NKVH);
    int hh = gw % (NHQ + NKVH);
    float* base;
    const float* w;
    if (hh < NHQ) { base = &g_q[(size_t)t*(NHQ*HDIM) + hh*HDIM]; w = qw; }
    else          { base = &g_k[(size_t)t*(NKVH*HDIM) + (hh-NHQ)*HDIM]; w = kw; }
    int d0 = lane * 2;
    float v0 = base[d0], v1 = base[d0+1];
    float ss = v0*v0 + v1*v1;
    #pragma unroll
    for (int off = 16; off; off >>= 1) ss += __shfl_xor_sync(0xffffffffu, ss, off);
    float r = rsqrtf(ss * (1.0f/HDIM) + 1e-5f);
    float n0 = v0 * r * w[d0];
    float n1 = v1 * r * w[d0+1];
    float c = cosb[t*(HDIM/2) + lane];
    float s = sinb[t*(HDIM/2) + lane];
    base[d0]   = n0*c - n1*s;
    base[d0+1] = n0*s + n1*c;
}

// ---------------- flash attention (tensor cores, split-bf16) ----------------
// 128 threads / 4 warps; warp w owns q-rows rb..rb+15 of a 64-row tile, full 64-kv width.
// smem bf16: Qhi@0, Qlo@4608, Khi@9216, Klo@13824, Vhi@18432, Vlo@23040 (stride 72).
#define TCF_SMEM (27648*2)
__global__ __launch_bounds__(128) void flash_tc() {
    extern __shared__ __align__(16) char dyn[];
    __nv_bfloat16* sm = (__nv_bfloat16*)dyn;
    __nv_bfloat16* Qh = sm;
    __nv_bfloat16* Kh = sm + 9216;
    __nv_bfloat16* Vh = sm + 18432;
    int tid = threadIdx.x, w = tid >> 5, lane = tid & 31;
    int qt = (int)gridDim.x - 1 - (int)blockIdx.x;
    int h = blockIdx.y, kvh = h >> 2;
    int q0 = qt * 64;
    int rb = w * 16;

    int lrow = tid >> 1, lcb = (tid & 1) * 32;

    // load + split Q tile
    {
        const float* src = &g_q[(size_t)(q0 + lrow)*(NHQ*HDIM) + h*HDIM + lcb];
        #pragma unroll
        for (int c = 0; c < 4; c++) {
            float4 v0 = *(const float4*)(src + c*8);
            float4 v1 = *(const float4*)(src + c*8 + 4);
            uint4 hi, lo; split8(v0, v1, hi, lo);
            *(uint4*)(Qh + lrow*72 + lcb + c*8) = hi;
            *(uint4*)(Qh + 4608 + lrow*72 + lcb + c*8) = lo;
        }
    }

    int a_row_f = rb + (lane & 7) + ((lane >> 3) & 1) * 8;
    int a_col_s = ((lane >> 4) & 1) * 8;
    int kq_row = lane & 7;
    int kq_off = ((lane >> 3) & 1) * 8;
    int v_row = lane & 15;

    float Oacc[8][4] = {};
    float m_i[2] = {-1e30f, -1e30f};
    float l_i[2] = {0.f, 0.f};

    for (int kt = 0; kt <= qt; kt++) {
        int k0 = kt * 64;
        __syncthreads();
        {
            const float* ks = &g_k[(size_t)(k0 + lrow)*(NKVH*HDIM) + kvh*HDIM + lcb];
            const float* vs = &g_v[(size_t)(k0 + lrow)*(NKVH*HDIM) + kvh*HDIM + lcb];
            #pragma unroll
            for (int c = 0; c < 4; c++) {
                float4 v0 = *(const float4*)(ks + c*8);
                float4 v1 = *(const float4*)(ks + c*8 + 4);
                uint4 hi, lo; split8(v0, v1, hi, lo);
                *(uint4*)(Kh + lrow*72 + lcb + c*8) = hi;
                *(uint4*)(Kh + 4608 + lrow*72 + lcb + c*8) = lo;
                v0 = *(const float4*)(vs + c*8);
                v1 = *(const float4*)(vs + c*8 + 4);
                split8(v0, v1, hi, lo);
                *(uint4*)(Vh + lrow*72 + lcb + c*8) = hi;
                *(uint4*)(Vh + 4608 + lrow*72 + lcb + c*8) = lo;
            }
        }
        __syncthreads();

        // S = Q K^T (3-term split)
        float S[8][4] = {};
        #pragma unroll
        for (int kd = 0; kd < 4; kd++) {
            u32 ah[4], al[4];
            ldsm4(ah, Qh + a_row_f*72 + kd*16 + a_col_s);
            ldsm4(al, Qh + 4608 + a_row_f*72 + kd*16 + a_col_s);
            #pragma unroll
            for (int nt = 0; nt < 8; nt++) {
                const __nv_bfloat16* pk = Kh + (nt*8 + kq_row)*72 + kd*16 + kq_off;
                u32 bh0, bh1, bl0, bl1;
                ldsm2(bh0, bh1, pk);
                ldsm2(bl0, bl1, pk + 4608);
                mma_bf16(S[nt], ah, bh0, bh1);
                mma_bf16(S[nt], ah, bl0, bl1);
                mma_bf16(S[nt], al, bh0, bh1);
            }
        }

        // online softmax (rows rA = lane>>2, rB = +8)
        const float sc = 0.125f;
        int colb = (lane & 3) * 2;
        int rAg = q0 + rb + (lane >> 2);
        int rBg = rAg + 8;
        if (kt == qt) {
            #pragma unroll
            for (int nt = 0; nt < 8; nt++) {
                int j0 = k0 + nt*8 + colb, j1 = j0 + 1;
                S[nt][0] = (j0 <= rAg) ? S[nt][0]*sc : -1e30f;
                S[nt][1] = (j1 <= rAg) ? S[nt][1]*sc : -1e30f;
                S[nt][2] = (j0 <= rBg) ? S[nt][2]*sc : -1e30f;
                S[nt][3] = (j1 <= rBg) ? S[nt][3]*sc : -1e30f;
            }
        } else {
            #pragma unroll
            for (int nt = 0; nt < 8; nt++) {
                S[nt][0] *= sc; S[nt][1] *= sc; S[nt][2] *= sc; S[nt][3] *= sc;
            }
        }
        float mxA = -1e30f, mxB = -1e30f;
        #pragma unroll
        for (int nt = 0; nt < 8; nt++) {
            mxA = fmaxf(mxA, fmaxf(S[nt][0], S[nt][1]));
            mxB = fmaxf(mxB, fmaxf(S[nt][2], S[nt][3]));
        }
        mxA = fmaxf(mxA, __shfl_xor_sync(0xffffffffu, mxA, 1));
        mxA = fmaxf(mxA, __shfl_xor_sync(0xffffffffu, mxA, 2));
        mxB = fmaxf(mxB, __shfl_xor_sync(0xffffffffu, mxB, 1));
        mxB = fmaxf(mxB, __shfl_xor_sync(0xffffffffu, mxB, 2));
        float mnA = fmaxf(m_i[0], mxA), mnB = fmaxf(m_i[1], mxB);
        float scA = __expf(m_i[0] - mnA), scB = __expf(m_i[1] - mnB);
        float rsA = 0.f, rsB = 0.f;
        #pragma unroll
        for (int nt = 0; nt < 8; nt++) {
            S[nt][0] = __expf(S[nt][0] - mnA); S[nt][1] = __expf(S[nt][1] - mnA);
            S[nt][2] = __expf(S[nt][2] - mnB); S[nt][3] = __expf(S[nt][3] - mnB);
            rsA += S[nt][0] + S[nt][1];
            rsB += S[nt][2] + S[nt][3];
        }
        rsA += __shfl_xor_sync(0xffffffffu, rsA, 1);
        rsA += __shfl_xor_sync(0xffffffffu, rsA, 2);
        rsB += __shfl_xor_sync(0xffffffffu, rsB, 1);
        rsB += __shfl_xor_sync(0xffffffffu, rsB, 2);
        l_i[0] = l_i[0]*scA + rsA; l_i[1] = l_i[1]*scB + rsB;
        m_i[0] = mnA; m_i[1] = mnB;
        #pragma unroll
        for (int nt = 0; nt < 8; nt++) {
            Oacc[nt][0] *= scA; Oacc[nt][1] *= scA;
            Oacc[nt][2] *= scB; Oacc[nt][3] *= scB;
        }

        // O += P V (P in registers, 3-term split)
        #pragma unroll
        for (int kf = 0; kf < 4; kf++) {
            u32 ph[4], pl[4];
            ph[0] = pkbf2(S[2*kf][0],   S[2*kf][1]);
            ph[1] = pkbf2(S[2*kf][2],   S[2*kf][3]);
            ph[2] = pkbf2(S[2*kf+1][0], S[2*kf+1][1]);
            ph[3] = pkbf2(S[2*kf+1][2], S[2*kf+1][3]);
            pl[0] = pkres2(S[2*kf][0],   S[2*kf][1]);
            pl[1] = pkres2(S[2*kf][2],   S[2*kf][3]);
            pl[2] = pkres2(S[2*kf+1][0], S[2*kf+1][1]);
            pl[3] = pkres2(S[2*kf+1][2], S[2*kf+1][3]);
            #pragma unroll
            for (int nt = 0; nt < 8; nt++) {
                const __nv_bfloat16* pv = Vh + (kf*16 + v_row)*72 + nt*8;
                u32 vh0, vh1, vl0, vl1;
                ldsm2t(vh0, vh1, pv);
                ldsm2t(vl0, vl1, pv + 4608);
                mma_bf16(Oacc[nt], ph, vh0, vh1);
                mma_bf16(Oacc[nt], ph, vl0, vl1);
                mma_bf16(Oacc[nt], pl, vh0, vh1);
            }
        }
    }
    float invA = 1.f / l_i[0], invB = 1.f / l_i[1];
    int rAg = q0 + rb + (lane >> 2);
    float* outA = &g_attn[(size_t)rAg*(NHQ*HDIM) + h*HDIM];
    float* outB = outA + 8*(NHQ*HDIM);
    #pragma unroll
    for (int nt = 0; nt < 8; nt++) {
        int c = nt*8 + (lane & 3)*2;
        *(float2*)&outA[c] = make_float2(Oacc[nt][0]*invA, Oacc[nt][1]*invA);
        *(float2*)&outB[c] = make_float2(Oacc[nt][2]*invB, Oacc[nt][3]*invB);
    }
}

// ---------------- gate GEMM (N=64) ----------------
__global__ __launch_bounds__(256) void gemm64(const float* __restrict__ A,
                                              const float* __restrict__ B,
                                              float* __restrict__ C,
                                              int M, int N, int K) {
    __shared__ float As[16][64];
    __shared__ float Bs[16][64];
    int tid = threadIdx.x;
    int tx = tid & 15, ty = tid >> 4;
    int m0 = blockIdx.y * 64, n0 = blockIdx.x * 64;
    int ar = tid >> 2;
    int ac = (tid & 3) * 4;
    int br = tid >> 4;
    int bc = (tid & 15) * 4;
    float acc[4][4] = {};
    for (int k0 = 0; k0 < K; k0 += 16) {
        float4 av = *(const float4*)&A[(size_t)(m0 + ar)*K + k0 + ac];
        float4 bv = *(const float4*)&B[(size_t)(k0 + br)*N + n0 + bc];
        As[ac+0][ar] = av.x; As[ac+1][ar] = av.y;
        As[ac+2][ar] = av.z; As[ac+3][ar] = av.w;
        *(float4*)&Bs[br][bc] = bv;
        __syncthreads();
        #pragma unroll
        for (int k = 0; k < 16; k++) {
            float4 a = *(const float4*)&As[k][ty*4];
            float4 b = *(const float4*)&Bs[k][tx*4];
            float aa[4] = {a.x,a.y,a.z,a.w};
            float bb[4] = {b.x,b.y,b.z,b.w};
            #pragma unroll
            for (int i = 0; i < 4; i++)
                #pragma unroll
                for (int j = 0; j < 4; j++)
                    acc[i][j] += aa[i]*bb[j];
        }
        __syncthreads();
    }
    #pragma unroll
    for (int i = 0; i < 4; i++) {
        float4 ov = make_float4(acc[i][0],acc[i][1],acc[i][2],acc[i][3]);
        *(float4*)&C[(size_t)(m0 + ty*4 + i)*N + n0 + tx*4] = ov;
    }
}

// ---------------- routing ----------------
__global__ void zero_cnt_k() { if (threadIdx.x < NE) g_cnt[threadIdx.x] = 0; }

__global__ void route_k() {
    int t = blockIdx.x;
    int lane = threadIdx.x;
    float v0 = g_logits[t*NE + lane];
    float v1 = g_logits[t*NE + 32 + lane];
    float selv[TOPK]; int seli[TOPK];
    #pragma unroll
    for (int it = 0; it < TOPK; it++) {
        float best = (v0 >= v1) ? v0 : v1;
        int   bi   = (v0 >= v1) ? lane : lane + 32;
        #pragma unroll
        for (int off = 16; off; off >>= 1) {
            float ov = __shfl_xor_sync(0xffffffffu, best, off);
            int   oi = __shfl_xor_sync(0xffffffffu, bi, off);
            if (ov > best || (ov == best && oi < bi)) { best = ov; bi = oi; }
        }
        selv[it] = best; seli[it] = bi;
        if (bi == lane)      v0 = -1e30f;
        if (bi == lane + 32) v1 = -1e30f;
    }
    if (lane < TOPK) {
        float sum = 0.f;
        #pragma unroll
        for (int i = 0; i < TOPK; i++) sum += __expf(selv[i] - selv[0]);
        float w = __expf(selv[lane] - selv[0]) / sum;
        int e = seli[lane];
        int pos = atomicAdd(&g_cnt[e], 1);
        g_list[e*SS + pos] = t*TOPK + lane;
        g_pairw[t*TOPK + lane] = w;
    }
}

// ---------------- final ----------------
__global__ __launch_bounds__(256) void final_k(float* __restrict__ out) {
    int t = blockIdx.x;
    int c = threadIdx.x * 4;
    float4 a = *(const float4*)&g_h[(size_t)t*DM + c];
    float4 b = *(const float4*)&g_sh[(size_t)t*DM + c];
    a.x += b.x; a.y += b.y; a.z += b.z; a.w += b.w;
    #pragma unroll
    for (int kk = 0; kk < TOPK; kk++) {
        float4 gv = *(const float4*)&g_g2[(size_t)(t*TOPK+kk)*DM + c];
        a.x += gv.x; a.y += gv.y; a.z += gv.z; a.w += gv.w;
    }
    *(float4*)&out[(size_t)t*DM + c] = a;
}

// ---------------- host ----------------
extern "C" void kernel_launch(void* const* d_in, const int* in_sizes, int n_in,
                              void* d_out, int out_size) {
    const float* x   = (const float*)d_in[0];
    const float* fc  = (const float*)d_in[1];
    const float* fs  = (const float*)d_in[2];
    const float* anw = (const float*)d_in[3];
    const float* fnw = (const float*)d_in[4];
    const float* wq  = (const float*)d_in[5];
    const float* wk  = (const float*)d_in[6];
    const float* wv  = (const float*)d_in[7];
    const float* wo  = (const float*)d_in[8];
    const float* qnw = (const float*)d_in[9];
    const float* knw = (const float*)d_in[10];
    const float* gw  = (const float*)d_in[11];
    const float* w1e = (const float*)d_in[12];
    const float* w3e = (const float*)d_in[13];
    const float* w2e = (const float*)d_in[14];
    const float* sw1 = (const float*)d_in[15];
    const float* sw3 = (const float*)d_in[16];
    const float* sw2 = (const float*)d_in[17];
    float* out = (float*)d_out;

    float *hx,*attn,*h,*z,*logits;
    cudaGetSymbolAddress((void**)&hx, g_hx);
    cudaGetSymbolAddress((void**)&attn, g_attn);
    cudaGetSymbolAddress((void**)&h,  g_h);
    cudaGetSymbolAddress((void**)&z,  g_z);
    cudaGetSymbolAddress((void**)&logits, g_logits);

    cudaFuncSetAttribute(flash_tc, cudaFuncAttributeMaxDynamicSharedMemorySize, TCF_SMEM);
    cudaFuncSetAttribute(ffn_a, cudaFuncAttributeMaxDynamicSharedMemorySize, FA_BYTES);
    cudaFuncSetAttribute(ffn_b, cudaFuncAttributeMaxDynamicSharedMemorySize, FB_BYTES);
    cudaFuncSetAttribute(tc_qkv, cudaFuncAttributeMaxDynamicSharedMemorySize, FB_BYTES);
    cudaFuncSetAttribute(tc_gemm_res, cudaFuncAttributeMaxDynamicSharedMemorySize, FB_BYTES);

    // attention branch
    rmsnorm_k<<<SS, 256>>>(x, anw, hx);
    tc_qkv<<<dim3(12, 16), 256, FB_BYTES>>>(hx, wq, wk, wv);
    qknorm_rope<<<(SS*(NHQ+NKVH)*32)/256, 256>>>(qnw, knw, fc, fs);
    flash_tc<<<dim3(16,16), 128, TCF_SMEM>>>();
    tc_gemm_res<<<dim3(8, 16), 256, FB_BYTES>>>(attn, wo, h, x, 1024, 1024);  // h = attn@wo + x

    // ffn branch
    rmsnorm_k<<<SS, 256>>>(h, fnw, z);
    gemm64<<<dim3(1, 16), 256>>>(z, gw, logits, SS, NE, DM);
    zero_cnt_k<<<1, 64>>>();
    route_k<<<SS, 32>>>();
    ffn_a<<<NE*8 + 128, 256, FA_BYTES>>>(w1e, w3e, sw1, sw3);
    ffn_b<<<NE*8 + 128, 256, FB_BYTES>>>(w2e, sw2);

    final_k<<<SS, 256>>>(out);
}

// round 15
// speedup vs baseline: 3.3849x; 1.0369x over previous
#include <cuda_runtime.h>
#include <cuda_bf16.h>
#include <math.h>

#define SS 1024
#define DM 1024
#define NHQ 16
#define NKVH 4
#define HDIM 64
#define NE 64
#define TOPK 6
#define HE 512
#define NPAIR (SS*TOPK)

typedef unsigned long long u64;
typedef unsigned int u32;

// ---------------- tensor-core helpers (bf16 mma + split) ----------------
__device__ __forceinline__ void mma_bf16(float* d, const u32* a, u32 b0, u32 b1) {
    asm volatile("mma.sync.aligned.m16n8k16.row.col.f32.bf16.bf16.f32 "
        "{%0,%1,%2,%3},{%4,%5,%6,%7},{%8,%9},{%0,%1,%2,%3};"
        : "+f"(d[0]),"+f"(d[1]),"+f"(d[2]),"+f"(d[3])
        : "r"(a[0]),"r"(a[1]),"r"(a[2]),"r"(a[3]), "r"(b0),"r"(b1));
}
__device__ __forceinline__ void ldsm4(u32* r, const __nv_bfloat16* p) {
    u32 a = (u32)__cvta_generic_to_shared(p);
    asm volatile("ldmatrix.sync.aligned.m8n8.x4.shared.b16 {%0,%1,%2,%3},[%4];"
        : "=r"(r[0]),"=r"(r[1]),"=r"(r[2]),"=r"(r[3]) : "r"(a));
}
__device__ __forceinline__ void ldsm2(u32 &r0, u32 &r1, const __nv_bfloat16* p) {
    u32 a = (u32)__cvta_generic_to_shared(p);
    asm volatile("ldmatrix.sync.aligned.m8n8.x2.shared.b16 {%0,%1},[%2];"
        : "=r"(r0),"=r"(r1) : "r"(a));
}
__device__ __forceinline__ void ldsm2t(u32 &r0, u32 &r1, const __nv_bfloat16* p) {
    u32 a = (u32)__cvta_generic_to_shared(p);
    asm volatile("ldmatrix.sync.aligned.m8n8.x2.trans.shared.b16 {%0,%1},[%2];"
        : "=r"(r0),"=r"(r1) : "r"(a));
}
__device__ __forceinline__ u32 pkbf2(float x, float y) {
    __nv_bfloat162 h = __floats2bfloat162_rn(x, y);
    return *reinterpret_cast<u32*>(&h);
}
__device__ __forceinline__ u32 pkres2(float x, float y) {
    float rx = x - __bfloat162float(__float2bfloat16(x));
    float ry = y - __bfloat162float(__float2bfloat16(y));
    return pkbf2(rx, ry);
}
__device__ __forceinline__ void split8(float4 v0, float4 v1, uint4 &hi, uint4 &lo) {
    float f[8] = {v0.x,v0.y,v0.z,v0.w,v1.x,v1.y,v1.z,v1.w};
    float r[8];
    #pragma unroll
    for (int i = 0; i < 8; i++) r[i] = f[i] - __bfloat162float(__float2bfloat16(f[i]));
    hi = make_uint4(pkbf2(f[0],f[1]),pkbf2(f[2],f[3]),pkbf2(f[4],f[5]),pkbf2(f[6],f[7]));
    lo = make_uint4(pkbf2(r[0],r[1]),pkbf2(r[2],r[3]),pkbf2(r[4],r[5]),pkbf2(r[6],r[7]));
}
__device__ __forceinline__ void cpa16(__nv_bfloat16* s, const __nv_bfloat16* g) {
    u32 a = (u32)__cvta_generic_to_shared(s);
    asm volatile("cp.async.ca.shared.global [%0], [%1], 16;" :: "r"(a), "l"(g));
}
#define CP_COMMIT() asm volatile("cp.async.commit_group;" ::: "memory")
#define CP_WAIT0()  asm volatile("cp.async.wait_group 0;" ::: "memory")

// ---------------- scratch ----------------
__device__ float g_hx[SS*DM];
__device__ float g_q[SS*NHQ*HDIM];
__device__ float g_k[SS*NKVH*HDIM];
__device__ float g_v[SS*NKVH*HDIM];
__device__ __nv_bfloat16 g_qh[SS*NHQ*HDIM];
__device__ __nv_bfloat16 g_ql[SS*NHQ*HDIM];
__device__ __nv_bfloat16 g_kh[SS*NKVH*HDIM];
__device__ __nv_bfloat16 g_kl[SS*NKVH*HDIM];
__device__ __nv_bfloat16 g_vh[SS*NKVH*HDIM];
__device__ __nv_bfloat16 g_vl[SS*NKVH*HDIM];
__device__ float g_attn[SS*NHQ*HDIM];
__device__ float g_h[SS*DM];
__device__ float g_z[SS*DM];
__device__ float g_logits[SS*NE];
__device__ float g_pairw[NPAIR];
__device__ int   g_cnt[NE];
__device__ int   g_list[NE*SS];
__device__ float g_gbuf[(size_t)NPAIR*HE];
__device__ float g_g2[(size_t)NPAIR*DM];
__device__ float g_a1[SS*HE];
__device__ float g_sh[SS*DM];

// ---------------- rmsnorm ----------------
__global__ __launch_bounds__(256) void rmsnorm_k(const float* __restrict__ x,
                                                 const float* __restrict__ w,
                                                 float* __restrict__ out) {
    int t = blockIdx.x;
    int tid = threadIdx.x;
    float4 xv = *(const float4*)&x[(size_t)t*DM + tid*4];
    float ss = xv.x*xv.x + xv.y*xv.y + xv.z*xv.z + xv.w*xv.w;
    #pragma unroll
    for (int off = 16; off; off >>= 1) ss += __shfl_xor_sync(0xffffffffu, ss, off);
    __shared__ float red[8];
    if ((tid & 31) == 0) red[tid >> 5] = ss;
    __syncthreads();
    float tot = 0.f;
    #pragma unroll
    for (int i = 0; i < 8; i++) tot += red[i];
    float r = rsqrtf(tot * (1.0f/DM) + 1e-5f);
    float4 wv = *(const float4*)&w[tid*4];
    float4 ov;
    ov.x = wv.x * (xv.x * r); ov.y = wv.y * (xv.y * r);
    ov.z = wv.z * (xv.z * r); ov.w = wv.w * (xv.w * r);
    *(float4*)&out[(size_t)t*DM + tid*4] = ov;
}

// ============ split-bf16 tensor GEMM core macros ============
#define FB_BYTES (2*13824*2 + 512)

#define TC_PROLOGUE(dst)                                                      \
    {   float4 va0 = *(const float4*)arp;                                     \
        float4 va1 = *(const float4*)(arp + 4);                               \
        float4 vb0 = *(const float4*)brp;                                     \
        float4 vb1 = *(const float4*)(brp + 4);                               \
        float4 vb2 = *(const float4*)(brp + 8);                               \
        float4 vb3 = *(const float4*)(brp + 12);                              \
        uint4 h, l;                                                           \
        split8(va0, va1, h, l);                                               \
        *(uint4*)((dst) + ar*40 + ac) = h;                                    \
        *(uint4*)((dst) + 2560 + ar*40 + ac) = l;                             \
        split8(vb0, vb1, h, l);                                               \
        *(uint4*)((dst) + 5120 + br2*136 + bc2) = h;                          \
        *(uint4*)((dst) + 9472 + br2*136 + bc2) = l;                          \
        split8(vb2, vb3, h, l);                                               \
        *(uint4*)((dst) + 5120 + br2*136 + bc2 + 8) = h;                      \
        *(uint4*)((dst) + 9472 + br2*136 + bc2 + 8) = l;                      \
    }

#define TC_STORE_NEXT(dst)                                                    \
    {   uint4 h, l;                                                           \
        split8(na0, na1, h, l);                                               \
        *(uint4*)((dst) + ar*40 + ac) = h;                                    \
        *(uint4*)((dst) + 2560 + ar*40 + ac) = l;                             \
        split8(nb0, nb1, h, l);                                               \
        *(uint4*)((dst) + 5120 + br2*136 + bc2) = h;                          \
        *(uint4*)((dst) + 9472 + br2*136 + bc2) = l;                          \
        split8(nb2, nb3, h, l);                                               \
        *(uint4*)((dst) + 5120 + br2*136 + bc2 + 8) = h;                      \
        *(uint4*)((dst) + 9472 + br2*136 + bc2 + 8) = l;                      \
    }

#define TC_COMPUTE(base)                                                      \
    {   _Pragma("unroll")                                                     \
        for (int kf = 0; kf < 2; kf++) {                                      \
            u32 ah[4], al[4];                                                 \
            ldsm4(ah, (base) + a_row_f*40 + kf*16 + a_col_s);                 \
            ldsm4(al, (base) + 2560 + a_row_f*40 + kf*16 + a_col_s);          \
            int rB = kf*16 + b_row_s;                                         \
            _Pragma("unroll")                                                 \
            for (int nf = 0; nf < 8; nf++) {                                  \
                u32 bh0, bh1, bl0, bl1;                                       \
                const __nv_bfloat16* pB = (base) + 5120 + rB*136 + ch + nf*8; \
                ldsm2t(bh0, bh1, pB);                                         \
                ldsm2t(bl0, bl1, pB + 4352);                                  \
                mma_bf16(acc[nf], ah, bh0, bh1);                              \
                mma_bf16(acc[nf], ah, bl0, bl1);                              \
                mma_bf16(acc[nf], al, bh0, bh1);                              \
            }                                                                 \
        }                                                                     \
    }

// ---------------- fused QKV GEMM (tensor cores, proven R12) ----------------
__global__ __launch_bounds__(256) void tc_qkv(const float* __restrict__ A,
                                              const float* __restrict__ wq,
                                              const float* __restrict__ wk,
                                              const float* __restrict__ wv) {
    extern __shared__ __align__(16) char dyn[];
    __nv_bfloat16* sm = (__nv_bfloat16*)dyn;
    int tid = threadIdx.x, w = tid >> 5, lane = tid & 31;
    int bn = blockIdx.x, m0 = blockIdx.y * 64;
    const float* B; float* C; int ldb; int col;
    if (bn < 8)       { B = wq; C = g_q; ldb = 1024; col = bn * 128; }
    else if (bn < 10) { B = wk; C = g_k; ldb = 256;  col = (bn - 8) * 128; }
    else              { B = wv; C = g_v; ldb = 256;  col = (bn - 10) * 128; }

    int ar = tid >> 2, ac = (tid & 3) * 8;
    int br2 = tid >> 3, bc2 = (tid & 7) * 16;
    int rb = (w & 3) * 16, ch = (w >> 2) * 64;
    int a_row_f = rb + (lane & 7) + ((lane >> 3) & 1) * 8;
    int a_col_s = ((lane >> 4) & 1) * 8;
    int b_row_s = lane & 15;

    const float* arp = A + (size_t)(m0 + ar)*DM + ac;
    const float* brp = B + (size_t)br2*ldb + col + bc2;
    float acc[8][4] = {};

    TC_PROLOGUE(sm)
    __syncthreads();
    int buf = 0;
    for (int kt = 1; kt <= 32; kt++) {
        bool more = (kt < 32);
        float4 na0, na1, nb0, nb1, nb2, nb3;
        if (more) {
            int k0 = kt * 32;
            na0 = *(const float4*)(arp + k0);
            na1 = *(const float4*)(arp + k0 + 4);
            const float* bp = brp + (size_t)k0 * ldb;
            nb0 = *(const float4*)bp;  nb1 = *(const float4*)(bp + 4);
            nb2 = *(const float4*)(bp + 8); nb3 = *(const float4*)(bp + 12);
        }
        const __nv_bfloat16* base = sm + buf*13824;
        TC_COMPUTE(base)
        if (more) { __nv_bfloat16* d = sm + (buf^1)*13824; TC_STORE_NEXT(d) }
        __syncthreads();
        buf ^= 1;
    }
    int r0 = m0 + rb + (lane >> 2);
    #pragma unroll
    for (int nf = 0; nf < 8; nf++) {
        int c = col + ch + nf*8 + (lane & 3)*2;
        *(float2*)&C[(size_t)r0*ldb + c]     = make_float2(acc[nf][0], acc[nf][1]);
        *(float2*)&C[(size_t)(r0+8)*ldb + c] = make_float2(acc[nf][2], acc[nf][3]);
    }
}

// ---------------- tensor GEMM + residual (wo; proven R11) ----------------
__global__ __launch_bounds__(256) void tc_gemm_res(const float* __restrict__ A,
                                                   const float* __restrict__ B,
                                                   float* __restrict__ C,
                                                   const float* __restrict__ res,
                                                   int N, int K) {
    extern __shared__ __align__(16) char dyn[];
    __nv_bfloat16* sm = (__nv_bfloat16*)dyn;
    int tid = threadIdx.x, w = tid >> 5, lane = tid & 31;
    int n0 = blockIdx.x * 128, m0 = blockIdx.y * 64;

    int ar = tid >> 2, ac = (tid & 3) * 8;
    int br2 = tid >> 3, bc2 = (tid & 7) * 16;
    int rb = (w & 3) * 16, ch = (w >> 2) * 64;
    int a_row_f = rb + (lane & 7) + ((lane >> 3) & 1) * 8;
    int a_col_s = ((lane >> 4) & 1) * 8;
    int b_row_s = lane & 15;

    const float* arp = A + (size_t)(m0 + ar)*K + ac;
    const float* brp = B + (size_t)br2*N + n0 + bc2;
    float acc[8][4] = {};

    TC_PROLOGUE(sm)
    __syncthreads();
    int buf = 0;
    int nkt = K / 32;
    for (int kt = 1; kt <= nkt; kt++) {
        bool more = (kt < nkt);
        float4 na0, na1, nb0, nb1, nb2, nb3;
        if (more) {
            int k0 = kt * 32;
            na0 = *(const float4*)(arp + k0);
            na1 = *(const float4*)(arp + k0 + 4);
            const float* bp = brp + (size_t)k0 * N;
            nb0 = *(const float4*)bp;  nb1 = *(const float4*)(bp + 4);
            nb2 = *(const float4*)(bp + 8); nb3 = *(const float4*)(bp + 12);
        }
        const __nv_bfloat16* base = sm + buf*13824;
        TC_COMPUTE(base)
        if (more) { __nv_bfloat16* d = sm + (buf^1)*13824; TC_STORE_NEXT(d) }
        __syncthreads();
        buf ^= 1;
    }
    int r0 = m0 + rb + (lane >> 2);
    #pragma unroll
    for (int nf = 0; nf < 8; nf++) {
        int c = n0 + ch + nf*8 + (lane & 3)*2;
        float2 v0 = make_float2(acc[nf][0], acc[nf][1]);
        float2 v1 = make_float2(acc[nf][2], acc[nf][3]);
        if (res) {
            float2 q0 = *(const float2*)&res[(size_t)r0*N + c];
            float2 q1 = *(const float2*)&res[(size_t)(r0+8)*N + c];
            v0.x += q0.x; v0.y += q0.y; v1.x += q1.x; v1.y += q1.y;
        }
        *(float2*)&C[(size_t)r0*N + c]     = v0;
        *(float2*)&C[(size_t)(r0+8)*N + c] = v1;
    }
}

// ============ FFN stage A (tensor cores, proven) ============
#define FA_BYTES (2*14336*2 + 512)
__global__ __launch_bounds__(256) void ffn_a(const float* __restrict__ w1e,
                                             const float* __restrict__ w3e,
                                             const float* __restrict__ sw1,
                                             const float* __restrict__ sw3) {
    extern __shared__ __align__(16) char dyn[];
    __nv_bfloat16* sm = (__nv_bfloat16*)dyn;
    int* s_arow = (int*)(dyn + 2*14336*2);
    int* s_orow = s_arow + 64;

    int tid = threadIdx.x, w = tid >> 5, lane = tid & 31;
    int bid = blockIdx.x;

    int ar = tid >> 2, ac = (tid & 3) * 8;
    int bmat = tid >> 7, br = (tid & 127) >> 2, bc = (tid & 3) * 16;
    int rb = (w & 3) * 16, ch = w >> 2;

    bool gather = (bid < NE*8);
    const float* B1g; const float* B3g;
    float* outb; const float* pw; int n0; int mTot; int mshb = 0;
    const int* lst = nullptr; int nrows = 0;

    if (gather) {
        int e = bid >> 3; n0 = (bid & 7) * 64;
        nrows = g_cnt[e];
        if (nrows == 0) return;
        lst = &g_list[e*SS];
        B1g = w1e + (size_t)e*DM*HE + n0;
        B3g = w3e + (size_t)e*DM*HE + n0;
        outb = g_gbuf; pw = g_pairw; mTot = nrows;
    } else {
        int b = bid - NE*8;
        n0 = (b & 7) * 64; mshb = (b >> 3) * 64;
        B1g = sw1 + n0; B3g = sw3 + n0;
        outb = g_a1; pw = nullptr; mTot = 64;
    }
    const float* Bgm = bmat ? B3g : B1g;
    int bhio = 5120 + bmat*4608, blio = bhio + 2304;

    int a_row_f = rb + (lane & 7) + ((lane >> 3) & 1) * 8;
    int a_col_s = ((lane >> 4) & 1) * 8;
    int b_row_s = lane & 15;
    int cB = ch * 32;

    for (int m0 = 0; m0 < mTot; m0 += 64) {
        __syncthreads();
        if (tid < 64) {
            int arow, orow;
            if (gather) {
                int p = (m0 + tid < nrows) ? lst[m0 + tid] : -1;
                arow = (p < 0) ? 0 : p / TOPK; orow = p;
            } else { arow = mshb + tid; orow = mshb + tid; }
            s_arow[tid] = arow; s_orow[tid] = orow;
        }
        __syncthreads();
        const float* arp = g_z + (size_t)s_arow[ar]*DM + ac;
        const float* brp = Bgm + (size_t)br*HE + bc;

        float acc1[4][4] = {}; float acc3[4][4] = {};

        {
            float4 va0 = *(const float4*)arp;
            float4 va1 = *(const float4*)(arp + 4);
            float4 vb0 = *(const float4*)brp;
            float4 vb1 = *(const float4*)(brp + 4);
            float4 vb2 = *(const float4*)(brp + 8);
            float4 vb3 = *(const float4*)(brp + 12);
            uint4 h, l;
            split8(va0, va1, h, l);
            *(uint4*)(sm + ar*40 + ac) = h;
            *(uint4*)(sm + 2560 + ar*40 + ac) = l;
            split8(vb0, vb1, h, l);
            *(uint4*)(sm + bhio + br*72 + bc) = h;
            *(uint4*)(sm + blio + br*72 + bc) = l;
            split8(vb2, vb3, h, l);
            *(uint4*)(sm + bhio + br*72 + bc + 8) = h;
            *(uint4*)(sm + blio + br*72 + bc + 8) = l;
        }
        __syncthreads();
        int buf = 0;
        for (int kt = 1; kt <= 32; kt++) {
            bool more = (kt < 32);
            float4 na0, na1, nb0, nb1, nb2, nb3;
            if (more) {
                int k0 = kt * 32;
                na0 = *(const float4*)(arp + k0);
                na1 = *(const float4*)(arp + k0 + 4);
                const float* bp = brp + (size_t)k0 * HE;
                nb0 = *(const float4*)bp;  nb1 = *(const float4*)(bp + 4);
                nb2 = *(const float4*)(bp + 8); nb3 = *(const float4*)(bp + 12);
            }
            {
                const __nv_bfloat16* base = sm + buf*14336;
                #pragma unroll
                for (int kf = 0; kf < 2; kf++) {
                    u32 ah[4], al[4];
                    ldsm4(ah, base + a_row_f*40 + kf*16 + a_col_s);
                    ldsm4(al, base + 2560 + a_row_f*40 + kf*16 + a_col_s);
                    int rB = kf*16 + b_row_s;
                    #pragma unroll
                    for (int nf = 0; nf < 4; nf++) {
                        u32 bh0, bh1, bl0, bl1;
                        const __nv_bfloat16* pB1 = base + 5120 + rB*72 + cB + nf*8;
                        ldsm2t(bh0, bh1, pB1);
                        ldsm2t(bl0, bl1, pB1 + 2304);
                        mma_bf16(acc1[nf], ah, bh0, bh1);
                        mma_bf16(acc1[nf], ah, bl0, bl1);
                        mma_bf16(acc1[nf], al, bh0, bh1);
                        const __nv_bfloat16* pB3 = pB1 + 4608;
                        ldsm2t(bh0, bh1, pB3);
                        ldsm2t(bl0, bl1, pB3 + 2304);
                        mma_bf16(acc3[nf], ah, bh0, bh1);
                        mma_bf16(acc3[nf], ah, bl0, bl1);
                        mma_bf16(acc3[nf], al, bh0, bh1);
                    }
                }
            }
            if (more) {
                __nv_bfloat16* d = sm + (buf^1)*14336;
                uint4 h, l;
                split8(na0, na1, h, l);
                *(uint4*)(d + ar*40 + ac) = h;
                *(uint4*)(d + 2560 + ar*40 + ac) = l;
                split8(nb0, nb1, h, l);
                *(uint4*)(d + bhio + br*72 + bc) = h;
                *(uint4*)(d + blio + br*72 + bc) = l;
                split8(nb2, nb3, h, l);
                *(uint4*)(d + bhio + br*72 + bc + 8) = h;
                *(uint4*)(d + blio + br*72 + bc + 8) = l;
            }
            __syncthreads();
            buf ^= 1;
        }
        int r0 = rb + (lane >> 2);
        int o0 = s_orow[r0], o1 = s_orow[r0 + 8];
        float wt0 = pw ? (o0 >= 0 ? pw[o0] : 0.f) : 1.f;
        float wt1 = pw ? (o1 >= 0 ? pw[o1] : 0.f) : 1.f;
        #pragma unroll
        for (int nf = 0; nf < 4; nf++) {
            int c = n0 + cB + nf*8 + (lane & 3)*2;
            if (o0 >= 0) {
                float x0 = acc1[nf][0], x1 = acc1[nf][1];
                float2 o;
                o.x = (x0/(1.f+__expf(-x0))) * acc3[nf][0] * wt0;
                o.y = (x1/(1.f+__expf(-x1))) * acc3[nf][1] * wt0;
                *(float2*)&outb[(size_t)o0*HE + c] = o;
            }
            if (o1 >= 0) {
                float x2 = acc1[nf][2], x3 = acc1[nf][3];
                float2 o;
                o.x = (x2/(1.f+__expf(-x2))) * acc3[nf][2] * wt1;
                o.y = (x3/(1.f+__expf(-x3))) * acc3[nf][3] * wt1;
                *(float2*)&outb[(size_t)o1*HE + c] = o;
            }
        }
    }
}

// ============ FFN stage B (tensor cores, proven) ============
__global__ __launch_bounds__(256) void ffn_b(const float* __restrict__ w2e,
                                             const float* __restrict__ sw2) {
    extern __shared__ __align__(16) char dyn[];
    __nv_bfloat16* sm = (__nv_bfloat16*)dyn;
    int* s_arow = (int*)(dyn + 2*13824*2);
    int* s_orow = s_arow + 64;

    int tid = threadIdx.x, w = tid >> 5, lane = tid & 31;
    int bid = blockIdx.x;

    int ar = tid >> 2, ac = (tid & 3) * 8;
    int br2 = tid >> 3, bc2 = (tid & 7) * 16;
    int rb = (w & 3) * 16, ch = (w >> 2) * 64;

    bool gather = (bid < NE*8);
    const float* Ag; const float* Bg;
    float* outb; int n0; int mTot; int mshb = 0;
    const int* lst = nullptr; int nrows = 0;

    if (gather) {
        int e = bid >> 3; n0 = (bid & 7) * 128;
        nrows = g_cnt[e];
        if (nrows == 0) return;
        lst = &g_list[e*SS];
        Ag = g_gbuf;
        Bg = w2e + (size_t)e*HE*DM + n0;
        outb = g_g2; mTot = nrows;
    } else {
        int b = bid - NE*8;
        n0 = (b & 7) * 128; mshb = (b >> 3) * 64;
        Ag = g_a1; Bg = sw2 + n0;
        outb = g_sh; mTot = 64;
    }

    int a_row_f = rb + (lane & 7) + ((lane >> 3) & 1) * 8;
    int a_col_s = ((lane >> 4) & 1) * 8;
    int b_row_s = lane & 15;

    for (int m0 = 0; m0 < mTot; m0 += 64) {
        __syncthreads();
        if (tid < 64) {
            int arow, orow;
            if (gather) {
                int p = (m0 + tid < nrows) ? lst[m0 + tid] : -1;
                arow = (p < 0) ? 0 : p; orow = p;
            } else { arow = mshb + tid; orow = mshb + tid; }
            s_arow[tid] = arow; s_orow[tid] = orow;
        }
        __syncthreads();
        const float* arp = Ag + (size_t)s_arow[ar]*HE + ac;
        const float* brp = Bg + (size_t)br2*DM + bc2;

        float acc[8][4] = {};

        TC_PROLOGUE(sm)
        __syncthreads();
        int buf = 0;
        for (int kt = 1; kt <= 16; kt++) {
            bool more = (kt < 16);
            float4 na0, na1, nb0, nb1, nb2, nb3;
            if (more) {
                int k0 = kt * 32;
                na0 = *(const float4*)(arp + k0);
                na1 = *(const float4*)(arp + k0 + 4);
                const float* bp = brp + (size_t)k0 * DM;
                nb0 = *(const float4*)bp;  nb1 = *(const float4*)(bp + 4);
                nb2 = *(const float4*)(bp + 8); nb3 = *(const float4*)(bp + 12);
            }
            const __nv_bfloat16* base = sm + buf*13824;
            TC_COMPUTE(base)
            if (more) { __nv_bfloat16* d = sm + (buf^1)*13824; TC_STORE_NEXT(d) }
            __syncthreads();
            buf ^= 1;
        }
        int r0 = rb + (lane >> 2);
        int o0 = s_orow[r0], o1 = s_orow[r0 + 8];
        #pragma unroll
        for (int nf = 0; nf < 8; nf++) {
            int c = n0 + ch + nf*8 + (lane & 3)*2;
            if (o0 >= 0)
                *(float2*)&outb[(size_t)o0*DM + c] = make_float2(acc[nf][0], acc[nf][1]);
            if (o1 >= 0)
                *(float2*)&outb[(size_t)o1*DM + c] = make_float2(acc[nf][2], acc[nf][3]);
        }
    }
}

// ---------------- q/k norm+rope + V convert; writes split-bf16 hi/lo ----------------
__global__ __launch_bounds__(256) void qkv_prep(const float* __restrict__ qw,
                                                const float* __restrict__ kw,
                                                const float* __restrict__ cosb,
                                                const float* __restrict__ sinb) {
    int gw = (blockIdx.x * blockDim.x + threadIdx.x) >> 5;
    int lane = threadIdx.x & 31;
    if (gw >= SS * (NHQ + 2*NKVH)) return;
    int t = gw / (NHQ + 2*NKVH);
    int hh = gw % (NHQ + 2*NKVH);
    int d0 = lane * 2;
    float o0, o1;
    __nv_bfloat16 *dsth, *dstl;
    size_t idx;
    if (hh < NHQ + NKVH) {
        const float* base;
        const float* w;
        if (hh < NHQ) {
            base = &g_q[(size_t)t*(NHQ*HDIM) + hh*HDIM]; w = qw;
            idx = (size_t)t*(NHQ*HDIM) + hh*HDIM + d0;
            dsth = g_qh; dstl = g_ql;
        } else {
            int kh_ = hh - NHQ;
            base = &g_k[(size_t)t*(NKVH*HDIM) + kh_*HDIM]; w = kw;
            idx = (size_t)t*(NKVH*HDIM) + kh_*HDIM + d0;
            dsth = g_kh; dstl = g_kl;
        }
        float v0 = base[d0], v1 = base[d0+1];
        float ss = v0*v0 + v1*v1;
        #pragma unroll
        for (int off = 16; off; off >>= 1) ss += __shfl_xor_sync(0xffffffffu, ss, off);
        float r = rsqrtf(ss * (1.0f/HDIM) + 1e-5f);
        float n0 = v0 * r * w[d0];
        float n1 = v1 * r * w[d0+1];
        float c = cosb[t*(HDIM/2) + lane];
        float s = sinb[t*(HDIM/2) + lane];
        o0 = n0*c - n1*s;
        o1 = n0*s + n1*c;
    } else {
        int vh_ = hh - NHQ - NKVH;
        const float* base = &g_v[(size_t)t*(NKVH*HDIM) + vh_*HDIM];
        o0 = base[d0]; o1 = base[d0+1];
        idx = (size_t)t*(NKVH*HDIM) + vh_*HDIM + d0;
        dsth = g_vh; dstl = g_vl;
    }
    *(u32*)&dsth[idx] = pkbf2(o0, o1);
    *(u32*)&dstl[idx] = pkres2(o0, o1);
}

// ---------------- flash attention v2: pre-split bf16 + cp.async double buffer ----------------
// 128 threads / 4 warps; warp w owns q-rows rb..rb+15 of a 64-row tile, full 64-kv width.
// smem bf16 elems: Qh@0, Ql@4608; buf{0,1}@9216+b*18432: Kh+0, Kl+4608, Vh+9216, Vl+13824.
#define TCF_SMEM (46080*2)
__global__ __launch_bounds__(128) void flash_tc() {
    extern __shared__ __align__(16) char dyn[];
    __nv_bfloat16* sm = (__nv_bfloat16*)dyn;
    __nv_bfloat16* Qhs = sm;
    __nv_bfloat16* Qls = sm + 4608;
    int tid = threadIdx.x, w = tid >> 5, lane = tid & 31;
    int qt = (int)gridDim.x - 1 - (int)blockIdx.x;
    int h = blockIdx.y, kvh = h >> 2;
    int q0 = qt * 64;
    int rb = w * 16;

    int lrow = tid >> 1, lcb = (tid & 1) * 32;

    // cp.async Q hi/lo
    {
        const __nv_bfloat16* sq = g_qh + (size_t)(q0 + lrow)*(NHQ*HDIM) + h*HDIM + lcb;
        const __nv_bfloat16* sl = g_ql + (size_t)(q0 + lrow)*(NHQ*HDIM) + h*HDIM + lcb;
        __nv_bfloat16* dq = Qhs + lrow*72 + lcb;
        __nv_bfloat16* dl = Qls + lrow*72 + lcb;
        #pragma unroll
        for (int c = 0; c < 4; c++) {
            cpa16(dq + c*8, sq + c*8);
            cpa16(dl + c*8, sl + c*8);
        }
    }
    // cp.async KV tile 0
    {
        __nv_bfloat16* b0 = sm + 9216;
        size_t goff = (size_t)lrow*(NKVH*HDIM) + kvh*HDIM + lcb;
        #pragma unroll
        for (int c = 0; c < 4; c++) {
            cpa16(b0 + lrow*72 + lcb + c*8,          g_kh + goff + c*8);
            cpa16(b0 + 4608 + lrow*72 + lcb + c*8,   g_kl + goff + c*8);
            cpa16(b0 + 9216 + lrow*72 + lcb + c*8,   g_vh + goff + c*8);
            cpa16(b0 + 13824 + lrow*72 + lcb + c*8,  g_vl + goff + c*8);
        }
    }
    CP_COMMIT();
    CP_WAIT0();
    __syncthreads();

    int a_row_f = rb + (lane & 7) + ((lane >> 3) & 1) * 8;
    int a_col_s = ((lane >> 4) & 1) * 8;
    int kq_row = lane & 7;
    int kq_off = ((lane >> 3) & 1) * 8;
    int v_row = lane & 15;

    // hoist Q fragments to registers (k-invariant)
    u32 qh_[4][4], ql_[4][4];
    #pragma unroll
    for (int kd = 0; kd < 4; kd++) {
        ldsm4(qh_[kd], Qhs + a_row_f*72 + kd*16 + a_col_s);
        ldsm4(ql_[kd], Qls + a_row_f*72 + kd*16 + a_col_s);
    }

    float Oacc[8][4] = {};
    float m_i[2] = {-1e30f, -1e30f};
    float l_i[2] = {0.f, 0.f};

    for (int kt = 0; kt <= qt; kt++) {
        int k0 = kt * 64;
        const __nv_bfloat16* cur = sm + 9216 + (kt & 1)*18432;
        bool more = (kt < qt);
        if (more) {
            __nv_bfloat16* nb = sm + 9216 + ((kt + 1) & 1)*18432;
            size_t goff = (size_t)(k0 + 64 + lrow)*(NKVH*HDIM) + kvh*HDIM + lcb;
            #pragma unroll
            for (int c = 0; c < 4; c++) {
                cpa16(nb + lrow*72 + lcb + c*8,          g_kh + goff + c*8);
                cpa16(nb + 4608 + lrow*72 + lcb + c*8,   g_kl + goff + c*8);
                cpa16(nb + 9216 + lrow*72 + lcb + c*8,   g_vh + goff + c*8);
                cpa16(nb + 13824 + lrow*72 + lcb + c*8,  g_vl + goff + c*8);
            }
            CP_COMMIT();
        }

        // S = Q K^T (3-term split)
        float S[8][4] = {};
        #pragma unroll
        for (int kd = 0; kd < 4; kd++) {
            #pragma unroll
            for (int nt = 0; nt < 8; nt++) {
                const __nv_bfloat16* pk = cur + (nt*8 + kq_row)*72 + kd*16 + kq_off;
                u32 bh0, bh1, bl0, bl1;
                ldsm2(bh0, bh1, pk);
                ldsm2(bl0, bl1, pk + 4608);
                mma_bf16(S[nt], qh_[kd], bh0, bh1);
                mma_bf16(S[nt], qh_[kd], bl0, bl1);
                mma_bf16(S[nt], ql_[kd], bh0, bh1);
            }
        }

        // online softmax (rows rA = lane>>2, rB = +8)
        const float sc = 0.125f;
        int colb = (lane & 3) * 2;
        int rAg = q0 + rb + (lane >> 2);
        int rBg = rAg + 8;
        if (kt == qt) {
            #pragma unroll
            for (int nt = 0; nt < 8; nt++) {
                int j0 = k0 + nt*8 + colb, j1 = j0 + 1;
                S[nt][0] = (j0 <= rAg) ? S[nt][0]*sc : -1e30f;
                S[nt][1] = (j1 <= rAg) ? S[nt][1]*sc : -1e30f;
                S[nt][2] = (j0 <= rBg) ? S[nt][2]*sc : -1e30f;
                S[nt][3] = (j1 <= rBg) ? S[nt][3]*sc : -1e30f;
            }
        } else {
            #pragma unroll
            for (int nt = 0; nt < 8; nt++) {
                S[nt][0] *= sc; S[nt][1] *= sc; S[nt][2] *= sc; S[nt][3] *= sc;
            }
        }
        float mxA = -1e30f, mxB = -1e30f;
        #pragma unroll
        for (int nt = 0; nt < 8; nt++) {
            mxA = fmaxf(mxA, fmaxf(S[nt][0], S[nt][1]));
            mxB = fmaxf(mxB, fmaxf(S[nt][2], S[nt][3]));
        }
        mxA = fmaxf(mxA, __shfl_xor_sync(0xffffffffu, mxA, 1));
        mxA = fmaxf(mxA, __shfl_xor_sync(0xffffffffu, mxA, 2));
        mxB = fmaxf(mxB, __shfl_xor_sync(0xffffffffu, mxB, 1));
        mxB = fmaxf(mxB, __shfl_xor_sync(0xffffffffu, mxB, 2));
        float mnA = fmaxf(m_i[0], mxA), mnB = fmaxf(m_i[1], mxB);
        float scA = __expf(m_i[0] - mnA), scB = __expf(m_i[1] - mnB);
        float rsA = 0.f, rsB = 0.f;
        #pragma unroll
        for (int nt = 0; nt < 8; nt++) {
            S[nt][0] = __expf(S[nt][0] - mnA); S[nt][1] = __expf(S[nt][1] - mnA);
            S[nt][2] = __expf(S[nt][2] - mnB); S[nt][3] = __expf(S[nt][3] - mnB);
            rsA += S[nt][0] + S[nt][1];
            rsB += S[nt][2] + S[nt][3];
        }
        rsA += __shfl_xor_sync(0xffffffffu, rsA, 1);
        rsA += __shfl_xor_sync(0xffffffffu, rsA, 2);
        rsB += __shfl_xor_sync(0xffffffffu, rsB, 1);
        rsB += __shfl_xor_sync(0xffffffffu, rsB, 2);
        l_i[0] = l_i[0]*scA + rsA; l_i[1] = l_i[1]*scB + rsB;
        m_i[0] = mnA; m_i[1] = mnB;
        #pragma unroll
        for (int nt = 0; nt < 8; nt++) {
            Oacc[nt][0] *= scA; Oacc[nt][1] *= scA;
            Oacc[nt][2] *= scB; Oacc[nt][3] *= scB;
        }

        // O += P V (P in registers, 3-term split)
        const __nv_bfloat16* Vc = cur + 9216;
        #pragma unroll
        for (int kf = 0; kf < 4; kf++) {
            u32 ph[4], pl[4];
            ph[0] = pkbf2(S[2*kf][0],   S[2*kf][1]);
            ph[1] = pkbf2(S[2*kf][2],   S[2*kf][3]);
            ph[2] = pkbf2(S[2*kf+1][0], S[2*kf+1][1]);
            ph[3] = pkbf2(S[2*kf+1][2], S[2*kf+1][3]);
            pl[0] = pkres2(S[2*kf][0],   S[2*kf][1]);
            pl[1] = pkres2(S[2*kf][2],   S[2*kf][3]);
            pl[2] = pkres2(S[2*kf+1][0], S[2*kf+1][1]);
            pl[3] = pkres2(S[2*kf+1][2], S[2*kf+1][3]);
            #pragma unroll
            for (int nt = 0; nt < 8; nt++) {
                const __nv_bfloat16* pv = Vc + (kf*16 + v_row)*72 + nt*8;
                u32 vh0, vh1, vl0, vl1;
                ldsm2t(vh0, vh1, pv);
                ldsm2t(vl0, vl1, pv + 4608);
                mma_bf16(Oacc[nt], ph, vh0, vh1);
                mma_bf16(Oacc[nt], ph, vl0, vl1);
                mma_bf16(Oacc[nt], pl, vh0, vh1);
            }
        }
        if (more) { CP_WAIT0(); }
        __syncthreads();
    }
    float invA = 1.f / l_i[0], invB = 1.f / l_i[1];
    int rAg = q0 + rb + (lane >> 2);
    float* outA = &g_attn[(size_t)rAg*(NHQ*HDIM) + h*HDIM];
    float* outB = outA + 8*(NHQ*HDIM);
    #pragma unroll
    for (int nt = 0; nt < 8; nt++) {
        int c = nt*8 + (lane & 3)*2;
        *(float2*)&outA[c] = make_float2(Oacc[nt][0]*invA, Oacc[nt][1]*invA);
        *(float2*)&outB[c] = make_float2(Oacc[nt][2]*invB, Oacc[nt][3]*invB);
    }
}

// ---------------- gate GEMM (N=64) ----------------
__global__ __launch_bounds__(256) void gemm64(const float* __restrict__ A,
                                              const float* __restrict__ B,
                                              float* __restrict__ C,
                                              int M, int N, int K) {
    __shared__ float As[16][64];
    __shared__ float Bs[16][64];
    int tid = threadIdx.x;
    int tx = tid & 15, ty = tid >> 4;
    int m0 = blockIdx.y * 64, n0 = blockIdx.x * 64;
    int ar = tid >> 2;
    int ac = (tid & 3) * 4;
    int br = tid >> 4;
    int bc = (tid & 15) * 4;
    float acc[4][4] = {};
    for (int k0 = 0; k0 < K; k0 += 16) {
        float4 av = *(const float4*)&A[(size_t)(m0 + ar)*K + k0 + ac];
        float4 bv = *(const float4*)&B[(size_t)(k0 + br)*N + n0 + bc];
        As[ac+0][ar] = av.x; As[ac+1][ar] = av.y;
        As[ac+2][ar] = av.z; As[ac+3][ar] = av.w;
        *(float4*)&Bs[br][bc] = bv;
        __syncthreads();
        #pragma unroll
        for (int k = 0; k < 16; k++) {
            float4 a = *(const float4*)&As[k][ty*4];
            float4 b = *(const float4*)&Bs[k][tx*4];
            float aa[4] = {a.x,a.y,a.z,a.w};
            float bb[4] = {b.x,b.y,b.z,b.w};
            #pragma unroll
            for (int i = 0; i < 4; i++)
                #pragma unroll
                for (int j = 0; j < 4; j++)
                    acc[i][j] += aa[i]*bb[j];
        }
        __syncthreads();
    }
    #pragma unroll
    for (int i = 0; i < 4; i++) {
        float4 ov = make_float4(acc[i][0],acc[i][1],acc[i][2],acc[i][3]);
        *(float4*)&C[(size_t)(m0 + ty*4 + i)*N + n0 + tx*4] = ov;
    }
}

// ---------------- routing ----------------
__global__ void zero_cnt_k() { if (threadIdx.x < NE) g_cnt[threadIdx.x] = 0; }

__global__ void route_k() {
    int t = blockIdx.x;
    int lane = threadIdx.x;
    float v0 = g_logits[t*NE + lane];
    float v1 = g_logits[t*NE + 32 + lane];
    float selv[TOPK]; int seli[TOPK];
    #pragma unroll
    for (int it = 0; it < TOPK; it++) {
        float best = (v0 >= v1) ? v0 : v1;
        int   bi   = (v0 >= v1) ? lane : lane + 32;
        #pragma unroll
        for (int off = 16; off; off >>= 1) {
            float ov = __shfl_xor_sync(0xffffffffu, best, off);
            int   oi = __shfl_xor_sync(0xffffffffu, bi, off);
            if (ov > best || (ov == best && oi < bi)) { best = ov; bi = oi; }
        }
        selv[it] = best; seli[it] = bi;
        if (bi == lane)      v0 = -1e30f;
        if (bi == lane + 32) v1 = -1e30f;
    }
    if (lane < TOPK) {
        float sum = 0.f;
        #pragma unroll
        for (int i = 0; i < TOPK; i++) sum += __expf(selv[i] - selv[0]);
        float w = __expf(selv[lane] - selv[0]) / sum;
        int e = seli[lane];
        int pos = atomicAdd(&g_cnt[e], 1);
        g_list[e*SS + pos] = t*TOPK + lane;
        g_pairw[t*TOPK + lane] = w;
    }
}

// ---------------- final ----------------
__global__ __launch_bounds__(256) void final_k(float* __restrict__ out) {
    int t = blockIdx.x;
    int c = threadIdx.x * 4;
    float4 a = *(const float4*)&g_h[(size_t)t*DM + c];
    float4 b = *(const float4*)&g_sh[(size_t)t*DM + c];
    a.x += b.x; a.y += b.y; a.z += b.z; a.w += b.w;
    #pragma unroll
    for (int kk = 0; kk < TOPK; kk++) {
        float4 gv = *(const float4*)&g_g2[(size_t)(t*TOPK+kk)*DM + c];
        a.x += gv.x; a.y += gv.y; a.z += gv.z; a.w += gv.w;
    }
    *(float4*)&out[(size_t)t*DM + c] = a;
}

// ---------------- host ----------------
extern "C" void kernel_launch(void* const* d_in, const int* in_sizes, int n_in,
                              void* d_out, int out_size) {
    const float* x   = (const float*)d_in[0];
    const float* fc  = (const float*)d_in[1];
    const float* fs  = (const float*)d_in[2];
    const float* anw = (const float*)d_in[3];
    const float* fnw = (const float*)d_in[4];
    const float* wq  = (const float*)d_in[5];
    const float* wk  = (const float*)d_in[6];
    const float* wv  = (const float*)d_in[7];
    const float* wo  = (const float*)d_in[8];
    const float* qnw = (const float*)d_in[9];
    const float* knw = (const float*)d_in[10];
    const float* gw  = (const float*)d_in[11];
    const float* w1e = (const float*)d_in[12];
    const float* w3e = (const float*)d_in[13];
    const float* w2e = (const float*)d_in[14];
    const float* sw1 = (const float*)d_in[15];
    const float* sw3 = (const float*)d_in[16];
    const float* sw2 = (const float*)d_in[17];
    float* out = (float*)d_out;

    float *hx,*attn,*h,*z,*logits;
    cudaGetSymbolAddress((void**)&hx, g_hx);
    cudaGetSymbolAddress((void**)&attn, g_attn);
    cudaGetSymbolAddress((void**)&h,  g_h);
    cudaGetSymbolAddress((void**)&z,  g_z);
    cudaGetSymbolAddress((void**)&logits, g_logits);

    cudaFuncSetAttribute(flash_tc, cudaFuncAttributeMaxDynamicSharedMemorySize, TCF_SMEM);
    cudaFuncSetAttribute(ffn_a, cudaFuncAttributeMaxDynamicSharedMemorySize, FA_BYTES);
    cudaFuncSetAttribute(ffn_b, cudaFuncAttributeMaxDynamicSharedMemorySize, FB_BYTES);
    cudaFuncSetAttribute(tc_qkv, cudaFuncAttributeMaxDynamicSharedMemorySize, FB_BYTES);
    cudaFuncSetAttribute(tc_gemm_res, cudaFuncAttributeMaxDynamicSharedMemorySize, FB_BYTES);

    // attention branch
    rmsnorm_k<<<SS, 256>>>(x, anw, hx);
    tc_qkv<<<dim3(12, 16), 256, FB_BYTES>>>(hx, wq, wk, wv);
    qkv_prep<<<(SS*(NHQ+2*NKVH)*32)/256, 256>>>(qnw, knw, fc, fs);   // norm+rope+split to bf16 hi/lo
    flash_tc<<<dim3(16,16), 128, TCF_SMEM>>>();
    tc_gemm_res<<<dim3(8, 16), 256, FB_BYTES>>>(attn, wo, h, x, 1024, 1024);  // h = attn@wo + x

    // ffn branch
    rmsnorm_k<<<SS, 256>>>(h, fnw, z);
    gemm64<<<dim3(1, 16), 256>>>(z, gw, logits, SS, NE, DM);
    zero_cnt_k<<<1, 64>>>();
    route_k<<<SS, 32>>>();
    ffn_a<<<NE*8 + 128, 256, FA_BYTES>>>(w1e, w3e, sw1, sw3);
    ffn_b<<<NE*8 + 128, 256, FB_BYTES>>>(w2e, sw2);

    final_k<<<SS, 256>>>(out);
}

// round 16
// speedup vs baseline: 3.3930x; 1.0024x over previous
#include <cuda_runtime.h>
#include <cuda_bf16.h>
#include <math.h>

#define SS 1024
#define DM 1024
#define NHQ 16
#define NKVH 4
#define HDIM 64
#define NE 64
#define TOPK 6
#define HE 512
#define NPAIR (SS*TOPK)

typedef unsigned long long u64;
typedef unsigned int u32;

// ---------------- tensor-core helpers ----------------
__device__ __forceinline__ void mma_bf16(float* d, const u32* a, u32 b0, u32 b1) {
    asm volatile("mma.sync.aligned.m16n8k16.row.col.f32.bf16.bf16.f32 "
        "{%0,%1,%2,%3},{%4,%5,%6,%7},{%8,%9},{%0,%1,%2,%3};"
        : "+f"(d[0]),"+f"(d[1]),"+f"(d[2]),"+f"(d[3])
        : "r"(a[0]),"r"(a[1]),"r"(a[2]),"r"(a[3]), "r"(b0),"r"(b1));
}
__device__ __forceinline__ void ldsm4(u32* r, const __nv_bfloat16* p) {
    u32 a = (u32)__cvta_generic_to_shared(p);
    asm volatile("ldmatrix.sync.aligned.m8n8.x4.shared.b16 {%0,%1,%2,%3},[%4];"
        : "=r"(r[0]),"=r"(r[1]),"=r"(r[2]),"=r"(r[3]) : "r"(a));
}
__device__ __forceinline__ void ldsm4t(u32* r, const __nv_bfloat16* p) {
    u32 a = (u32)__cvta_generic_to_shared(p);
    asm volatile("ldmatrix.sync.aligned.m8n8.x4.trans.shared.b16 {%0,%1,%2,%3},[%4];"
        : "=r"(r[0]),"=r"(r[1]),"=r"(r[2]),"=r"(r[3]) : "r"(a));
}
__device__ __forceinline__ void ldsm2(u32 &r0, u32 &r1, const __nv_bfloat16* p) {
    u32 a = (u32)__cvta_generic_to_shared(p);
    asm volatile("ldmatrix.sync.aligned.m8n8.x2.shared.b16 {%0,%1},[%2];"
        : "=r"(r0),"=r"(r1) : "r"(a));
}
__device__ __forceinline__ void ldsm2t(u32 &r0, u32 &r1, const __nv_bfloat16* p) {
    u32 a = (u32)__cvta_generic_to_shared(p);
    asm volatile("ldmatrix.sync.aligned.m8n8.x2.trans.shared.b16 {%0,%1},[%2];"
        : "=r"(r0),"=r"(r1) : "r"(a));
}
__device__ __forceinline__ u32 pkbf2(float x, float y) {
    __nv_bfloat162 h = __floats2bfloat162_rn(x, y);
    return *reinterpret_cast<u32*>(&h);
}
__device__ __forceinline__ u32 pkres2(float x, float y) {
    float rx = x - __bfloat162float(__float2bfloat16(x));
    float ry = y - __bfloat162float(__float2bfloat16(y));
    return pkbf2(rx, ry);
}
__device__ __forceinline__ void split8(float4 v0, float4 v1, uint4 &hi, uint4 &lo) {
    float f[8] = {v0.x,v0.y,v0.z,v0.w,v1.x,v1.y,v1.z,v1.w};
    float r[8];
    #pragma unroll
    for (int i = 0; i < 8; i++) r[i] = f[i] - __bfloat162float(__float2bfloat16(f[i]));
    hi = make_uint4(pkbf2(f[0],f[1]),pkbf2(f[2],f[3]),pkbf2(f[4],f[5]),pkbf2(f[6],f[7]));
    lo = make_uint4(pkbf2(r[0],r[1]),pkbf2(r[2],r[3]),pkbf2(r[4],r[5]),pkbf2(r[6],r[7]));
}
__device__ __forceinline__ void cpa16(__nv_bfloat16* s, const __nv_bfloat16* g) {
    u32 a = (u32)__cvta_generic_to_shared(s);
    asm volatile("cp.async.ca.shared.global [%0], [%1], 16;" :: "r"(a), "l"(g));
}
#define CP_COMMIT() asm volatile("cp.async.commit_group;" ::: "memory")
#define CP_WAIT0()  asm volatile("cp.async.wait_group 0;" ::: "memory")

// ---------------- scratch ----------------
__device__ float g_q[SS*NHQ*HDIM];
__device__ float g_k[SS*NKVH*HDIM];
__device__ float g_v[SS*NKVH*HDIM];
__device__ __nv_bfloat16 g_hxh[SS*DM];
__device__ __nv_bfloat16 g_hxl[SS*DM];
__device__ __nv_bfloat16 g_zh[SS*DM];
__device__ __nv_bfloat16 g_zl[SS*DM];
__device__ __nv_bfloat16 g_qh[SS*NHQ*HDIM];
__device__ __nv_bfloat16 g_ql[SS*NHQ*HDIM];
__device__ __nv_bfloat16 g_kh[SS*NKVH*HDIM];
__device__ __nv_bfloat16 g_kl[SS*NKVH*HDIM];
__device__ __nv_bfloat16 g_vh[SS*NKVH*HDIM];
__device__ __nv_bfloat16 g_vl[SS*NKVH*HDIM];
__device__ __nv_bfloat16 g_ath[SS*NHQ*HDIM];
__device__ __nv_bfloat16 g_atl[SS*NHQ*HDIM];
__device__ __nv_bfloat16 g_gbh[(size_t)NPAIR*HE];
__device__ __nv_bfloat16 g_gbl[(size_t)NPAIR*HE];
__device__ __nv_bfloat16 g_a1h[SS*HE];
__device__ __nv_bfloat16 g_a1l[SS*HE];
__device__ float g_h[SS*DM];
__device__ float g_z[SS*DM];
__device__ float g_logits[SS*NE];
__device__ float g_pairw[NPAIR];
__device__ int   g_cnt[NE];
__device__ int   g_list[NE*SS];
__device__ float g_g2[(size_t)NPAIR*DM];
__device__ float g_sh[SS*DM];

// ---------------- rmsnorm (emits fp32 + pre-split bf16 hi/lo) ----------------
__global__ __launch_bounds__(256) void rmsnorm_k(const float* __restrict__ x,
                                                 const float* __restrict__ w,
                                                 float* __restrict__ out,
                                                 __nv_bfloat16* __restrict__ outh,
                                                 __nv_bfloat16* __restrict__ outl) {
    int t = blockIdx.x;
    int tid = threadIdx.x;
    float4 xv = *(const float4*)&x[(size_t)t*DM + tid*4];
    float ss = xv.x*xv.x + xv.y*xv.y + xv.z*xv.z + xv.w*xv.w;
    #pragma unroll
    for (int off = 16; off; off >>= 1) ss += __shfl_xor_sync(0xffffffffu, ss, off);
    __shared__ float red[8];
    if ((tid & 31) == 0) red[tid >> 5] = ss;
    __syncthreads();
    float tot = 0.f;
    #pragma unroll
    for (int i = 0; i < 8; i++) tot += red[i];
    float r = rsqrtf(tot * (1.0f/DM) + 1e-5f);
    float4 wv = *(const float4*)&w[tid*4];
    float4 ov;
    ov.x = wv.x * (xv.x * r); ov.y = wv.y * (xv.y * r);
    ov.z = wv.z * (xv.z * r); ov.w = wv.w * (xv.w * r);
    size_t idx = (size_t)t*DM + tid*4;
    *(float4*)&out[idx] = ov;
    uint2 hv = make_uint2(pkbf2(ov.x,ov.y), pkbf2(ov.z,ov.w));
    uint2 lv = make_uint2(pkres2(ov.x,ov.y), pkres2(ov.z,ov.w));
    *(uint2*)&outh[idx] = hv;
    *(uint2*)&outl[idx] = lv;
}

// ============ split-bf16 tensor GEMM core (pre-split A, x4t B) ============
// BM=64, BN=128, BK=32, 256 threads, 8 warps.
#define FB_BYTES (2*13824*2 + 512)

#define TC_PROLOGUE_PS(dst)                                                   \
    {   uint4 hv = *(const uint4*)ahp;                                        \
        uint4 lv = *(const uint4*)alp;                                        \
        *(uint4*)((dst) + ar*40 + ac) = hv;                                   \
        *(uint4*)((dst) + 2560 + ar*40 + ac) = lv;                            \
        float4 vb0 = *(const float4*)brp;                                     \
        float4 vb1 = *(const float4*)(brp + 4);                               \
        float4 vb2 = *(const float4*)(brp + 8);                               \
        float4 vb3 = *(const float4*)(brp + 12);                              \
        uint4 h, l;                                                           \
        split8(vb0, vb1, h, l);                                               \
        *(uint4*)((dst) + 5120 + br2*136 + bc2) = h;                          \
        *(uint4*)((dst) + 9472 + br2*136 + bc2) = l;                          \
        split8(vb2, vb3, h, l);                                               \
        *(uint4*)((dst) + 5120 + br2*136 + bc2 + 8) = h;                      \
        *(uint4*)((dst) + 9472 + br2*136 + bc2 + 8) = l;                      \
    }

#define TC_STORE_NEXT_PS(dst)                                                 \
    {   *(uint4*)((dst) + ar*40 + ac) = nah;                                  \
        *(uint4*)((dst) + 2560 + ar*40 + ac) = nal;                           \
        uint4 h, l;                                                           \
        split8(nb0, nb1, h, l);                                               \
        *(uint4*)((dst) + 5120 + br2*136 + bc2) = h;                          \
        *(uint4*)((dst) + 9472 + br2*136 + bc2) = l;                          \
        split8(nb2, nb3, h, l);                                               \
        *(uint4*)((dst) + 5120 + br2*136 + bc2 + 8) = h;                      \
        *(uint4*)((dst) + 9472 + br2*136 + bc2 + 8) = l;                      \
    }

#define TC_COMPUTE4(base)                                                     \
    {   _Pragma("unroll")                                                     \
        for (int kf = 0; kf < 2; kf++) {                                      \
            u32 ah[4], al[4];                                                 \
            ldsm4(ah, (base) + a_row_f*40 + kf*16 + a_col_s);                 \
            ldsm4(al, (base) + 2560 + a_row_f*40 + kf*16 + a_col_s);          \
            int rB = kf*16 + b_row_s;                                         \
            _Pragma("unroll")                                                 \
            for (int nfp = 0; nfp < 4; nfp++) {                               \
                const __nv_bfloat16* pB = (base) + 5120 + rB*136 + ch + nfp*16 + b_col4; \
                u32 bh[4], bl[4];                                             \
                ldsm4t(bh, pB);                                               \
                ldsm4t(bl, pB + 4352);                                        \
                mma_bf16(acc[2*nfp],   ah, bh[0], bh[1]);                     \
                mma_bf16(acc[2*nfp+1], ah, bh[2], bh[3]);                     \
                mma_bf16(acc[2*nfp],   ah, bl[0], bl[1]);                     \
                mma_bf16(acc[2*nfp+1], ah, bl[2], bl[3]);                     \
                mma_bf16(acc[2*nfp],   al, bh[0], bh[1]);                     \
                mma_bf16(acc[2*nfp+1], al, bh[2], bh[3]);                     \
            }                                                                 \
        }                                                                     \
    }

// ---------------- fused QKV GEMM (pre-split A) ----------------
__global__ __launch_bounds__(256) void tc_qkv(const float* __restrict__ wq,
                                              const float* __restrict__ wk,
                                              const float* __restrict__ wv) {
    extern __shared__ __align__(16) char dyn[];
    __nv_bfloat16* sm = (__nv_bfloat16*)dyn;
    int tid = threadIdx.x, w = tid >> 5, lane = tid & 31;
    int bn = blockIdx.x, m0 = blockIdx.y * 64;
    const float* B; float* C; int ldb; int col;
    if (bn < 8)       { B = wq; C = g_q; ldb = 1024; col = bn * 128; }
    else if (bn < 10) { B = wk; C = g_k; ldb = 256;  col = (bn - 8) * 128; }
    else              { B = wv; C = g_v; ldb = 256;  col = (bn - 10) * 128; }

    int ar = tid >> 2, ac = (tid & 3) * 8;
    int br2 = tid >> 3, bc2 = (tid & 7) * 16;
    int rb = (w & 3) * 16, ch = (w >> 2) * 64;
    int a_row_f = rb + (lane & 7) + ((lane >> 3) & 1) * 8;
    int a_col_s = ((lane >> 4) & 1) * 8;
    int b_row_s = lane & 15;
    int b_col4 = ((lane >> 4) & 1) * 8;

    const __nv_bfloat16* ahp = g_hxh + (size_t)(m0 + ar)*DM + ac;
    const __nv_bfloat16* alp = g_hxl + (size_t)(m0 + ar)*DM + ac;
    const float* brp = B + (size_t)br2*ldb + col + bc2;
    float acc[8][4] = {};

    TC_PROLOGUE_PS(sm)
    __syncthreads();
    int buf = 0;
    for (int kt = 1; kt <= 32; kt++) {
        bool more = (kt < 32);
        uint4 nah, nal; float4 nb0, nb1, nb2, nb3;
        if (more) {
            int k0 = kt * 32;
            nah = *(const uint4*)(ahp + k0);
            nal = *(const uint4*)(alp + k0);
            const float* bp = brp + (size_t)k0 * ldb;
            nb0 = *(const float4*)bp;  nb1 = *(const float4*)(bp + 4);
            nb2 = *(const float4*)(bp + 8); nb3 = *(const float4*)(bp + 12);
        }
        const __nv_bfloat16* base = sm + buf*13824;
        TC_COMPUTE4(base)
        if (more) { __nv_bfloat16* d = sm + (buf^1)*13824; TC_STORE_NEXT_PS(d) }
        __syncthreads();
        buf ^= 1;
    }
    int r0 = m0 + rb + (lane >> 2);
    #pragma unroll
    for (int nf = 0; nf < 8; nf++) {
        int c = col + ch + nf*8 + (lane & 3)*2;
        *(float2*)&C[(size_t)r0*ldb + c]     = make_float2(acc[nf][0], acc[nf][1]);
        *(float2*)&C[(size_t)(r0+8)*ldb + c] = make_float2(acc[nf][2], acc[nf][3]);
    }
}

// ---------------- wo GEMM + residual (A = attn hi/lo pre-split) ----------------
__global__ __launch_bounds__(256) void tc_wo(const float* __restrict__ B,
                                             float* __restrict__ C,
                                             const float* __restrict__ res) {
    extern __shared__ __align__(16) char dyn[];
    __nv_bfloat16* sm = (__nv_bfloat16*)dyn;
    int tid = threadIdx.x, w = tid >> 5, lane = tid & 31;
    const int N = 1024, K = 1024;
    int n0 = blockIdx.x * 128, m0 = blockIdx.y * 64;

    int ar = tid >> 2, ac = (tid & 3) * 8;
    int br2 = tid >> 3, bc2 = (tid & 7) * 16;
    int rb = (w & 3) * 16, ch = (w >> 2) * 64;
    int a_row_f = rb + (lane & 7) + ((lane >> 3) & 1) * 8;
    int a_col_s = ((lane >> 4) & 1) * 8;
    int b_row_s = lane & 15;
    int b_col4 = ((lane >> 4) & 1) * 8;

    const __nv_bfloat16* ahp = g_ath + (size_t)(m0 + ar)*K + ac;
    const __nv_bfloat16* alp = g_atl + (size_t)(m0 + ar)*K + ac;
    const float* brp = B + (size_t)br2*N + n0 + bc2;
    float acc[8][4] = {};

    TC_PROLOGUE_PS(sm)
    __syncthreads();
    int buf = 0;
    for (int kt = 1; kt <= 32; kt++) {
        bool more = (kt < 32);
        uint4 nah, nal; float4 nb0, nb1, nb2, nb3;
        if (more) {
            int k0 = kt * 32;
            nah = *(const uint4*)(ahp + k0);
            nal = *(const uint4*)(alp + k0);
            const float* bp = brp + (size_t)k0 * N;
            nb0 = *(const float4*)bp;  nb1 = *(const float4*)(bp + 4);
            nb2 = *(const float4*)(bp + 8); nb3 = *(const float4*)(bp + 12);
        }
        const __nv_bfloat16* base = sm + buf*13824;
        TC_COMPUTE4(base)
        if (more) { __nv_bfloat16* d = sm + (buf^1)*13824; TC_STORE_NEXT_PS(d) }
        __syncthreads();
        buf ^= 1;
    }
    int r0 = m0 + rb + (lane >> 2);
    #pragma unroll
    for (int nf = 0; nf < 8; nf++) {
        int c = n0 + ch + nf*8 + (lane & 3)*2;
        float2 v0 = make_float2(acc[nf][0], acc[nf][1]);
        float2 v1 = make_float2(acc[nf][2], acc[nf][3]);
        float2 q0 = *(const float2*)&res[(size_t)r0*N + c];
        float2 q1 = *(const float2*)&res[(size_t)(r0+8)*N + c];
        v0.x += q0.x; v0.y += q0.y; v1.x += q1.x; v1.y += q1.y;
        *(float2*)&C[(size_t)r0*N + c]     = v0;
        *(float2*)&C[(size_t)(r0+8)*N + c] = v1;
    }
}

// ============ FFN stage A: MoE GEMM1 + shared dual (pre-split A/z, x4t B) ============
#define FA_BYTES (2*14336*2 + 512)
__global__ __launch_bounds__(256) void ffn_a(const float* __restrict__ w1e,
                                             const float* __restrict__ w3e,
                                             const float* __restrict__ sw1,
                                             const float* __restrict__ sw3) {
    extern __shared__ __align__(16) char dyn[];
    __nv_bfloat16* sm = (__nv_bfloat16*)dyn;
    int* s_arow = (int*)(dyn + 2*14336*2);
    int* s_orow = s_arow + 64;

    int tid = threadIdx.x, w = tid >> 5, lane = tid & 31;
    int bid = blockIdx.x;

    int ar = tid >> 2, ac = (tid & 3) * 8;
    int bmat = tid >> 7, br = (tid & 127) >> 2, bc = (tid & 3) * 16;
    int rb = (w & 3) * 16, ch = w >> 2;

    bool gather = (bid < NE*8);
    const float* B1g; const float* B3g;
    __nv_bfloat16 *outh, *outl;
    const float* pw; int n0; int mTot; int mshb = 0;
    const int* lst = nullptr; int nrows = 0;

    if (gather) {
        int e = bid >> 3; n0 = (bid & 7) * 64;
        nrows = g_cnt[e];
        if (nrows == 0) return;
        lst = &g_list[e*SS];
        B1g = w1e + (size_t)e*DM*HE + n0;
        B3g = w3e + (size_t)e*DM*HE + n0;
        outh = g_gbh; outl = g_gbl; pw = g_pairw; mTot = nrows;
    } else {
        int b = bid - NE*8;
        n0 = (b & 7) * 64; mshb = (b >> 3) * 64;
        B1g = sw1 + n0; B3g = sw3 + n0;
        outh = g_a1h; outl = g_a1l; pw = nullptr; mTot = 64;
    }
    const float* Bgm = bmat ? B3g : B1g;
    int bhio = 5120 + bmat*4608, blio = bhio + 2304;

    int a_row_f = rb + (lane & 7) + ((lane >> 3) & 1) * 8;
    int a_col_s = ((lane >> 4) & 1) * 8;
    int b_row_s = lane & 15;
    int b_col4 = ((lane >> 4) & 1) * 8;
    int cB = ch * 32;

    for (int m0 = 0; m0 < mTot; m0 += 64) {
        __syncthreads();
        if (tid < 64) {
            int arow, orow;
            if (gather) {
                int p = (m0 + tid < nrows) ? lst[m0 + tid] : -1;
                arow = (p < 0) ? 0 : p / TOPK; orow = p;
            } else { arow = mshb + tid; orow = mshb + tid; }
            s_arow[tid] = arow; s_orow[tid] = orow;
        }
        __syncthreads();
        const __nv_bfloat16* ahp = g_zh + (size_t)s_arow[ar]*DM + ac;
        const __nv_bfloat16* alp = g_zl + (size_t)s_arow[ar]*DM + ac;
        const float* brp = Bgm + (size_t)br*HE + bc;

        float acc1[4][4] = {}; float acc3[4][4] = {};

        {   // prologue
            uint4 hv = *(const uint4*)ahp;
            uint4 lv = *(const uint4*)alp;
            *(uint4*)(sm + ar*40 + ac) = hv;
            *(uint4*)(sm + 2560 + ar*40 + ac) = lv;
            float4 vb0 = *(const float4*)brp;
            float4 vb1 = *(const float4*)(brp + 4);
            float4 vb2 = *(const float4*)(brp + 8);
            float4 vb3 = *(const float4*)(brp + 12);
            uint4 h, l;
            split8(vb0, vb1, h, l);
            *(uint4*)(sm + bhio + br*72 + bc) = h;
            *(uint4*)(sm + blio + br*72 + bc) = l;
            split8(vb2, vb3, h, l);
            *(uint4*)(sm + bhio + br*72 + bc + 8) = h;
            *(uint4*)(sm + blio + br*72 + bc + 8) = l;
        }
        __syncthreads();
        int buf = 0;
        for (int kt = 1; kt <= 32; kt++) {
            bool more = (kt < 32);
            uint4 nah, nal; float4 nb1, nb2, nb3, nb4;
            if (more) {
                int k0 = kt * 32;
                nah = *(const uint4*)(ahp + k0);
                nal = *(const uint4*)(alp + k0);
                const float* bp = brp + (size_t)k0 * HE;
                nb1 = *(const float4*)bp;  nb2 = *(const float4*)(bp + 4);
                nb3 = *(const float4*)(bp + 8); nb4 = *(const float4*)(bp + 12);
            }
            {
                const __nv_bfloat16* base = sm + buf*14336;
                #pragma unroll
                for (int kf = 0; kf < 2; kf++) {
                    u32 ah[4], al[4];
                    ldsm4(ah, base + a_row_f*40 + kf*16 + a_col_s);
                    ldsm4(al, base + 2560 + a_row_f*40 + kf*16 + a_col_s);
                    int rB = kf*16 + b_row_s;
                    #pragma unroll
                    for (int nfp = 0; nfp < 2; nfp++) {
                        const __nv_bfloat16* pB1 = base + 5120 + rB*72 + cB + nfp*16 + b_col4;
                        u32 b1h[4], b1l[4], b3h[4], b3l[4];
                        ldsm4t(b1h, pB1);
                        ldsm4t(b1l, pB1 + 2304);
                        ldsm4t(b3h, pB1 + 4608);
                        ldsm4t(b3l, pB1 + 6912);
                        mma_bf16(acc1[2*nfp],   ah, b1h[0], b1h[1]);
                        mma_bf16(acc1[2*nfp+1], ah, b1h[2], b1h[3]);
                        mma_bf16(acc1[2*nfp],   ah, b1l[0], b1l[1]);
                        mma_bf16(acc1[2*nfp+1], ah, b1l[2], b1l[3]);
                        mma_bf16(acc1[2*nfp],   al, b1h[0], b1h[1]);
                        mma_bf16(acc1[2*nfp+1], al, b1h[2], b1h[3]);
                        mma_bf16(acc3[2*nfp],   ah, b3h[0], b3h[1]);
                        mma_bf16(acc3[2*nfp+1], ah, b3h[2], b3h[3]);
                        mma_bf16(acc3[2*nfp],   ah, b3l[0], b3l[1]);
                        mma_bf16(acc3[2*nfp+1], ah, b3l[2], b3l[3]);
                        mma_bf16(acc3[2*nfp],   al, b3h[0], b3h[1]);
                        mma_bf16(acc3[2*nfp+1], al, b3h[2], b3h[3]);
                    }
                }
            }
            if (more) {
                __nv_bfloat16* d = sm + (buf^1)*14336;
                *(uint4*)(d + ar*40 + ac) = nah;
                *(uint4*)(d + 2560 + ar*40 + ac) = nal;
                uint4 h, l;
                split8(nb1, nb2, h, l);
                *(uint4*)(d + bhio + br*72 + bc) = h;
                *(uint4*)(d + blio + br*72 + bc) = l;
                split8(nb3, nb4, h, l);
                *(uint4*)(d + bhio + br*72 + bc + 8) = h;
                *(uint4*)(d + blio + br*72 + bc + 8) = l;
            }
            __syncthreads();
            buf ^= 1;
        }
        int r0 = rb + (lane >> 2);
        int o0 = s_orow[r0], o1 = s_orow[r0 + 8];
        float wt0 = pw ? (o0 >= 0 ? pw[o0] : 0.f) : 1.f;
        float wt1 = pw ? (o1 >= 0 ? pw[o1] : 0.f) : 1.f;
        #pragma unroll
        for (int nf = 0; nf < 4; nf++) {
            int c = n0 + cB + nf*8 + (lane & 3)*2;
            if (o0 >= 0) {
                float x0 = acc1[nf][0], x1 = acc1[nf][1];
                float ox = (x0/(1.f+__expf(-x0))) * acc3[nf][0] * wt0;
                float oy = (x1/(1.f+__expf(-x1))) * acc3[nf][1] * wt0;
                size_t idx = (size_t)o0*HE + c;
                *(u32*)&outh[idx] = pkbf2(ox, oy);
                *(u32*)&outl[idx] = pkres2(ox, oy);
            }
            if (o1 >= 0) {
                float x2 = acc1[nf][2], x3 = acc1[nf][3];
                float ox = (x2/(1.f+__expf(-x2))) * acc3[nf][2] * wt1;
                float oy = (x3/(1.f+__expf(-x3))) * acc3[nf][3] * wt1;
                size_t idx = (size_t)o1*HE + c;
                *(u32*)&outh[idx] = pkbf2(ox, oy);
                *(u32*)&outl[idx] = pkres2(ox, oy);
            }
        }
    }
}

// ============ FFN stage B: MoE GEMM2 + shared down (pre-split A, x4t B) ============
__global__ __launch_bounds__(256) void ffn_b(const float* __restrict__ w2e,
                                             const float* __restrict__ sw2) {
    extern __shared__ __align__(16) char dyn[];
    __nv_bfloat16* sm = (__nv_bfloat16*)dyn;
    int* s_arow = (int*)(dyn + 2*13824*2);
    int* s_orow = s_arow + 64;

    int tid = threadIdx.x, w = tid >> 5, lane = tid & 31;
    int bid = blockIdx.x;

    int ar = tid >> 2, ac = (tid & 3) * 8;
    int br2 = tid >> 3, bc2 = (tid & 7) * 16;
    int rb = (w & 3) * 16, ch = (w >> 2) * 64;

    bool gather = (bid < NE*8);
    const __nv_bfloat16 *Agh, *Agl;
    const float* Bg;
    float* outb; int n0; int mTot; int mshb = 0;
    const int* lst = nullptr; int nrows = 0;

    if (gather) {
        int e = bid >> 3; n0 = (bid & 7) * 128;
        nrows = g_cnt[e];
        if (nrows == 0) return;
        lst = &g_list[e*SS];
        Agh = g_gbh; Agl = g_gbl;
        Bg = w2e + (size_t)e*HE*DM + n0;
        outb = g_g2; mTot = nrows;
    } else {
        int b = bid - NE*8;
        n0 = (b & 7) * 128; mshb = (b >> 3) * 64;
        Agh = g_a1h; Agl = g_a1l; Bg = sw2 + n0;
        outb = g_sh; mTot = 64;
    }

    int a_row_f = rb + (lane & 7) + ((lane >> 3) & 1) * 8;
    int a_col_s = ((lane >> 4) & 1) * 8;
    int b_row_s = lane & 15;
    int b_col4 = ((lane >> 4) & 1) * 8;

    for (int m0 = 0; m0 < mTot; m0 += 64) {
        __syncthreads();
        if (tid < 64) {
            int arow, orow;
            if (gather) {
                int p = (m0 + tid < nrows) ? lst[m0 + tid] : -1;
                arow = (p < 0) ? 0 : p; orow = p;
            } else { arow = mshb + tid; orow = mshb + tid; }
            s_arow[tid] = arow; s_orow[tid] = orow;
        }
        __syncthreads();
        const __nv_bfloat16* ahp = Agh + (size_t)s_arow[ar]*HE + ac;
        const __nv_bfloat16* alp = Agl + (size_t)s_arow[ar]*HE + ac;
        const float* brp = Bg + (size_t)br2*DM + bc2;

        float acc[8][4] = {};

        TC_PROLOGUE_PS(sm)
        __syncthreads();
        int buf = 0;
        for (int kt = 1; kt <= 16; kt++) {
            bool more = (kt < 16);
            uint4 nah, nal; float4 nb0, nb1, nb2, nb3;
            if (more) {
                int k0 = kt * 32;
                nah = *(const uint4*)(ahp + k0);
                nal = *(const uint4*)(alp + k0);
                const float* bp = brp + (size_t)k0 * DM;
                nb0 = *(const float4*)bp;  nb1 = *(const float4*)(bp + 4);
                nb2 = *(const float4*)(bp + 8); nb3 = *(const float4*)(bp + 12);
            }
            const __nv_bfloat16* base = sm + buf*13824;
            TC_COMPUTE4(base)
            if (more) { __nv_bfloat16* d = sm + (buf^1)*13824; TC_STORE_NEXT_PS(d) }
            __syncthreads();
            buf ^= 1;
        }
        int r0 = rb + (lane >> 2);
        int o0 = s_orow[r0], o1 = s_orow[r0 + 8];
        #pragma unroll
        for (int nf = 0; nf < 8; nf++) {
            int c = n0 + ch + nf*8 + (lane & 3)*2;
            if (o0 >= 0)
                *(float2*)&outb[(size_t)o0*DM + c] = make_float2(acc[nf][0], acc[nf][1]);
            if (o1 >= 0)
                *(float2*)&outb[(size_t)o1*DM + c] = make_float2(acc[nf][2], acc[nf][3]);
        }
    }
}

// ---------------- q/k norm+rope + V convert; writes split-bf16 hi/lo ----------------
__global__ __launch_bounds__(256) void qkv_prep(const float* __restrict__ qw,
                                                const float* __restrict__ kw,
                                                const float* __restrict__ cosb,
                                                const float* __restrict__ sinb) {
    int gw = (blockIdx.x * blockDim.x + threadIdx.x) >> 5;
    int lane = threadIdx.x & 31;
    if (gw >= SS * (NHQ + 2*NKVH)) return;
    int t = gw / (NHQ + 2*NKVH);
    int hh = gw % (NHQ + 2*NKVH);
    int d0 = lane * 2;
    float o0, o1;
    __nv_bfloat16 *dsth, *dstl;
    size_t idx;
    if (hh < NHQ + NKVH) {
        const float* base;
        const float* w;
        if (hh < NHQ) {
            base = &g_q[(size_t)t*(NHQ*HDIM) + hh*HDIM]; w = qw;
            idx = (size_t)t*(NHQ*HDIM) + hh*HDIM + d0;
            dsth = g_qh; dstl = g_ql;
        } else {
            int kh_ = hh - NHQ;
            base = &g_k[(size_t)t*(NKVH*HDIM) + kh_*HDIM]; w = kw;
            idx = (size_t)t*(NKVH*HDIM) + kh_*HDIM + d0;
            dsth = g_kh; dstl = g_kl;
        }
        float v0 = base[d0], v1 = base[d0+1];
        float ss = v0*v0 + v1*v1;
        #pragma unroll
        for (int off = 16; off; off >>= 1) ss += __shfl_xor_sync(0xffffffffu, ss, off);
        float r = rsqrtf(ss * (1.0f/HDIM) + 1e-5f);
        float n0 = v0 * r * w[d0];
        float n1 = v1 * r * w[d0+1];
        float c = cosb[t*(HDIM/2) + lane];
        float s = sinb[t*(HDIM/2) + lane];
        o0 = n0*c - n1*s;
        o1 = n0*s + n1*c;
    } else {
        int vh_ = hh - NHQ - NKVH;
        const float* base = &g_v[(size_t)t*(NKVH*HDIM) + vh_*HDIM];
        o0 = base[d0]; o1 = base[d0+1];
        idx = (size_t)t*(NKVH*HDIM) + vh_*HDIM + d0;
        dsth = g_vh; dstl = g_vl;
    }
    *(u32*)&dsth[idx] = pkbf2(o0, o1);
    *(u32*)&dstl[idx] = pkres2(o0, o1);
}

// ---------------- flash attention (proven R15; output pre-split) ----------------
#define TCF_SMEM (46080*2)
__global__ __launch_bounds__(128) void flash_tc() {
    extern __shared__ __align__(16) char dyn[];
    __nv_bfloat16* sm = (__nv_bfloat16*)dyn;
    __nv_bfloat16* Qhs = sm;
    __nv_bfloat16* Qls = sm + 4608;
    int tid = threadIdx.x, w = tid >> 5, lane = tid & 31;
    int qt = (int)gridDim.x - 1 - (int)blockIdx.x;
    int h = blockIdx.y, kvh = h >> 2;
    int q0 = qt * 64;
    int rb = w * 16;

    int lrow = tid >> 1, lcb = (tid & 1) * 32;

    {
        const __nv_bfloat16* sq = g_qh + (size_t)(q0 + lrow)*(NHQ*HDIM) + h*HDIM + lcb;
        const __nv_bfloat16* sl = g_ql + (size_t)(q0 + lrow)*(NHQ*HDIM) + h*HDIM + lcb;
        __nv_bfloat16* dq = Qhs + lrow*72 + lcb;
        __nv_bfloat16* dl = Qls + lrow*72 + lcb;
        #pragma unroll
        for (int c = 0; c < 4; c++) {
            cpa16(dq + c*8, sq + c*8);
            cpa16(dl + c*8, sl + c*8);
        }
    }
    {
        __nv_bfloat16* b0 = sm + 9216;
        size_t goff = (size_t)lrow*(NKVH*HDIM) + kvh*HDIM + lcb;
        #pragma unroll
        for (int c = 0; c < 4; c++) {
            cpa16(b0 + lrow*72 + lcb + c*8,          g_kh + goff + c*8);
            cpa16(b0 + 4608 + lrow*72 + lcb + c*8,   g_kl + goff + c*8);
            cpa16(b0 + 9216 + lrow*72 + lcb + c*8,   g_vh + goff + c*8);
            cpa16(b0 + 13824 + lrow*72 + lcb + c*8,  g_vl + goff + c*8);
        }
    }
    CP_COMMIT();
    CP_WAIT0();
    __syncthreads();

    int a_row_f = rb + (lane & 7) + ((lane >> 3) & 1) * 8;
    int a_col_s = ((lane >> 4) & 1) * 8;
    int kq_row = lane & 7;
    int kq_off = ((lane >> 3) & 1) * 8;
    int v_row = lane & 15;

    u32 qh_[4][4], ql_[4][4];
    #pragma unroll
    for (int kd = 0; kd < 4; kd++) {
        ldsm4(qh_[kd], Qhs + a_row_f*72 + kd*16 + a_col_s);
        ldsm4(ql_[kd], Qls + a_row_f*72 + kd*16 + a_col_s);
    }

    float Oacc[8][4] = {};
    float m_i[2] = {-1e30f, -1e30f};
    float l_i[2] = {0.f, 0.f};

    for (int kt = 0; kt <= qt; kt++) {
        int k0 = kt * 64;
        const __nv_bfloat16* cur = sm + 9216 + (kt & 1)*18432;
        bool more = (kt < qt);
        if (more) {
            __nv_bfloat16* nb = sm + 9216 + ((kt + 1) & 1)*18432;
            size_t goff = (size_t)(k0 + 64 + lrow)*(NKVH*HDIM) + kvh*HDIM + lcb;
            #pragma unroll
            for (int c = 0; c < 4; c++) {
                cpa16(nb + lrow*72 + lcb + c*8,          g_kh + goff + c*8);
                cpa16(nb + 4608 + lrow*72 + lcb + c*8,   g_kl + goff + c*8);
                cpa16(nb + 9216 + lrow*72 + lcb + c*8,   g_vh + goff + c*8);
                cpa16(nb + 13824 + lrow*72 + lcb + c*8,  g_vl + goff + c*8);
            }
            CP_COMMIT();
        }

        float S[8][4] = {};
        #pragma unroll
        for (int kd = 0; kd < 4; kd++) {
            #pragma unroll
            for (int nt = 0; nt < 8; nt++) {
                const __nv_bfloat16* pk = cur + (nt*8 + kq_row)*72 + kd*16 + kq_off;
                u32 bh0, bh1, bl0, bl1;
                ldsm2(bh0, bh1, pk);
                ldsm2(bl0, bl1, pk + 4608);
                mma_bf16(S[nt], qh_[kd], bh0, bh1);
                mma_bf16(S[nt], qh_[kd], bl0, bl1);
                mma_bf16(S[nt], ql_[kd], bh0, bh1);
            }
        }

        const float sc = 0.125f;
        int colb = (lane & 3) * 2;
        int rAg = q0 + rb + (lane >> 2);
        int rBg = rAg + 8;
        if (kt == qt) {
            #pragma unroll
            for (int nt = 0; nt < 8; nt++) {
                int j0 = k0 + nt*8 + colb, j1 = j0 + 1;
                S[nt][0] = (j0 <= rAg) ? S[nt][0]*sc : -1e30f;
                S[nt][1] = (j1 <= rAg) ? S[nt][1]*sc : -1e30f;
                S[nt][2] = (j0 <= rBg) ? S[nt][2]*sc : -1e30f;
                S[nt][3] = (j1 <= rBg) ? S[nt][3]*sc : -1e30f;
            }
        } else {
            #pragma unroll
            for (int nt = 0; nt < 8; nt++) {
                S[nt][0] *= sc; S[nt][1] *= sc; S[nt][2] *= sc; S[nt][3] *= sc;
            }
        }
        float mxA = -1e30f, mxB = -1e30f;
        #pragma unroll
        for (int nt = 0; nt < 8; nt++) {
            mxA = fmaxf(mxA, fmaxf(S[nt][0], S[nt][1]));
            mxB = fmaxf(mxB, fmaxf(S[nt][2], S[nt][3]));
        }
        mxA = fmaxf(mxA, __shfl_xor_sync(0xffffffffu, mxA, 1));
        mxA = fmaxf(mxA, __shfl_xor_sync(0xffffffffu, mxA, 2));
        mxB = fmaxf(mxB, __shfl_xor_sync(0xffffffffu, mxB, 1));
        mxB = fmaxf(mxB, __shfl_xor_sync(0xffffffffu, mxB, 2));
        float mnA = fmaxf(m_i[0], mxA), mnB = fmaxf(m_i[1], mxB);
        float scA = __expf(m_i[0] - mnA), scB = __expf(m_i[1] - mnB);
        float rsA = 0.f, rsB = 0.f;
        #pragma unroll
        for (int nt = 0; nt < 8; nt++) {
            S[nt][0] = __expf(S[nt][0] - mnA); S[nt][1] = __expf(S[nt][1] - mnA);
            S[nt][2] = __expf(S[nt][2] - mnB); S[nt][3] = __expf(S[nt][3] - mnB);
            rsA += S[nt][0] + S[nt][1];
            rsB += S[nt][2] + S[nt][3];
        }
        rsA += __shfl_xor_sync(0xffffffffu, rsA, 1);
        rsA += __shfl_xor_sync(0xffffffffu, rsA, 2);
        rsB += __shfl_xor_sync(0xffffffffu, rsB, 1);
        rsB += __shfl_xor_sync(0xffffffffu, rsB, 2);
        l_i[0] = l_i[0]*scA + rsA; l_i[1] = l_i[1]*scB + rsB;
        m_i[0] = mnA; m_i[1] = mnB;
        #pragma unroll
        for (int nt = 0; nt < 8; nt++) {
            Oacc[nt][0] *= scA; Oacc[nt][1] *= scA;
            Oacc[nt][2] *= scB; Oacc[nt][3] *= scB;
        }

        const __nv_bfloat16* Vc = cur + 9216;
        #pragma unroll
        for (int kf = 0; kf < 4; kf++) {
            u32 ph[4], pl[4];
            ph[0] = pkbf2(S[2*kf][0],   S[2*kf][1]);
            ph[1] = pkbf2(S[2*kf][2],   S[2*kf][3]);
            ph[2] = pkbf2(S[2*kf+1][0], S[2*kf+1][1]);
            ph[3] = pkbf2(S[2*kf+1][2], S[2*kf+1][3]);
            pl[0] = pkres2(S[2*kf][0],   S[2*kf][1]);
            pl[1] = pkres2(S[2*kf][2],   S[2*kf][3]);
            pl[2] = pkres2(S[2*kf+1][0], S[2*kf+1][1]);
            pl[3] = pkres2(S[2*kf+1][2], S[2*kf+1][3]);
            #pragma unroll
            for (int nt = 0; nt < 8; nt++) {
                const __nv_bfloat16* pv = Vc + (kf*16 + v_row)*72 + nt*8;
                u32 vh0, vh1, vl0, vl1;
                ldsm2t(vh0, vh1, pv);
                ldsm2t(vl0, vl1, pv + 4608);
                mma_bf16(Oacc[nt], ph, vh0, vh1);
                mma_bf16(Oacc[nt], ph, vl0, vl1);
                mma_bf16(Oacc[nt], pl, vh0, vh1);
            }
        }
        if (more) { CP_WAIT0(); }
        __syncthreads();
    }
    float invA = 1.f / l_i[0], invB = 1.f / l_i[1];
    int rAg = q0 + rb + (lane >> 2);
    size_t baseA = (size_t)rAg*(NHQ*HDIM) + h*HDIM;
    size_t baseB = baseA + (size_t)8*(NHQ*HDIM);
    #pragma unroll
    for (int nt = 0; nt < 8; nt++) {
        int c = nt*8 + (lane & 3)*2;
        float ax = Oacc[nt][0]*invA, ay = Oacc[nt][1]*invA;
        float bx = Oacc[nt][2]*invB, by = Oacc[nt][3]*invB;
        *(u32*)&g_ath[baseA + c] = pkbf2(ax, ay);
        *(u32*)&g_atl[baseA + c] = pkres2(ax, ay);
        *(u32*)&g_ath[baseB + c] = pkbf2(bx, by);
        *(u32*)&g_atl[baseB + c] = pkres2(bx, by);
    }
}

// ---------------- gate GEMM (N=64, fp32 z) ----------------
__global__ __launch_bounds__(256) void gemm64(const float* __restrict__ A,
                                              const float* __restrict__ B,
                                              float* __restrict__ C,
                                              int M, int N, int K) {
    __shared__ float As[16][64];
    __shared__ float Bs[16][64];
    int tid = threadIdx.x;
    int tx = tid & 15, ty = tid >> 4;
    int m0 = blockIdx.y * 64, n0 = blockIdx.x * 64;
    int ar = tid >> 2;
    int ac = (tid & 3) * 4;
    int br = tid >> 4;
    int bc = (tid & 15) * 4;
    float acc[4][4] = {};
    for (int k0 = 0; k0 < K; k0 += 16) {
        float4 av = *(const float4*)&A[(size_t)(m0 + ar)*K + k0 + ac];
        float4 bv = *(const float4*)&B[(size_t)(k0 + br)*N + n0 + bc];
        As[ac+0][ar] = av.x; As[ac+1][ar] = av.y;
        As[ac+2][ar] = av.z; As[ac+3][ar] = av.w;
        *(float4*)&Bs[br][bc] = bv;
        __syncthreads();
        #pragma unroll
        for (int k = 0; k < 16; k++) {
            float4 a = *(const float4*)&As[k][ty*4];
            float4 b = *(const float4*)&Bs[k][tx*4];
            float aa[4] = {a.x,a.y,a.z,a.w};
            float bb[4] = {b.x,b.y,b.z,b.w};
            #pragma unroll
            for (int i = 0; i < 4; i++)
                #pragma unroll
                for (int j = 0; j < 4; j++)
                    acc[i][j] += aa[i]*bb[j];
        }
        __syncthreads();
    }
    #pragma unroll
    for (int i = 0; i < 4; i++) {
        float4 ov = make_float4(acc[i][0],acc[i][1],acc[i][2],acc[i][3]);
        *(float4*)&C[(size_t)(m0 + ty*4 + i)*N + n0 + tx*4] = ov;
    }
}

// ---------------- routing ----------------
__global__ void zero_cnt_k() { if (threadIdx.x < NE) g_cnt[threadIdx.x] = 0; }

__global__ void route_k() {
    int t = blockIdx.x;
    int lane = threadIdx.x;
    float v0 = g_logits[t*NE + lane];
    float v1 = g_logits[t*NE + 32 + lane];
    float selv[TOPK]; int seli[TOPK];
    #pragma unroll
    for (int it = 0; it < TOPK; it++) {
        float best = (v0 >= v1) ? v0 : v1;
        int   bi   = (v0 >= v1) ? lane : lane + 32;
        #pragma unroll
        for (int off = 16; off; off >>= 1) {
            float ov = __shfl_xor_sync(0xffffffffu, best, off);
            int   oi = __shfl_xor_sync(0xffffffffu, bi, off);
            if (ov > best || (ov == best && oi < bi)) { best = ov; bi = oi; }
        }
        selv[it] = best; seli[it] = bi;
        if (bi == lane)      v0 = -1e30f;
        if (bi == lane + 32) v1 = -1e30f;
    }
    if (lane < TOPK) {
        float sum = 0.f;
        #pragma unroll
        for (int i = 0; i < TOPK; i++) sum += __expf(selv[i] - selv[0]);
        float w = __expf(selv[lane] - selv[0]) / sum;
        int e = seli[lane];
        int pos = atomicAdd(&g_cnt[e], 1);
        g_list[e*SS + pos] = t*TOPK + lane;
        g_pairw[t*TOPK + lane] = w;
    }
}

// ---------------- final ----------------
__global__ __launch_bounds__(256) void final_k(float* __restrict__ out) {
    int t = blockIdx.x;
    int c = threadIdx.x * 4;
    float4 a = *(const float4*)&g_h[(size_t)t*DM + c];
    float4 b = *(const float4*)&g_sh[(size_t)t*DM + c];
    a.x += b.x; a.y += b.y; a.z += b.z; a.w += b.w;
    #pragma unroll
    for (int kk = 0; kk < TOPK; kk++) {
        float4 gv = *(const float4*)&g_g2[(size_t)(t*TOPK+kk)*DM + c];
        a.x += gv.x; a.y += gv.y; a.z += gv.z; a.w += gv.w;
    }
    *(float4*)&out[(size_t)t*DM + c] = a;
}

// ---------------- host ----------------
extern "C" void kernel_launch(void* const* d_in, const int* in_sizes, int n_in,
                              void* d_out, int out_size) {
    const float* x   = (const float*)d_in[0];
    const float* fc  = (const float*)d_in[1];
    const float* fs  = (const float*)d_in[2];
    const float* anw = (const float*)d_in[3];
    const float* fnw = (const float*)d_in[4];
    const float* wq  = (const float*)d_in[5];
    const float* wk  = (const float*)d_in[6];
    const float* wv  = (const float*)d_in[7];
    const float* wo  = (const float*)d_in[8];
    const float* qnw = (const float*)d_in[9];
    const float* knw = (const float*)d_in[10];
    const float* gw  = (const float*)d_in[11];
    const float* w1e = (const float*)d_in[12];
    const float* w3e = (const float*)d_in[13];
    const float* w2e = (const float*)d_in[14];
    const float* sw1 = (const float*)d_in[15];
    const float* sw3 = (const float*)d_in[16];
    const float* sw2 = (const float*)d_in[17];
    float* out = (float*)d_out;

    float *h, *z, *logits;
    __nv_bfloat16 *hxh, *hxl, *zh, *zl;
    cudaGetSymbolAddress((void**)&h,  g_h);
    cudaGetSymbolAddress((void**)&z,  g_z);
    cudaGetSymbolAddress((void**)&logits, g_logits);
    cudaGetSymbolAddress((void**)&hxh, g_hxh);
    cudaGetSymbolAddress((void**)&hxl, g_hxl);
    cudaGetSymbolAddress((void**)&zh, g_zh);
    cudaGetSymbolAddress((void**)&zl, g_zl);

    cudaFuncSetAttribute(flash_tc, cudaFuncAttributeMaxDynamicSharedMemorySize, TCF_SMEM);
    cudaFuncSetAttribute(ffn_a, cudaFuncAttributeMaxDynamicSharedMemorySize, FA_BYTES);
    cudaFuncSetAttribute(ffn_b, cudaFuncAttributeMaxDynamicSharedMemorySize, FB_BYTES);
    cudaFuncSetAttribute(tc_qkv, cudaFuncAttributeMaxDynamicSharedMemorySize, FB_BYTES);
    cudaFuncSetAttribute(tc_wo, cudaFuncAttributeMaxDynamicSharedMemorySize, FB_BYTES);

    // attention branch
    rmsnorm_k<<<SS, 256>>>(x, anw, h /*unused fp32 slot*/, hxh, hxl);
    tc_qkv<<<dim3(12, 16), 256, FB_BYTES>>>(wq, wk, wv);
    qkv_prep<<<(SS*(NHQ+2*NKVH)*32)/256, 256>>>(qnw, knw, fc, fs);
    flash_tc<<<dim3(16,16), 128, TCF_SMEM>>>();
    tc_wo<<<dim3(8, 16), 256, FB_BYTES>>>(wo, h, x);   // h = attn@wo + x

    // ffn branch
    rmsnorm_k<<<SS, 256>>>(h, fnw, z, zh, zl);
    gemm64<<<dim3(1, 16), 256>>>(z, gw, logits, SS, NE, DM);
    zero_cnt_k<<<1, 64>>>();
    route_k<<<SS, 32>>>();
    ffn_a<<<NE*8 + 128, 256, FA_BYTES>>>(w1e, w3e, sw1, sw3);
    ffn_b<<<NE*8 + 128, 256, FB_BYTES>>>(w2e, sw2);

    final_k<<<SS, 256>>>(out);
}